// round 8
// baseline (speedup 1.0000x reference)
#include <cuda_runtime.h>
#include <cuda_bf16.h>
#include <math.h>
#include <stdint.h>

#define B_ 256

// ---------------- device scratch ----------------
__device__ float g_Weff[25 * 220];
__device__ float g_beff[25];
__device__ uint32_t g_xp[B_ * 22 * 1000];            // packed x bf16 h | l<<16
__device__ uint32_t g_y1p[B_ * 25 * 330];            // packed bf16 h | l<<16
__device__ uint32_t g_y2p[B_ * 50 * 107];            // packed bf16 h | l<<16
__device__ float g_y3[B_ * 100 * 32];
__device__ float g_feat[B_ * 1400];
// chunk-image weights (bf16 split)
__device__ __align__(16) uint16_t g_w1h[2 * 32 * 136];
__device__ __align__(16) uint16_t g_w1l[2 * 32 * 136];
__device__ __align__(16) uint16_t g_w2h[2 * 64 * 136];
__device__ __align__(16) uint16_t g_w2l[2 * 64 * 136];
__device__ __align__(16) uint16_t g_w3h[4 * 128 * 136];
__device__ __align__(16) uint16_t g_w3l[4 * 128 * 136];

__device__ __forceinline__ float elu1(float x) { return x > 0.f ? x : expm1f(x); }

__device__ __forceinline__ uint32_t smem_u32(const void* p) {
    uint32_t a;
    asm("{ .reg .u64 t; cvta.to.shared.u64 t, %1; cvt.u32.u64 %0, t; }" : "=r"(a) : "l"(p));
    return a;
}
__device__ __forceinline__ void ldsm4(uint32_t* r, uint32_t addr) {
    asm volatile("ldmatrix.sync.aligned.m8n8.x4.shared.b16 {%0,%1,%2,%3}, [%4];"
                 : "=r"(r[0]), "=r"(r[1]), "=r"(r[2]), "=r"(r[3]) : "r"(addr));
}
__device__ __forceinline__ void ldsm4t(uint32_t* r, uint32_t addr) {
    asm volatile("ldmatrix.sync.aligned.m8n8.x4.trans.shared.b16 {%0,%1,%2,%3}, [%4];"
                 : "=r"(r[0]), "=r"(r[1]), "=r"(r[2]), "=r"(r[3]) : "r"(addr));
}
__device__ __forceinline__ void mma16816(float* d, const uint32_t* a, const uint32_t* b) {
    asm volatile("mma.sync.aligned.m16n8k16.row.col.f32.bf16.bf16.f32 "
                 "{%0,%1,%2,%3}, {%4,%5,%6,%7}, {%8,%9}, {%0,%1,%2,%3};"
                 : "+f"(d[0]), "+f"(d[1]), "+f"(d[2]), "+f"(d[3])
                 : "r"(a[0]), "r"(a[1]), "r"(a[2]), "r"(a[3]), "r"(b[0]), "r"(b[1]));
}
__device__ __forceinline__ uint32_t pack_bf16_split(float v) {
    __nv_bfloat16 h = __float2bfloat16(v);
    float hf = __bfloat162float(h);
    __nv_bfloat16 l = __float2bfloat16(v - hf);
    uint16_t hb = reinterpret_cast<uint16_t&>(h);
    uint16_t lb = reinterpret_cast<uint16_t&>(l);
    return (uint32_t)hb | ((uint32_t)lb << 16);
}

// ---------------- kernel 0: fold conv_time into conv_spat ----------------
__global__ void precompute_k(const float* __restrict__ w_time, const float* __restrict__ b_time,
                             const float* __restrict__ w_spat, const float* __restrict__ b_spat)
{
    for (int idx = threadIdx.x; idx < 25 * 220; idx += blockDim.x) {
        int p = idx / 220, rem = idx % 220, c = rem / 10, k = rem % 10;
        float s = 0.f;
        #pragma unroll
        for (int o = 0; o < 25; o++)
            s = fmaf(w_spat[p * 550 + o * 22 + c], w_time[o * 10 + k], s);
        g_Weff[idx] = s;
    }
    if (threadIdx.x < 25) {
        int p = threadIdx.x;
        float s = b_spat[p];
        for (int o = 0; o < 25; o++) {
            float w = 0.f;
            for (int c = 0; c < 22; c++) w += w_spat[p * 550 + o * 22 + c];
            s = fmaf(b_time[o], w, s);
        }
        g_beff[p] = s;
    }
}

// ---------------- kernel 0a: pack x to bf16 split ----------------
__global__ void precompute_x_k(const float* __restrict__ x)
{
    for (int i = blockIdx.x * blockDim.x + threadIdx.x; i < B_ * 22000;
         i += gridDim.x * blockDim.x)
        g_xp[i] = pack_bf16_split(x[i]);
}

// ---------------- kernel 0b: Weff chunk-images ----------------
__global__ void precompute1b_k()
{
    int idx = blockIdx.x * 256 + threadIdx.x;
    if (idx >= 2 * 32 * 136) return;
    int ch = idx / 4352, r = idx % 4352, row = r / 136, kloc = r % 136;
    int gk = ch * 128 + kloc;
    float v = (kloc < 128 && row < 25 && gk < 220) ? g_Weff[row * 220 + gk] : 0.f;
    uint32_t p = pack_bf16_split(v);
    g_w1h[idx] = (uint16_t)(p & 0xffff);
    g_w1l[idx] = (uint16_t)(p >> 16);
}

// ---------------- kernel 0c: w2 chunk-images ----------------
__global__ void precompute3_k(const float* __restrict__ w2)   // [50][250]
{
    int idx = blockIdx.x * 256 + threadIdx.x;
    if (idx >= 2 * 64 * 136) return;
    int ch = idx / 8704, r = idx % 8704, row = r / 136, kloc = r % 136;
    int gk = ch * 128 + kloc;
    float v = (kloc < 128 && row < 50 && gk < 250) ? w2[row * 250 + gk] : 0.f;
    uint32_t p = pack_bf16_split(v);
    g_w2h[idx] = (uint16_t)(p & 0xffff);
    g_w2l[idx] = (uint16_t)(p >> 16);
}

// ---------------- kernel 0d: w3 chunk-images ----------------
__global__ void precompute2_k(const float* __restrict__ w3)   // [100][500]
{
    int idx = blockIdx.x * 256 + threadIdx.x;
    if (idx >= 4 * 128 * 136) return;
    int ch = idx / 17408, r = idx % 17408, row = r / 136, kloc = r % 136;
    int gk = ch * 128 + kloc;
    float v = (kloc < 128 && row < 100 && gk < 500) ? w3[row * 500 + gk] : 0.f;
    uint32_t p = pack_bf16_split(v);
    g_w3h[idx] = (uint16_t)(p & 0xffff);
    g_w3l[idx] = (uint16_t)(p >> 16);
}

// ---------------- stage 1 (TENSOR): x -> y1p ----------------
// grid (256 samples, 6 n-tiles). D[32][192] = A(Weff)[32][256] x B(im2col x)[192][256]^T
// tile nt covers conv positions [nt*192, nt*192+192) = pooled [nt*64, nt*64+64)
#define S1_KP 136
#define S1_NP 200
#define S1_AH 0
#define S1_AL 8704
#define S1_BH 17408
#define S1_BL 68608
#define S1_SMEM 119808

__global__ __launch_bounds__(256, 1) void stage1_k()
{
    extern __shared__ char smc[];
    const uint32_t sb = smem_u32(smc);
    const int tid = threadIdx.x, wid = tid >> 5, lane = tid & 31;
    const int b = blockIdx.x, nt = blockIdx.y;
    const int n0 = nt * 192;
    __shared__ float bs[25];
    if (tid < 25) bs[tid] = g_beff[tid];

    float d[6][4];
    #pragma unroll
    for (int i = 0; i < 6; i++)
        #pragma unroll
        for (int j = 0; j < 4; j++) d[i][j] = 0.f;

    const int mw = wid & 1, nq = wid >> 1;   // m16 tile, 48-col n-quarter
    const uint32_t aOff = ((mw * 16 + ((lane >> 3) & 1) * 8 + (lane & 7)) * S1_KP + (lane >> 4) * 8) * 2;
    const uint32_t bOff = ((((lane >> 3) & 1) * 8 + (lane & 7)) * S1_NP + (lane >> 4) * 8 + nq * 48) * 2;
    const uint32_t aH = sb + S1_AH + aOff, aL = sb + S1_AL + aOff;
    const uint32_t bHb = sb + S1_BH + bOff, bLb = sb + S1_BL + bOff;

    const int kloc = tid >> 1, seg = tid & 1;
    uint16_t* bhRow = reinterpret_cast<uint16_t*>(smc + S1_BH) + kloc * S1_NP + seg * 96;
    uint16_t* blRow = reinterpret_cast<uint16_t*>(smc + S1_BL) + kloc * S1_NP + seg * 96;

    for (int ch = 0; ch < 2; ch++) {
        __syncthreads();
        // A copy (544 float4 per split)
        {
            const float4* srcH = reinterpret_cast<const float4*>(g_w1h + ch * 4352);
            const float4* srcL = reinterpret_cast<const float4*>(g_w1l + ch * 4352);
            float4* dstH = reinterpret_cast<float4*>(smc + S1_AH);
            float4* dstL = reinterpret_cast<float4*>(smc + S1_AL);
            #pragma unroll 1
            for (int i = tid; i < 544; i += 256) { dstH[i] = srcH[i]; dstL[i] = srcL[i]; }
        }
        // B gather from packed x
        {
            const int gk = ch * 128 + kloc;
            if (gk < 220) {
                const int c = gk / 10, kk = gk - c * 10;
                const uint32_t* src = g_xp + b * 22000 + c * 1000 + n0 + kk;
                const int jmax = 990 - n0;          // conv positions < 990
                #pragma unroll 8
                for (int j = 0; j < 96; j++) {
                    int jj = seg * 96 + j;
                    uint32_t p = (jj < jmax) ? __ldg(&src[jj]) : 0u;
                    bhRow[j] = (uint16_t)(p & 0xffff);
                    blRow[j] = (uint16_t)(p >> 16);
                }
            } else {
                #pragma unroll 8
                for (int j = 0; j < 96; j++) { bhRow[j] = 0; blRow[j] = 0; }
            }
        }
        __syncthreads();

        #pragma unroll
        for (int t = 0; t < 8; t++) {
            uint32_t ah[4], al[4];
            ldsm4(ah, aH + t * 32);
            ldsm4(al, aL + t * 32);
            const uint32_t bt = (uint32_t)t * (16 * S1_NP * 2);
            #pragma unroll
            for (int q = 0; q < 3; q++) {
                uint32_t bh[4], bl[4];
                ldsm4t(bh, bHb + bt + q * 32);
                ldsm4t(bl, bLb + bt + q * 32);
                mma16816(d[2 * q],     ah, bh);
                mma16816(d[2 * q],     al, bh);
                mma16816(d[2 * q],     ah, bl);
                mma16816(d[2 * q + 1], ah, bh + 2);
                mma16816(d[2 * q + 1], al, bh + 2);
                mma16816(d[2 * q + 1], ah, bl + 2);
            }
        }
    }

    // epilogue: D -> smem f32 [32][200], pool + ELU + pack
    __syncthreads();
    float* Dsm = reinterpret_cast<float*>(smc);
    {
        const int r0 = mw * 16 + (lane >> 2);
        const int cb = (lane & 3) * 2;
        #pragma unroll
        for (int q = 0; q < 3; q++) {
            int n = nq * 48 + q * 16 + cb;
            Dsm[r0 * 200 + n]           = d[2 * q][0];
            Dsm[r0 * 200 + n + 1]       = d[2 * q][1];
            Dsm[(r0 + 8) * 200 + n]     = d[2 * q][2];
            Dsm[(r0 + 8) * 200 + n + 1] = d[2 * q][3];
            Dsm[r0 * 200 + n + 8]       = d[2 * q + 1][0];
            Dsm[r0 * 200 + n + 9]       = d[2 * q + 1][1];
            Dsm[(r0 + 8) * 200 + n + 8] = d[2 * q + 1][2];
            Dsm[(r0 + 8) * 200 + n + 9] = d[2 * q + 1][3];
        }
    }
    __syncthreads();
    const int p0 = nt * 64;
    const int np = (330 - p0 < 64) ? (330 - p0) : 64;
    const int cnt = 25 * np;
    for (int i = tid; i < cnt; i += 256) {
        int o = i / np, j = i - o * np;
        int nl = 3 * j;
        float v = fmaxf(Dsm[o * 200 + nl], fmaxf(Dsm[o * 200 + nl + 1], Dsm[o * 200 + nl + 2]))
                  + bs[o];
        g_y1p[b * 8250 + o * 330 + p0 + j] = pack_bf16_split(elu1(v));
    }
}

// ---------------- stage 2 (TENSOR): y1p -> y2p ----------------
#define S2_KP 136
#define S2_NP 200
#define S2_AH 0
#define S2_AL 17408
#define S2_BH 34816
#define S2_BL 86016
#define S2_SMEM 137216

__global__ __launch_bounds__(256, 1) void stage2_k(const float* __restrict__ b2)
{
    extern __shared__ char smc[];
    const uint32_t sb = smem_u32(smc);
    const int tid = threadIdx.x, wid = tid >> 5, lane = tid & 31;
    const int b = blockIdx.x, ntile = blockIdx.y;
    const int n0 = ntile * 168;

    float d[12][4];
    #pragma unroll
    for (int i = 0; i < 12; i++)
        #pragma unroll
        for (int j = 0; j < 4; j++) d[i][j] = 0.f;

    const int mw = wid & 3, nw = wid >> 2;
    const uint32_t aOff = ((mw * 16 + ((lane >> 3) & 1) * 8 + (lane & 7)) * S2_KP + (lane >> 4) * 8) * 2;
    const uint32_t bOff = ((((lane >> 3) & 1) * 8 + (lane & 7)) * S2_NP + (lane >> 4) * 8 + nw * 96) * 2;
    const uint32_t aH = sb + S2_AH + aOff, aL = sb + S2_AL + aOff;
    const uint32_t bHb = sb + S2_BH + bOff, bLb = sb + S2_BL + bOff;

    const int kloc = tid >> 1, seg = tid & 1;
    uint16_t* bhRow = reinterpret_cast<uint16_t*>(smc + S2_BH) + kloc * S2_NP + seg * 96;
    uint16_t* blRow = reinterpret_cast<uint16_t*>(smc + S2_BL) + kloc * S2_NP + seg * 96;

    for (int ch = 0; ch < 2; ch++) {
        __syncthreads();
        {
            const float4* srcH = reinterpret_cast<const float4*>(g_w2h + ch * 8704);
            const float4* srcL = reinterpret_cast<const float4*>(g_w2l + ch * 8704);
            float4* dstH = reinterpret_cast<float4*>(smc + S2_AH);
            float4* dstL = reinterpret_cast<float4*>(smc + S2_AL);
            #pragma unroll 1
            for (int i = tid; i < 1088; i += 256) { dstH[i] = srcH[i]; dstL[i] = srcL[i]; }
        }
        {
            const int gk = ch * 128 + kloc;
            if (gk < 250) {
                const int c = gk / 10, kk = gk - c * 10;
                const uint32_t* src = g_y1p + b * 8250 + c * 330 + n0 + kk;
                const int jmax = 330 - n0 - kk;
                #pragma unroll 8
                for (int j = 0; j < 96; j++) {
                    int jj = seg * 96 + j;
                    uint32_t p = (jj < jmax) ? __ldg(&src[jj]) : 0u;
                    bhRow[j] = (uint16_t)(p & 0xffff);
                    blRow[j] = (uint16_t)(p >> 16);
                }
            } else {
                #pragma unroll 8
                for (int j = 0; j < 96; j++) { bhRow[j] = 0; blRow[j] = 0; }
            }
        }
        __syncthreads();

        #pragma unroll
        for (int t = 0; t < 8; t++) {
            uint32_t ah[4], al[4];
            ldsm4(ah, aH + t * 32);
            ldsm4(al, aL + t * 32);
            const uint32_t bt = (uint32_t)t * (16 * S2_NP * 2);
            #pragma unroll
            for (int q = 0; q < 6; q++) {
                uint32_t bh[4], bl[4];
                ldsm4t(bh, bHb + bt + q * 32);
                ldsm4t(bl, bLb + bt + q * 32);
                mma16816(d[2 * q],     ah, bh);
                mma16816(d[2 * q],     al, bh);
                mma16816(d[2 * q],     ah, bl);
                mma16816(d[2 * q + 1], ah, bh + 2);
                mma16816(d[2 * q + 1], al, bh + 2);
                mma16816(d[2 * q + 1], ah, bl + 2);
            }
        }
    }

    __syncthreads();
    float* Dsm = reinterpret_cast<float*>(smc);
    {
        const int r0 = mw * 16 + (lane >> 2);
        const int cb = (lane & 3) * 2;
        #pragma unroll
        for (int q = 0; q < 6; q++) {
            int n = nw * 96 + q * 16 + cb;
            Dsm[r0 * 200 + n]           = d[2 * q][0];
            Dsm[r0 * 200 + n + 1]       = d[2 * q][1];
            Dsm[(r0 + 8) * 200 + n]     = d[2 * q][2];
            Dsm[(r0 + 8) * 200 + n + 1] = d[2 * q][3];
            Dsm[r0 * 200 + n + 8]       = d[2 * q + 1][0];
            Dsm[r0 * 200 + n + 9]       = d[2 * q + 1][1];
            Dsm[(r0 + 8) * 200 + n + 8] = d[2 * q + 1][2];
            Dsm[(r0 + 8) * 200 + n + 9] = d[2 * q + 1][3];
        }
    }
    __syncthreads();
    const int cnt = ntile ? 50 * 51 : 50 * 56;
    for (int i = tid; i < cnt; i += 256) {
        int o, p;
        if (ntile == 0) { o = i / 56; p = i - o * 56; }
        else            { o = i / 51; p = 56 + (i - o * 51); }
        int nl = 3 * p - n0;
        float v = fmaxf(Dsm[o * 200 + nl], fmaxf(Dsm[o * 200 + nl + 1], Dsm[o * 200 + nl + 2]))
                  + __ldg(&b2[o]);
        g_y2p[b * 5350 + o * 107 + p] = pack_bf16_split(elu1(v));
    }
}

// ---------------- stage 3 (TENSOR): y2p -> y3 ----------------
#define S3_KP 136
#define S3_NP 200
#define S3_AH 0
#define S3_AL 34816
#define S3_BH 69632
#define S3_BL 120832
#define S3_SMEM 172032

__global__ __launch_bounds__(256, 1) void stage3_k(const float* __restrict__ b3)
{
    extern __shared__ char smc[];
    const uint32_t sb = smem_u32(smc);
    const int tid = threadIdx.x, wid = tid >> 5, lane = tid & 31;
    const int s0 = blockIdx.x * 2;

    float d[24][4];
    #pragma unroll
    for (int i = 0; i < 24; i++)
        #pragma unroll
        for (int j = 0; j < 4; j++) d[i][j] = 0.f;

    const uint32_t aOff = ((wid * 16 + ((lane >> 3) & 1) * 8 + (lane & 7)) * S3_KP + (lane >> 4) * 8) * 2;
    const uint32_t bOff = ((((lane >> 3) & 1) * 8 + (lane & 7)) * S3_NP + (lane >> 4) * 8) * 2;
    const uint32_t aH = sb + S3_AH + aOff, aL = sb + S3_AL + aOff;
    const uint32_t bHb = sb + S3_BH + bOff, bLb = sb + S3_BL + bOff;

    const int kloc = tid >> 1, seg = tid & 1;
    uint16_t* bhRow = reinterpret_cast<uint16_t*>(smc + S3_BH) + kloc * S3_NP + seg * 96;
    uint16_t* blRow = reinterpret_cast<uint16_t*>(smc + S3_BL) + kloc * S3_NP + seg * 96;

    for (int ch = 0; ch < 4; ch++) {
        __syncthreads();
        {
            const float4* srcH = reinterpret_cast<const float4*>(g_w3h + ch * 17408);
            const float4* srcL = reinterpret_cast<const float4*>(g_w3l + ch * 17408);
            float4* dstH = reinterpret_cast<float4*>(smc + S3_AH);
            float4* dstL = reinterpret_cast<float4*>(smc + S3_AL);
            #pragma unroll 1
            for (int i = tid; i < 2176; i += 256) { dstH[i] = srcH[i]; dstL[i] = srcL[i]; }
        }
        {
            const int gk = ch * 128 + kloc;
            if (gk < 500) {
                const int c = gk / 10, kk = gk - c * 10;
                const uint32_t* src = g_y2p + (s0 + seg) * 5350 + c * 107 + kk;
                #pragma unroll 8
                for (int j = 0; j < 96; j++) {
                    uint32_t p = __ldg(&src[j]);
                    bhRow[j] = (uint16_t)(p & 0xffff);
                    blRow[j] = (uint16_t)(p >> 16);
                }
            } else {
                #pragma unroll 8
                for (int j = 0; j < 96; j++) { bhRow[j] = 0; blRow[j] = 0; }
            }
        }
        __syncthreads();

        #pragma unroll
        for (int t = 0; t < 8; t++) {
            uint32_t ah[4], al[4];
            ldsm4(ah, aH + t * 32);
            ldsm4(al, aL + t * 32);
            const uint32_t bt = (uint32_t)t * (16 * S3_NP * 2);
            #pragma unroll
            for (int q = 0; q < 12; q++) {
                uint32_t bh[4], bl[4];
                ldsm4t(bh, bHb + bt + q * 32);
                ldsm4t(bl, bLb + bt + q * 32);
                mma16816(d[2 * q],     ah, bh);
                mma16816(d[2 * q],     al, bh);
                mma16816(d[2 * q],     ah, bl);
                mma16816(d[2 * q + 1], ah, bh + 2);
                mma16816(d[2 * q + 1], al, bh + 2);
                mma16816(d[2 * q + 1], ah, bl + 2);
            }
        }
    }

    __syncthreads();
    float* Dsm = reinterpret_cast<float*>(smc);
    {
        const int r0 = wid * 16 + (lane >> 2);
        const int cb = (lane & 3) * 2;
        #pragma unroll
        for (int nt = 0; nt < 24; nt++) {
            int n = nt * 8 + cb;
            Dsm[r0 * 200 + n]           = d[nt][0];
            Dsm[r0 * 200 + n + 1]       = d[nt][1];
            Dsm[(r0 + 8) * 200 + n]     = d[nt][2];
            Dsm[(r0 + 8) * 200 + n + 1] = d[nt][3];
        }
    }
    __syncthreads();
    for (int i = tid; i < 6400; i += 256) {
        int o = i >> 6, r = i & 63, s = r >> 5, t = r & 31;
        int n = s * 96 + t * 3;
        float v = fmaxf(Dsm[o * 200 + n], fmaxf(Dsm[o * 200 + n + 1], Dsm[o * 200 + n + 2]))
                  + __ldg(&b3[o]);
        g_y3[(s0 + s) * 3200 + o * 32 + t] = elu1(v);
    }
}

// ---------------- stage 4: y3 -> feat[256,1400] ----------------
__global__ __launch_bounds__(224, 3) void stage4_k(const float* __restrict__ w4,
                                                   const float* __restrict__ b4)
{
    extern __shared__ float sm[];
    float* xs = sm;             // [100][32]
    float* wc = sm + 3200;      // [50][201]
    const int b = blockIdx.x;
    const int o = threadIdx.x;
    for (int i = threadIdx.x; i < 3200; i += 224) xs[i] = g_y3[b * 3200 + i];

    float acc[21];
    #pragma unroll
    for (int i = 0; i < 21; i++) acc[i] = 0.f;

    for (int c0 = 0; c0 < 100; c0 += 5) {
        __syncthreads();
        const float2* wg = reinterpret_cast<const float2*>(w4 + c0 * 10);
        for (int i = threadIdx.x; i < 5000; i += 224) {
            int oo = i / 25, r2 = i - oo * 25;
            float2 v = __ldg(&wg[oo * 500 + r2]);
            wc[(2 * r2) * 201 + oo]     = v.x;
            wc[(2 * r2 + 1) * 201 + oo] = v.y;
        }
        __syncthreads();
        if (o < 200) {
            #pragma unroll
            for (int c = 0; c < 5; c++) {
                float xr[32];
                const float4* xp = reinterpret_cast<const float4*>(xs + (c0 + c) * 32);
                #pragma unroll
                for (int q = 0; q < 8; q++) {
                    float4 v = xp[q];
                    xr[q * 4 + 0] = v.x; xr[q * 4 + 1] = v.y;
                    xr[q * 4 + 2] = v.z; xr[q * 4 + 3] = v.w;
                }
                #pragma unroll
                for (int k = 0; k < 10; k++) {
                    float wv = wc[(c * 10 + k) * 201 + o];
                    #pragma unroll
                    for (int j = 0; j < 21; j++)
                        acc[j] = fmaf(wv, xr[j + k], acc[j]);
                }
            }
        }
    }

    if (o < 200) {
        float bo = __ldg(&b4[o]);
        #pragma unroll
        for (int t = 0; t < 7; t++) {
            float m = fmaxf(acc[3 * t], fmaxf(acc[3 * t + 1], acc[3 * t + 2])) + bo;
            g_feat[b * 1400 + o * 7 + t] = elu1(m);
        }
    }
}

// ---------------- head ----------------
__global__ void head_k(const int* __restrict__ sid, const float* __restrict__ hW,
                       const float* __restrict__ hB, float* __restrict__ out)
{
    const int b = blockIdx.x;
    const int s = sid[b];
    const float* f = g_feat + b * 1400;
    const float* W = hW + s * (4 * 1400);
    float acc[4] = {0.f, 0.f, 0.f, 0.f};
    for (int i = threadIdx.x; i < 1400; i += blockDim.x) {
        float fv = f[i];
        #pragma unroll
        for (int o = 0; o < 4; o++) acc[o] = fmaf(fv, __ldg(&W[o * 1400 + i]), acc[o]);
    }
    #pragma unroll
    for (int off = 16; off > 0; off >>= 1) {
        #pragma unroll
        for (int o = 0; o < 4; o++) acc[o] += __shfl_down_sync(0xFFFFFFFFu, acc[o], off);
    }
    __shared__ float red[4][4];
    const int w = threadIdx.x >> 5, l = threadIdx.x & 31;
    if (l == 0) {
        #pragma unroll
        for (int o = 0; o < 4; o++) red[o][w] = acc[o];
    }
    __syncthreads();
    if (threadIdx.x < 4) {
        int o = threadIdx.x;
        out[b * 4 + o] = red[o][0] + red[o][1] + red[o][2] + red[o][3] + __ldg(&hB[s * 4 + o]);
    }
}

// ---------------- launch ----------------
extern "C" void kernel_launch(void* const* d_in, const int* in_sizes, int n_in,
                              void* d_out, int out_size)
{
    const float* x      = (const float*)d_in[0];
    const int*   sid    = (const int*)  d_in[1];
    const float* w_time = (const float*)d_in[2];
    const float* b_time = (const float*)d_in[3];
    const float* w_spat = (const float*)d_in[4];
    const float* b_spat = (const float*)d_in[5];
    const float* w2     = (const float*)d_in[6];
    const float* b2     = (const float*)d_in[7];
    const float* w3     = (const float*)d_in[8];
    const float* b3     = (const float*)d_in[9];
    const float* w4     = (const float*)d_in[10];
    const float* b4     = (const float*)d_in[11];
    const float* hW     = (const float*)d_in[12];
    const float* hB     = (const float*)d_in[13];
    float* out = (float*)d_out;

    const int smem4 = (3200 + 50 * 201 + 3) * 4;     // 53,012
    cudaFuncSetAttribute(stage1_k, cudaFuncAttributeMaxDynamicSharedMemorySize, S1_SMEM);
    cudaFuncSetAttribute(stage2_k, cudaFuncAttributeMaxDynamicSharedMemorySize, S2_SMEM);
    cudaFuncSetAttribute(stage3_k, cudaFuncAttributeMaxDynamicSharedMemorySize, S3_SMEM);
    cudaFuncSetAttribute(stage4_k, cudaFuncAttributeMaxDynamicSharedMemorySize, smem4);

    precompute_k<<<1, 256>>>(w_time, b_time, w_spat, b_spat);
    precompute_x_k<<<2048, 256>>>(x);
    precompute1b_k<<<(2 * 32 * 136 + 255) / 256, 256>>>();
    precompute3_k<<<(2 * 64 * 136 + 255) / 256, 256>>>(w2);
    precompute2_k<<<(4 * 128 * 136 + 255) / 256, 256>>>(w3);
    stage1_k<<<dim3(B_, 6), 256, S1_SMEM>>>();
    stage2_k<<<dim3(B_, 2), 256, S2_SMEM>>>(b2);
    stage3_k<<<128, 256, S3_SMEM>>>(b3);
    stage4_k<<<B_, 224, smem4>>>(w4, b4);
    head_k<<<B_, 128>>>(sid, hW, hB, out);
}

// round 9
// speedup vs baseline: 1.3056x; 1.3056x over previous
#include <cuda_runtime.h>
#include <cuda_bf16.h>
#include <math.h>
#include <stdint.h>

#define B_ 256

// ---------------- device scratch ----------------
__device__ float g_Weff[25 * 220];
__device__ float g_beff[25];
__device__ uint32_t g_y1p[B_ * 25 * 330];            // packed bf16 h | l<<16
__device__ uint32_t g_y2p[B_ * 50 * 107];
__device__ uint32_t g_y3p[B_ * 100 * 32];
__device__ float g_feat[B_ * 1400];
// chunk-image weights (bf16 split)
__device__ __align__(16) uint16_t g_w2h[2 * 64 * 136];
__device__ __align__(16) uint16_t g_w2l[2 * 64 * 136];
__device__ __align__(16) uint16_t g_w3h[4 * 128 * 136];
__device__ __align__(16) uint16_t g_w3l[4 * 128 * 136];
__device__ __align__(16) uint16_t g_w4h[8 * 256 * 136];
__device__ __align__(16) uint16_t g_w4l[8 * 256 * 136];

__device__ __forceinline__ float elu1(float x) { return x > 0.f ? x : expm1f(x); }

__device__ __forceinline__ uint32_t smem_u32(const void* p) {
    uint32_t a;
    asm("{ .reg .u64 t; cvta.to.shared.u64 t, %1; cvt.u32.u64 %0, t; }" : "=r"(a) : "l"(p));
    return a;
}
__device__ __forceinline__ void ldsm4(uint32_t* r, uint32_t addr) {
    asm volatile("ldmatrix.sync.aligned.m8n8.x4.shared.b16 {%0,%1,%2,%3}, [%4];"
                 : "=r"(r[0]), "=r"(r[1]), "=r"(r[2]), "=r"(r[3]) : "r"(addr));
}
__device__ __forceinline__ void ldsm4t(uint32_t* r, uint32_t addr) {
    asm volatile("ldmatrix.sync.aligned.m8n8.x4.trans.shared.b16 {%0,%1,%2,%3}, [%4];"
                 : "=r"(r[0]), "=r"(r[1]), "=r"(r[2]), "=r"(r[3]) : "r"(addr));
}
__device__ __forceinline__ void mma16816(float* d, const uint32_t* a, const uint32_t* b) {
    asm volatile("mma.sync.aligned.m16n8k16.row.col.f32.bf16.bf16.f32 "
                 "{%0,%1,%2,%3}, {%4,%5,%6,%7}, {%8,%9}, {%0,%1,%2,%3};"
                 : "+f"(d[0]), "+f"(d[1]), "+f"(d[2]), "+f"(d[3])
                 : "r"(a[0]), "r"(a[1]), "r"(a[2]), "r"(a[3]), "r"(b[0]), "r"(b[1]));
}
__device__ __forceinline__ uint32_t pack_bf16_split(float v) {
    __nv_bfloat16 h = __float2bfloat16(v);
    float hf = __bfloat162float(h);
    __nv_bfloat16 l = __float2bfloat16(v - hf);
    uint16_t hb = reinterpret_cast<uint16_t&>(h);
    uint16_t lb = reinterpret_cast<uint16_t&>(l);
    return (uint32_t)hb | ((uint32_t)lb << 16);
}

// ---------------- kernel 0: fold conv_time into conv_spat ----------------
__global__ void precompute_k(const float* __restrict__ w_time, const float* __restrict__ b_time,
                             const float* __restrict__ w_spat, const float* __restrict__ b_spat)
{
    for (int idx = threadIdx.x; idx < 25 * 220; idx += blockDim.x) {
        int p = idx / 220, rem = idx % 220, c = rem / 10, k = rem % 10;
        float s = 0.f;
        #pragma unroll
        for (int o = 0; o < 25; o++)
            s = fmaf(w_spat[p * 550 + o * 22 + c], w_time[o * 10 + k], s);
        g_Weff[idx] = s;
    }
    if (threadIdx.x < 25) {
        int p = threadIdx.x;
        float s = b_spat[p];
        for (int o = 0; o < 25; o++) {
            float w = 0.f;
            for (int c = 0; c < 22; c++) w += w_spat[p * 550 + o * 22 + c];
            s = fmaf(b_time[o], w, s);
        }
        g_beff[p] = s;
    }
}

// ---------------- kernel 0b: ALL weight chunk-images in one launch ----------------
// jobs: w2 [2ch][64][136] (17408), w3 [4ch][128][136] (69632), w4 [8ch][256][136] (278528)
__global__ void precompute_w_k(const float* __restrict__ w2, const float* __restrict__ w3,
                               const float* __restrict__ w4)
{
    int idx = blockIdx.x * 256 + threadIdx.x;
    if (idx < 17408) {
        int ch = idx / 8704, r = idx % 8704, row = r / 136, kloc = r % 136;
        int gk = ch * 128 + kloc;
        float v = (kloc < 128 && row < 50 && gk < 250) ? w2[row * 250 + gk] : 0.f;
        uint32_t p = pack_bf16_split(v);
        g_w2h[idx] = (uint16_t)(p & 0xffff);
        g_w2l[idx] = (uint16_t)(p >> 16);
    } else if (idx < 87040) {
        int i3 = idx - 17408;
        int ch = i3 / 17408, r = i3 % 17408, row = r / 136, kloc = r % 136;
        int gk = ch * 128 + kloc;
        float v = (kloc < 128 && row < 100 && gk < 500) ? w3[row * 500 + gk] : 0.f;
        uint32_t p = pack_bf16_split(v);
        g_w3h[i3] = (uint16_t)(p & 0xffff);
        g_w3l[i3] = (uint16_t)(p >> 16);
    } else if (idx < 365568) {
        int i4 = idx - 87040;
        int ch = i4 / 34816, r = i4 % 34816, row = r / 136, kloc = r % 136;
        int gk = ch * 128 + kloc;
        float v = (kloc < 128 && row < 200 && gk < 1000) ? w4[row * 1000 + gk] : 0.f;
        uint32_t p = pack_bf16_split(v);
        g_w4h[i4] = (uint16_t)(p & 0xffff);
        g_w4l[i4] = (uint16_t)(p >> 16);
    }
}

// ---------------- scalar conv body ----------------
template<int P, int C, int XS, int WS>
__device__ __forceinline__ void conv_acc(const float* __restrict__ xs,
                                         const float* __restrict__ ws,
                                         float* __restrict__ acc)
{
    #pragma unroll
    for (int i = 0; i < P * 3; i++) acc[i] = 0.f;
    #pragma unroll 1
    for (int c = 0; c < C; c++) {
        float xr[12];
        #pragma unroll
        for (int i = 0; i < 12; i++) xr[i] = xs[c * XS + i];
        #pragma unroll
        for (int p = 0; p < P; p++) {
            const float* wp = ws + p * WS + c * 12;
            float4 w0 = *reinterpret_cast<const float4*>(wp);
            float4 w1 = *reinterpret_cast<const float4*>(wp + 4);
            float2 w2 = *reinterpret_cast<const float2*>(wp + 8);
            float wk[10] = {w0.x, w0.y, w0.z, w0.w, w1.x, w1.y, w1.z, w1.w, w2.x, w2.y};
            #pragma unroll
            for (int k = 0; k < 10; k++) {
                acc[p * 3 + 0] = fmaf(wk[k], xr[k + 0], acc[p * 3 + 0]);
                acc[p * 3 + 1] = fmaf(wk[k], xr[k + 1], acc[p * 3 + 1]);
                acc[p * 3 + 2] = fmaf(wk[k], xr[k + 2], acc[p * 3 + 2]);
            }
        }
    }
}

// ---------------- stage 1 (scalar, proven): x -> y1p ----------------
__global__ __launch_bounds__(352, 2) void stage1_k(const float* __restrict__ x)
{
    extern __shared__ float sm[];
    float* xs = sm;                // [22][504]
    float* ws = sm + 22 * 504;     // [25][264]
    __shared__ float bs[25];
    const int b = blockIdx.x, half = blockIdx.y;
    const int xoff = half * 495;
    const float* xb = x + b * 22000;
    for (int i = threadIdx.x; i < 22 * 504; i += 352) {
        int c = i / 504, t = i - c * 504;
        xs[i] = xb[c * 1000 + xoff + t];
    }
    for (int i = threadIdx.x; i < 5500; i += 352) {
        int p = i / 220, r = i - p * 220;
        int c = r / 10, k = r - c * 10;
        ws[p * 264 + c * 12 + k] = g_Weff[i];
    }
    if (threadIdx.x < 25) bs[threadIdx.x] = g_beff[threadIdx.x];
    __syncthreads();

    const int tpL = threadIdx.x % 176;
    const int pg  = threadIdx.x / 176;
    if (tpL >= 165) return;
    const float* xp = xs + 3 * tpL;
    const int tp = half * 165 + tpL;

    if (pg == 0) {
        float acc[39];
        conv_acc<13, 22, 504, 264>(xp, ws, acc);
        #pragma unroll
        for (int p = 0; p < 13; p++) {
            float m = fmaxf(acc[p * 3], fmaxf(acc[p * 3 + 1], acc[p * 3 + 2])) + bs[p];
            g_y1p[b * 8250 + p * 330 + tp] = pack_bf16_split(elu1(m));
        }
    } else {
        float acc[36];
        conv_acc<12, 22, 504, 264>(xp, ws + 13 * 264, acc);
        #pragma unroll
        for (int p = 0; p < 12; p++) {
            float m = fmaxf(acc[p * 3], fmaxf(acc[p * 3 + 1], acc[p * 3 + 2])) + bs[13 + p];
            g_y1p[b * 8250 + (13 + p) * 330 + tp] = pack_bf16_split(elu1(m));
        }
    }
}

// ---------------- stage 2 (TENSOR): y1p -> y2p ----------------
#define S2_KP 136
#define S2_NP 200
#define S2_AH 0
#define S2_AL 17408
#define S2_BH 34816
#define S2_BL 86016
#define S2_SMEM 137216

__global__ __launch_bounds__(256, 1) void stage2_k(const float* __restrict__ b2)
{
    extern __shared__ char smc[];
    const uint32_t sb = smem_u32(smc);
    const int tid = threadIdx.x, wid = tid >> 5, lane = tid & 31;
    const int b = blockIdx.x, ntile = blockIdx.y;
    const int n0 = ntile * 168;

    float d[12][4];
    #pragma unroll
    for (int i = 0; i < 12; i++)
        #pragma unroll
        for (int j = 0; j < 4; j++) d[i][j] = 0.f;

    const int mw = wid & 3, nw = wid >> 2;
    const uint32_t aOff = ((mw * 16 + ((lane >> 3) & 1) * 8 + (lane & 7)) * S2_KP + (lane >> 4) * 8) * 2;
    const uint32_t bOff = ((((lane >> 3) & 1) * 8 + (lane & 7)) * S2_NP + (lane >> 4) * 8 + nw * 96) * 2;
    const uint32_t aH = sb + S2_AH + aOff, aL = sb + S2_AL + aOff;
    const uint32_t bHb = sb + S2_BH + bOff, bLb = sb + S2_BL + bOff;

    const int kloc = tid >> 1, seg = tid & 1;
    uint16_t* bhRow = reinterpret_cast<uint16_t*>(smc + S2_BH) + kloc * S2_NP + seg * 96;
    uint16_t* blRow = reinterpret_cast<uint16_t*>(smc + S2_BL) + kloc * S2_NP + seg * 96;

    for (int ch = 0; ch < 2; ch++) {
        __syncthreads();
        {
            const float4* srcH = reinterpret_cast<const float4*>(g_w2h + ch * 8704);
            const float4* srcL = reinterpret_cast<const float4*>(g_w2l + ch * 8704);
            float4* dstH = reinterpret_cast<float4*>(smc + S2_AH);
            float4* dstL = reinterpret_cast<float4*>(smc + S2_AL);
            #pragma unroll 1
            for (int i = tid; i < 1088; i += 256) { dstH[i] = srcH[i]; dstL[i] = srcL[i]; }
        }
        {
            const int gk = ch * 128 + kloc;
            if (gk < 250) {
                const int c = gk / 10, kk = gk - c * 10;
                const uint32_t* src = g_y1p + b * 8250 + c * 330 + n0 + kk;
                const int jmax = 330 - n0 - kk;
                #pragma unroll 8
                for (int j = 0; j < 96; j++) {
                    int jj = seg * 96 + j;
                    uint32_t p = (jj < jmax) ? __ldg(&src[jj]) : 0u;
                    bhRow[j] = (uint16_t)(p & 0xffff);
                    blRow[j] = (uint16_t)(p >> 16);
                }
            } else {
                #pragma unroll 8
                for (int j = 0; j < 96; j++) { bhRow[j] = 0; blRow[j] = 0; }
            }
        }
        __syncthreads();

        #pragma unroll
        for (int t = 0; t < 8; t++) {
            uint32_t ah[4], al[4];
            ldsm4(ah, aH + t * 32);
            ldsm4(al, aL + t * 32);
            const uint32_t bt = (uint32_t)t * (16 * S2_NP * 2);
            #pragma unroll
            for (int q = 0; q < 6; q++) {
                uint32_t bh[4], bl[4];
                ldsm4t(bh, bHb + bt + q * 32);
                ldsm4t(bl, bLb + bt + q * 32);
                mma16816(d[2 * q],     ah, bh);
                mma16816(d[2 * q],     al, bh);
                mma16816(d[2 * q],     ah, bl);
                mma16816(d[2 * q + 1], ah, bh + 2);
                mma16816(d[2 * q + 1], al, bh + 2);
                mma16816(d[2 * q + 1], ah, bl + 2);
            }
        }
    }

    __syncthreads();
    float* Dsm = reinterpret_cast<float*>(smc);
    {
        const int r0 = mw * 16 + (lane >> 2);
        const int cb = (lane & 3) * 2;
        #pragma unroll
        for (int q = 0; q < 6; q++) {
            int n = nw * 96 + q * 16 + cb;
            Dsm[r0 * 200 + n]           = d[2 * q][0];
            Dsm[r0 * 200 + n + 1]       = d[2 * q][1];
            Dsm[(r0 + 8) * 200 + n]     = d[2 * q][2];
            Dsm[(r0 + 8) * 200 + n + 1] = d[2 * q][3];
            Dsm[r0 * 200 + n + 8]       = d[2 * q + 1][0];
            Dsm[r0 * 200 + n + 9]       = d[2 * q + 1][1];
            Dsm[(r0 + 8) * 200 + n + 8] = d[2 * q + 1][2];
            Dsm[(r0 + 8) * 200 + n + 9] = d[2 * q + 1][3];
        }
    }
    __syncthreads();
    const int cnt = ntile ? 50 * 51 : 50 * 56;
    for (int i = tid; i < cnt; i += 256) {
        int o, p;
        if (ntile == 0) { o = i / 56; p = i - o * 56; }
        else            { o = i / 51; p = 56 + (i - o * 51); }
        int nl = 3 * p - n0;
        float v = fmaxf(Dsm[o * 200 + nl], fmaxf(Dsm[o * 200 + nl + 1], Dsm[o * 200 + nl + 2]))
                  + __ldg(&b2[o]);
        g_y2p[b * 5350 + o * 107 + p] = pack_bf16_split(elu1(v));
    }
}

// ---------------- stage 3 (TENSOR): y2p -> y3p ----------------
#define S3_KP 136
#define S3_NP 200
#define S3_AH 0
#define S3_AL 34816
#define S3_BH 69632
#define S3_BL 120832
#define S3_SMEM 172032

__global__ __launch_bounds__(256, 1) void stage3_k(const float* __restrict__ b3)
{
    extern __shared__ char smc[];
    const uint32_t sb = smem_u32(smc);
    const int tid = threadIdx.x, wid = tid >> 5, lane = tid & 31;
    const int s0 = blockIdx.x * 2;

    float d[24][4];
    #pragma unroll
    for (int i = 0; i < 24; i++)
        #pragma unroll
        for (int j = 0; j < 4; j++) d[i][j] = 0.f;

    const uint32_t aOff = ((wid * 16 + ((lane >> 3) & 1) * 8 + (lane & 7)) * S3_KP + (lane >> 4) * 8) * 2;
    const uint32_t bOff = ((((lane >> 3) & 1) * 8 + (lane & 7)) * S3_NP + (lane >> 4) * 8) * 2;
    const uint32_t aH = sb + S3_AH + aOff, aL = sb + S3_AL + aOff;
    const uint32_t bHb = sb + S3_BH + bOff, bLb = sb + S3_BL + bOff;

    const int kloc = tid >> 1, seg = tid & 1;
    uint16_t* bhRow = reinterpret_cast<uint16_t*>(smc + S3_BH) + kloc * S3_NP + seg * 96;
    uint16_t* blRow = reinterpret_cast<uint16_t*>(smc + S3_BL) + kloc * S3_NP + seg * 96;

    for (int ch = 0; ch < 4; ch++) {
        __syncthreads();
        {
            const float4* srcH = reinterpret_cast<const float4*>(g_w3h + ch * 17408);
            const float4* srcL = reinterpret_cast<const float4*>(g_w3l + ch * 17408);
            float4* dstH = reinterpret_cast<float4*>(smc + S3_AH);
            float4* dstL = reinterpret_cast<float4*>(smc + S3_AL);
            #pragma unroll 1
            for (int i = tid; i < 2176; i += 256) { dstH[i] = srcH[i]; dstL[i] = srcL[i]; }
        }
        {
            const int gk = ch * 128 + kloc;
            if (gk < 500) {
                const int c = gk / 10, kk = gk - c * 10;
                const uint32_t* src = g_y2p + (s0 + seg) * 5350 + c * 107 + kk;
                #pragma unroll 8
                for (int j = 0; j < 96; j++) {
                    uint32_t p = __ldg(&src[j]);
                    bhRow[j] = (uint16_t)(p & 0xffff);
                    blRow[j] = (uint16_t)(p >> 16);
                }
            } else {
                #pragma unroll 8
                for (int j = 0; j < 96; j++) { bhRow[j] = 0; blRow[j] = 0; }
            }
        }
        __syncthreads();

        #pragma unroll
        for (int t = 0; t < 8; t++) {
            uint32_t ah[4], al[4];
            ldsm4(ah, aH + t * 32);
            ldsm4(al, aL + t * 32);
            const uint32_t bt = (uint32_t)t * (16 * S3_NP * 2);
            #pragma unroll
            for (int q = 0; q < 12; q++) {
                uint32_t bh[4], bl[4];
                ldsm4t(bh, bHb + bt + q * 32);
                ldsm4t(bl, bLb + bt + q * 32);
                mma16816(d[2 * q],     ah, bh);
                mma16816(d[2 * q],     al, bh);
                mma16816(d[2 * q],     ah, bl);
                mma16816(d[2 * q + 1], ah, bh + 2);
                mma16816(d[2 * q + 1], al, bh + 2);
                mma16816(d[2 * q + 1], ah, bl + 2);
            }
        }
    }

    __syncthreads();
    float* Dsm = reinterpret_cast<float*>(smc);
    {
        const int r0 = wid * 16 + (lane >> 2);
        const int cb = (lane & 3) * 2;
        #pragma unroll
        for (int nt = 0; nt < 24; nt++) {
            int n = nt * 8 + cb;
            Dsm[r0 * 200 + n]           = d[nt][0];
            Dsm[r0 * 200 + n + 1]       = d[nt][1];
            Dsm[(r0 + 8) * 200 + n]     = d[nt][2];
            Dsm[(r0 + 8) * 200 + n + 1] = d[nt][3];
        }
    }
    __syncthreads();
    for (int i = tid; i < 6400; i += 256) {
        int o = i >> 6, r = i & 63, s = r >> 5, t = r & 31;
        int n = s * 96 + t * 3;
        float v = fmaxf(Dsm[o * 200 + n], fmaxf(Dsm[o * 200 + n + 1], Dsm[o * 200 + n + 2]))
                  + __ldg(&b3[o]);
        g_y3p[(s0 + s) * 3200 + o * 32 + t] = pack_bf16_split(elu1(v));
    }
}

// ---------------- stage 4 (TENSOR): y3p -> feat ----------------
// per CTA (2 samples): D[256][48] = A(w4 pad 200->256)[256][1024] x B(im2col y3)[48][1024]^T
// n = seg*24 + j (j=0..20 valid conv positions, 21..23 zero); 8 K-chunks of 128.
#define S4_KP 136
#define S4_NP 56
#define S4_AH 0
#define S4_AL 69632
#define S4_BH 139264
#define S4_BL 153600
#define S4_SMEM 167936

__global__ __launch_bounds__(256, 1) void stage4_k(const float* __restrict__ b4)
{
    extern __shared__ char smc[];
    const uint32_t sb = smem_u32(smc);
    const int tid = threadIdx.x, wid = tid >> 5, lane = tid & 31;
    const int s0 = blockIdx.x * 2;

    float d[12][4];   // [m-tile 0/1][6 n8-tiles] -> index m*6+q
    #pragma unroll
    for (int i = 0; i < 12; i++)
        #pragma unroll
        for (int j = 0; j < 4; j++) d[i][j] = 0.f;

    // each warp owns rows [wid*32, wid*32+32): two m16 tiles
    const uint32_t aOff0 = ((wid * 32 + ((lane >> 3) & 1) * 8 + (lane & 7)) * S4_KP + (lane >> 4) * 8) * 2;
    const uint32_t aOff1 = aOff0 + 16 * S4_KP * 2;
    const uint32_t bOff = ((((lane >> 3) & 1) * 8 + (lane & 7)) * S4_NP + (lane >> 4) * 8) * 2;
    const uint32_t aH0 = sb + S4_AH + aOff0, aL0 = sb + S4_AL + aOff0;
    const uint32_t aH1 = sb + S4_AH + aOff1, aL1 = sb + S4_AL + aOff1;
    const uint32_t bHb = sb + S4_BH + bOff, bLb = sb + S4_BL + bOff;

    const int kloc = tid >> 1, seg = tid & 1;
    uint16_t* bhRow = reinterpret_cast<uint16_t*>(smc + S4_BH) + kloc * S4_NP + seg * 24;
    uint16_t* blRow = reinterpret_cast<uint16_t*>(smc + S4_BL) + kloc * S4_NP + seg * 24;

    for (int ch = 0; ch < 8; ch++) {
        __syncthreads();
        // A copy: 256x136 u16 per split = 4352 float4
        {
            const float4* srcH = reinterpret_cast<const float4*>(g_w4h + ch * 34816);
            const float4* srcL = reinterpret_cast<const float4*>(g_w4l + ch * 34816);
            float4* dstH = reinterpret_cast<float4*>(smc + S4_AH);
            float4* dstL = reinterpret_cast<float4*>(smc + S4_AL);
            #pragma unroll 1
            for (int i = tid; i < 4352; i += 256) { dstH[i] = srcH[i]; dstL[i] = srcL[i]; }
        }
        // B gather from packed y3
        {
            const int gk = ch * 128 + kloc;
            if (gk < 1000) {
                const int c = gk / 10, kk = gk - c * 10;
                const uint32_t* src = g_y3p + (s0 + seg) * 3200 + c * 32 + kk;
                #pragma unroll
                for (int j = 0; j < 24; j++) {
                    uint32_t p = (j < 21) ? __ldg(&src[j]) : 0u;
                    bhRow[j] = (uint16_t)(p & 0xffff);
                    blRow[j] = (uint16_t)(p >> 16);
                }
            } else {
                #pragma unroll
                for (int j = 0; j < 24; j++) { bhRow[j] = 0; blRow[j] = 0; }
            }
        }
        __syncthreads();

        #pragma unroll
        for (int t = 0; t < 8; t++) {
            uint32_t ah0[4], al0[4], ah1[4], al1[4];
            ldsm4(ah0, aH0 + t * 32);
            ldsm4(al0, aL0 + t * 32);
            ldsm4(ah1, aH1 + t * 32);
            ldsm4(al1, aL1 + t * 32);
            const uint32_t bt = (uint32_t)t * (16 * S4_NP * 2);
            #pragma unroll
            for (int q = 0; q < 3; q++) {
                uint32_t bh[4], bl[4];
                ldsm4t(bh, bHb + bt + q * 32);
                ldsm4t(bl, bLb + bt + q * 32);
                mma16816(d[2 * q],     ah0, bh);
                mma16816(d[2 * q],     al0, bh);
                mma16816(d[2 * q],     ah0, bl);
                mma16816(d[2 * q + 1], ah0, bh + 2);
                mma16816(d[2 * q + 1], al0, bh + 2);
                mma16816(d[2 * q + 1], ah0, bl + 2);
                mma16816(d[6 + 2 * q],     ah1, bh);
                mma16816(d[6 + 2 * q],     al1, bh);
                mma16816(d[6 + 2 * q],     ah1, bl);
                mma16816(d[6 + 2 * q + 1], ah1, bh + 2);
                mma16816(d[6 + 2 * q + 1], al1, bh + 2);
                mma16816(d[6 + 2 * q + 1], ah1, bl + 2);
            }
        }
    }

    // epilogue: D -> smem f32 [256][56], pool + ELU -> g_feat
    __syncthreads();
    float* Dsm = reinterpret_cast<float*>(smc);
    {
        const int r0 = wid * 32 + (lane >> 2);
        const int cb = (lane & 3) * 2;
        #pragma unroll
        for (int m = 0; m < 2; m++) {
            #pragma unroll
            for (int q = 0; q < 6; q++) {
                int row = r0 + m * 16;
                int n = q * 8 + cb;
                Dsm[row * 56 + n]           = d[m * 6 + q][0];
                Dsm[row * 56 + n + 1]       = d[m * 6 + q][1];
                Dsm[(row + 8) * 56 + n]     = d[m * 6 + q][2];
                Dsm[(row + 8) * 56 + n + 1] = d[m * 6 + q][3];
            }
        }
    }
    __syncthreads();
    for (int i = tid; i < 2800; i += 256) {
        int o = i / 14, r = i - o * 14, s = r / 7, t = r - s * 7;
        int n = s * 24 + t * 3;
        float v = fmaxf(Dsm[o * 56 + n], fmaxf(Dsm[o * 56 + n + 1], Dsm[o * 56 + n + 2]))
                  + __ldg(&b4[o]);
        g_feat[(s0 + s) * 1400 + o * 7 + t] = elu1(v);
    }
}

// ---------------- head ----------------
__global__ void head_k(const int* __restrict__ sid, const float* __restrict__ hW,
                       const float* __restrict__ hB, float* __restrict__ out)
{
    const int b = blockIdx.x;
    const int s = sid[b];
    const float* f = g_feat + b * 1400;
    const float* W = hW + s * (4 * 1400);
    float acc[4] = {0.f, 0.f, 0.f, 0.f};
    for (int i = threadIdx.x; i < 1400; i += blockDim.x) {
        float fv = f[i];
        #pragma unroll
        for (int o = 0; o < 4; o++) acc[o] = fmaf(fv, __ldg(&W[o * 1400 + i]), acc[o]);
    }
    #pragma unroll
    for (int off = 16; off > 0; off >>= 1) {
        #pragma unroll
        for (int o = 0; o < 4; o++) acc[o] += __shfl_down_sync(0xFFFFFFFFu, acc[o], off);
    }
    __shared__ float red[4][4];
    const int w = threadIdx.x >> 5, l = threadIdx.x & 31;
    if (l == 0) {
        #pragma unroll
        for (int o = 0; o < 4; o++) red[o][w] = acc[o];
    }
    __syncthreads();
    if (threadIdx.x < 4) {
        int o = threadIdx.x;
        out[b * 4 + o] = red[o][0] + red[o][1] + red[o][2] + red[o][3] + __ldg(&hB[s * 4 + o]);
    }
}

// ---------------- launch ----------------
extern "C" void kernel_launch(void* const* d_in, const int* in_sizes, int n_in,
                              void* d_out, int out_size)
{
    const float* x      = (const float*)d_in[0];
    const int*   sid    = (const int*)  d_in[1];
    const float* w_time = (const float*)d_in[2];
    const float* b_time = (const float*)d_in[3];
    const float* w_spat = (const float*)d_in[4];
    const float* b_spat = (const float*)d_in[5];
    const float* w2     = (const float*)d_in[6];
    const float* b2     = (const float*)d_in[7];
    const float* w3     = (const float*)d_in[8];
    const float* b3     = (const float*)d_in[9];
    const float* w4     = (const float*)d_in[10];
    const float* b4     = (const float*)d_in[11];
    const float* hW     = (const float*)d_in[12];
    const float* hB     = (const float*)d_in[13];
    float* out = (float*)d_out;

    const int smem1 = (22 * 504 + 25 * 264) * 4;     // 70,752
    cudaFuncSetAttribute(stage1_k, cudaFuncAttributeMaxDynamicSharedMemorySize, smem1);
    cudaFuncSetAttribute(stage2_k, cudaFuncAttributeMaxDynamicSharedMemorySize, S2_SMEM);
    cudaFuncSetAttribute(stage3_k, cudaFuncAttributeMaxDynamicSharedMemorySize, S3_SMEM);
    cudaFuncSetAttribute(stage4_k, cudaFuncAttributeMaxDynamicSharedMemorySize, S4_SMEM);

    precompute_k<<<1, 256>>>(w_time, b_time, w_spat, b_spat);
    precompute_w_k<<<(365568 + 255) / 256, 256>>>(w2, w3, w4);
    stage1_k<<<dim3(B_, 2), 352, smem1>>>(x);
    stage2_k<<<dim3(B_, 2), 256, S2_SMEM>>>(b2);
    stage3_k<<<128, 256, S3_SMEM>>>(b3);
    stage4_k<<<128, 256, S4_SMEM>>>(b4);
    head_k<<<B_, 128>>>(sid, hW, hB, out);
}

// round 10
// speedup vs baseline: 1.4712x; 1.1269x over previous
#include <cuda_runtime.h>
#include <cuda_bf16.h>
#include <math.h>
#include <stdint.h>

#define B_ 256

// ---------------- device scratch ----------------
__device__ float g_Weff[25 * 220];
__device__ float g_beff[25];
__device__ uint32_t g_y1p[B_ * 25 * 330];            // packed bf16 h | l<<16
__device__ uint32_t g_y2p[B_ * 50 * 107];
__device__ uint32_t g_y3p[B_ * 100 * 32];
__device__ float g_feat[B_ * 1400];
// chunk-image weights (bf16 split)
__device__ __align__(16) uint16_t g_w2h[2 * 64 * 136];
__device__ __align__(16) uint16_t g_w2l[2 * 64 * 136];
__device__ __align__(16) uint16_t g_w3h[4 * 128 * 136];
__device__ __align__(16) uint16_t g_w3l[4 * 128 * 136];
__device__ __align__(16) uint16_t g_w4h[8 * 256 * 136];
__device__ __align__(16) uint16_t g_w4l[8 * 256 * 136];

__device__ __forceinline__ float elu1(float x) { return x > 0.f ? x : expm1f(x); }

__device__ __forceinline__ uint32_t smem_u32(const void* p) {
    uint32_t a;
    asm("{ .reg .u64 t; cvta.to.shared.u64 t, %1; cvt.u32.u64 %0, t; }" : "=r"(a) : "l"(p));
    return a;
}
__device__ __forceinline__ void ldsm4(uint32_t* r, uint32_t addr) {
    asm volatile("ldmatrix.sync.aligned.m8n8.x4.shared.b16 {%0,%1,%2,%3}, [%4];"
                 : "=r"(r[0]), "=r"(r[1]), "=r"(r[2]), "=r"(r[3]) : "r"(addr));
}
__device__ __forceinline__ void ldsm4t(uint32_t* r, uint32_t addr) {
    asm volatile("ldmatrix.sync.aligned.m8n8.x4.trans.shared.b16 {%0,%1,%2,%3}, [%4];"
                 : "=r"(r[0]), "=r"(r[1]), "=r"(r[2]), "=r"(r[3]) : "r"(addr));
}
__device__ __forceinline__ void mma16816(float* d, const uint32_t* a, const uint32_t* b) {
    asm volatile("mma.sync.aligned.m16n8k16.row.col.f32.bf16.bf16.f32 "
                 "{%0,%1,%2,%3}, {%4,%5,%6,%7}, {%8,%9}, {%0,%1,%2,%3};"
                 : "+f"(d[0]), "+f"(d[1]), "+f"(d[2]), "+f"(d[3])
                 : "r"(a[0]), "r"(a[1]), "r"(a[2]), "r"(a[3]), "r"(b[0]), "r"(b[1]));
}
__device__ __forceinline__ uint32_t pack_bf16_split(float v) {
    __nv_bfloat16 h = __float2bfloat16(v);
    float hf = __bfloat162float(h);
    __nv_bfloat16 l = __float2bfloat16(v - hf);
    uint16_t hb = reinterpret_cast<uint16_t&>(h);
    uint16_t lb = reinterpret_cast<uint16_t&>(l);
    return (uint32_t)hb | ((uint32_t)lb << 16);
}

// ---------------- kernel 0: fold conv_time into conv_spat ----------------
__global__ void precompute_k(const float* __restrict__ w_time, const float* __restrict__ b_time,
                             const float* __restrict__ w_spat, const float* __restrict__ b_spat)
{
    for (int idx = threadIdx.x; idx < 25 * 220; idx += blockDim.x) {
        int p = idx / 220, rem = idx % 220, c = rem / 10, k = rem % 10;
        float s = 0.f;
        #pragma unroll
        for (int o = 0; o < 25; o++)
            s = fmaf(w_spat[p * 550 + o * 22 + c], w_time[o * 10 + k], s);
        g_Weff[idx] = s;
    }
    if (threadIdx.x < 25) {
        int p = threadIdx.x;
        float s = b_spat[p];
        for (int o = 0; o < 25; o++) {
            float w = 0.f;
            for (int c = 0; c < 22; c++) w += w_spat[p * 550 + o * 22 + c];
            s = fmaf(b_time[o], w, s);
        }
        g_beff[p] = s;
    }
}

// ---------------- kernel 0b: ALL weight chunk-images in one launch ----------------
__global__ void precompute_w_k(const float* __restrict__ w2, const float* __restrict__ w3,
                               const float* __restrict__ w4)
{
    int idx = blockIdx.x * 256 + threadIdx.x;
    if (idx < 17408) {
        int ch = idx / 8704, r = idx % 8704, row = r / 136, kloc = r % 136;
        int gk = ch * 128 + kloc;
        float v = (kloc < 128 && row < 50 && gk < 250) ? w2[row * 250 + gk] : 0.f;
        uint32_t p = pack_bf16_split(v);
        g_w2h[idx] = (uint16_t)(p & 0xffff);
        g_w2l[idx] = (uint16_t)(p >> 16);
    } else if (idx < 87040) {
        int i3 = idx - 17408;
        int ch = i3 / 17408, r = i3 % 17408, row = r / 136, kloc = r % 136;
        int gk = ch * 128 + kloc;
        float v = (kloc < 128 && row < 100 && gk < 500) ? w3[row * 500 + gk] : 0.f;
        uint32_t p = pack_bf16_split(v);
        g_w3h[i3] = (uint16_t)(p & 0xffff);
        g_w3l[i3] = (uint16_t)(p >> 16);
    } else if (idx < 365568) {
        int i4 = idx - 87040;
        int ch = i4 / 34816, r = i4 % 34816, row = r / 136, kloc = r % 136;
        int gk = ch * 128 + kloc;
        float v = (kloc < 128 && row < 200 && gk < 1000) ? w4[row * 1000 + gk] : 0.f;
        uint32_t p = pack_bf16_split(v);
        g_w4h[i4] = (uint16_t)(p & 0xffff);
        g_w4l[i4] = (uint16_t)(p >> 16);
    }
}

// ---------------- scalar conv body ----------------
template<int P, int C, int XS, int WS>
__device__ __forceinline__ void conv_acc(const float* __restrict__ xs,
                                         const float* __restrict__ ws,
                                         float* __restrict__ acc)
{
    #pragma unroll
    for (int i = 0; i < P * 3; i++) acc[i] = 0.f;
    #pragma unroll 1
    for (int c = 0; c < C; c++) {
        float xr[12];
        #pragma unroll
        for (int i = 0; i < 12; i++) xr[i] = xs[c * XS + i];
        #pragma unroll
        for (int p = 0; p < P; p++) {
            const float* wp = ws + p * WS + c * 12;
            float4 w0 = *reinterpret_cast<const float4*>(wp);
            float4 w1 = *reinterpret_cast<const float4*>(wp + 4);
            float2 w2 = *reinterpret_cast<const float2*>(wp + 8);
            float wk[10] = {w0.x, w0.y, w0.z, w0.w, w1.x, w1.y, w1.z, w1.w, w2.x, w2.y};
            #pragma unroll
            for (int k = 0; k < 10; k++) {
                acc[p * 3 + 0] = fmaf(wk[k], xr[k + 0], acc[p * 3 + 0]);
                acc[p * 3 + 1] = fmaf(wk[k], xr[k + 1], acc[p * 3 + 1]);
                acc[p * 3 + 2] = fmaf(wk[k], xr[k + 2], acc[p * 3 + 2]);
            }
        }
    }
}

// ---------------- stage 1 (scalar, proven): x -> y1p ----------------
__global__ __launch_bounds__(352, 2) void stage1_k(const float* __restrict__ x)
{
    extern __shared__ float sm[];
    float* xs = sm;                // [22][504]
    float* ws = sm + 22 * 504;     // [25][264]
    __shared__ float bs[25];
    const int b = blockIdx.x, half = blockIdx.y;
    const int xoff = half * 495;
    const float* xb = x + b * 22000;
    for (int i = threadIdx.x; i < 22 * 504; i += 352) {
        int c = i / 504, t = i - c * 504;
        xs[i] = xb[c * 1000 + xoff + t];
    }
    for (int i = threadIdx.x; i < 5500; i += 352) {
        int p = i / 220, r = i - p * 220;
        int c = r / 10, k = r - c * 10;
        ws[p * 264 + c * 12 + k] = g_Weff[i];
    }
    if (threadIdx.x < 25) bs[threadIdx.x] = g_beff[threadIdx.x];
    __syncthreads();

    const int tpL = threadIdx.x % 176;
    const int pg  = threadIdx.x / 176;
    if (tpL >= 165) return;
    const float* xp = xs + 3 * tpL;
    const int tp = half * 165 + tpL;

    if (pg == 0) {
        float acc[39];
        conv_acc<13, 22, 504, 264>(xp, ws, acc);
        #pragma unroll
        for (int p = 0; p < 13; p++) {
            float m = fmaxf(acc[p * 3], fmaxf(acc[p * 3 + 1], acc[p * 3 + 2])) + bs[p];
            g_y1p[b * 8250 + p * 330 + tp] = pack_bf16_split(elu1(m));
        }
    } else {
        float acc[36];
        conv_acc<12, 22, 504, 264>(xp, ws + 13 * 264, acc);
        #pragma unroll
        for (int p = 0; p < 12; p++) {
            float m = fmaxf(acc[p * 3], fmaxf(acc[p * 3 + 1], acc[p * 3 + 2])) + bs[13 + p];
            g_y1p[b * 8250 + (13 + p) * 330 + tp] = pack_bf16_split(elu1(m));
        }
    }
}

// ---------------- stage 2 (TENSOR, 3 n-tiles, 2 CTA/SM): y1p -> y2p ----------------
// grid (256, 3). D[64][112] = A(w2)[64][256] x B(im2col y1)[112][256]^T
// tile nt: pooled [p0, p0+np), p0 = {0,36,72}, np = {36,36,35}; n0 = 3*p0
#define S2_KP 136
#define S2_NP 120
#define S2_AH 0
#define S2_AL 17408
#define S2_BH 34816
#define S2_BL 65536
#define S2_SMEM 96256

__global__ __launch_bounds__(256, 2) void stage2_k(const float* __restrict__ b2)
{
    extern __shared__ char smc[];
    const uint32_t sb = smem_u32(smc);
    const int tid = threadIdx.x, wid = tid >> 5, lane = tid & 31;
    const int b = blockIdx.x, nt = blockIdx.y;
    const int p0 = nt * 36;
    const int np = (nt == 2) ? 35 : 36;
    const int n0 = 3 * p0;

    float d[7][4];
    #pragma unroll
    for (int i = 0; i < 7; i++)
        #pragma unroll
        for (int j = 0; j < 4; j++) d[i][j] = 0.f;

    const int mw = wid & 3, nw = wid >> 2;   // 4 m16-tiles x 2 n-halves(56)
    const uint32_t aOff = ((mw * 16 + ((lane >> 3) & 1) * 8 + (lane & 7)) * S2_KP + (lane >> 4) * 8) * 2;
    const uint32_t bOff = ((((lane >> 3) & 1) * 8 + (lane & 7)) * S2_NP + (lane >> 4) * 8 + nw * 56) * 2;
    const uint32_t aH = sb + S2_AH + aOff, aL = sb + S2_AL + aOff;
    const uint32_t bHb = sb + S2_BH + bOff, bLb = sb + S2_BL + bOff;

    const int kloc = tid >> 1, seg = tid & 1;
    uint16_t* bhRow = reinterpret_cast<uint16_t*>(smc + S2_BH) + kloc * S2_NP + seg * 56;
    uint16_t* blRow = reinterpret_cast<uint16_t*>(smc + S2_BL) + kloc * S2_NP + seg * 56;

    for (int ch = 0; ch < 2; ch++) {
        __syncthreads();
        {
            const float4* srcH = reinterpret_cast<const float4*>(g_w2h + ch * 8704);
            const float4* srcL = reinterpret_cast<const float4*>(g_w2l + ch * 8704);
            float4* dstH = reinterpret_cast<float4*>(smc + S2_AH);
            float4* dstL = reinterpret_cast<float4*>(smc + S2_AL);
            #pragma unroll 1
            for (int i = tid; i < 1088; i += 256) { dstH[i] = srcH[i]; dstL[i] = srcL[i]; }
        }
        {
            const int gk = ch * 128 + kloc;
            if (gk < 250) {
                const int c = gk / 10, kk = gk - c * 10;
                const uint32_t* src = g_y1p + b * 8250 + c * 330 + n0 + kk;
                const int jmax = 330 - n0 - kk;   // col cc valid while cc < jmax
                #pragma unroll 7
                for (int j = 0; j < 56; j += 2) {
                    int cc = seg * 56 + j;
                    uint32_t q0 = (cc < jmax)     ? __ldg(&src[cc])     : 0u;
                    uint32_t q1 = (cc + 1 < jmax) ? __ldg(&src[cc + 1]) : 0u;
                    *reinterpret_cast<uint32_t*>(bhRow + j) = __byte_perm(q0, q1, 0x5410);
                    *reinterpret_cast<uint32_t*>(blRow + j) = __byte_perm(q0, q1, 0x7632);
                }
            } else {
                #pragma unroll 7
                for (int j = 0; j < 56; j += 2) {
                    *reinterpret_cast<uint32_t*>(bhRow + j) = 0u;
                    *reinterpret_cast<uint32_t*>(blRow + j) = 0u;
                }
            }
        }
        __syncthreads();

        #pragma unroll
        for (int t = 0; t < 8; t++) {
            uint32_t ah[4], al[4];
            ldsm4(ah, aH + t * 32);
            ldsm4(al, aL + t * 32);
            const uint32_t bt = (uint32_t)t * (16 * S2_NP * 2);
            #pragma unroll
            for (int q = 0; q < 3; q++) {
                uint32_t bh[4], bl[4];
                ldsm4t(bh, bHb + bt + q * 32);
                ldsm4t(bl, bLb + bt + q * 32);
                mma16816(d[2 * q],     ah, bh);
                mma16816(d[2 * q],     al, bh);
                mma16816(d[2 * q],     ah, bl);
                mma16816(d[2 * q + 1], ah, bh + 2);
                mma16816(d[2 * q + 1], al, bh + 2);
                mma16816(d[2 * q + 1], ah, bl + 2);
            }
            {   // 7th n8 tile (cols 48..55): x4 trans load, use first pair only
                uint32_t bh[4], bl[4];
                ldsm4t(bh, bHb + bt + 3 * 32);
                ldsm4t(bl, bLb + bt + 3 * 32);
                mma16816(d[6], ah, bh);
                mma16816(d[6], al, bh);
                mma16816(d[6], ah, bl);
            }
        }
    }

    // epilogue: D -> smem f32 [64][120], pool + ELU + pack
    __syncthreads();
    float* Dsm = reinterpret_cast<float*>(smc);
    {
        const int r0 = mw * 16 + (lane >> 2);
        const int cb = (lane & 3) * 2;
        #pragma unroll
        for (int q = 0; q < 7; q++) {
            int n = nw * 56 + q * 8 + cb;
            Dsm[r0 * 120 + n]           = d[q][0];
            Dsm[r0 * 120 + n + 1]       = d[q][1];
            Dsm[(r0 + 8) * 120 + n]     = d[q][2];
            Dsm[(r0 + 8) * 120 + n + 1] = d[q][3];
        }
    }
    __syncthreads();
    const int cnt = 50 * np;
    for (int i = tid; i < cnt; i += 256) {
        int o = i / np, j = i - o * np;
        int nl = 3 * j;
        float v = fmaxf(Dsm[o * 120 + nl], fmaxf(Dsm[o * 120 + nl + 1], Dsm[o * 120 + nl + 2]))
                  + __ldg(&b2[o]);
        g_y2p[b * 5350 + o * 107 + p0 + j] = pack_bf16_split(elu1(v));
    }
}

// ---------------- stage 3 (TENSOR): y2p -> y3p ----------------
#define S3_KP 136
#define S3_NP 200
#define S3_AH 0
#define S3_AL 34816
#define S3_BH 69632
#define S3_BL 120832
#define S3_SMEM 172032

__global__ __launch_bounds__(256, 1) void stage3_k(const float* __restrict__ b3)
{
    extern __shared__ char smc[];
    const uint32_t sb = smem_u32(smc);
    const int tid = threadIdx.x, wid = tid >> 5, lane = tid & 31;
    const int s0 = blockIdx.x * 2;

    float d[24][4];
    #pragma unroll
    for (int i = 0; i < 24; i++)
        #pragma unroll
        for (int j = 0; j < 4; j++) d[i][j] = 0.f;

    const uint32_t aOff = ((wid * 16 + ((lane >> 3) & 1) * 8 + (lane & 7)) * S3_KP + (lane >> 4) * 8) * 2;
    const uint32_t bOff = ((((lane >> 3) & 1) * 8 + (lane & 7)) * S3_NP + (lane >> 4) * 8) * 2;
    const uint32_t aH = sb + S3_AH + aOff, aL = sb + S3_AL + aOff;
    const uint32_t bHb = sb + S3_BH + bOff, bLb = sb + S3_BL + bOff;

    const int kloc = tid >> 1, seg = tid & 1;
    uint16_t* bhRow = reinterpret_cast<uint16_t*>(smc + S3_BH) + kloc * S3_NP + seg * 96;
    uint16_t* blRow = reinterpret_cast<uint16_t*>(smc + S3_BL) + kloc * S3_NP + seg * 96;

    for (int ch = 0; ch < 4; ch++) {
        __syncthreads();
        {
            const float4* srcH = reinterpret_cast<const float4*>(g_w3h + ch * 17408);
            const float4* srcL = reinterpret_cast<const float4*>(g_w3l + ch * 17408);
            float4* dstH = reinterpret_cast<float4*>(smc + S3_AH);
            float4* dstL = reinterpret_cast<float4*>(smc + S3_AL);
            #pragma unroll 1
            for (int i = tid; i < 2176; i += 256) { dstH[i] = srcH[i]; dstL[i] = srcL[i]; }
        }
        {
            const int gk = ch * 128 + kloc;
            if (gk < 500) {
                const int c = gk / 10, kk = gk - c * 10;
                const uint32_t* src = g_y2p + (s0 + seg) * 5350 + c * 107 + kk;
                #pragma unroll 8
                for (int j = 0; j < 96; j += 2) {
                    uint32_t q0 = __ldg(&src[j]);
                    uint32_t q1 = __ldg(&src[j + 1]);
                    *reinterpret_cast<uint32_t*>(bhRow + j) = __byte_perm(q0, q1, 0x5410);
                    *reinterpret_cast<uint32_t*>(blRow + j) = __byte_perm(q0, q1, 0x7632);
                }
            } else {
                #pragma unroll 8
                for (int j = 0; j < 96; j += 2) {
                    *reinterpret_cast<uint32_t*>(bhRow + j) = 0u;
                    *reinterpret_cast<uint32_t*>(blRow + j) = 0u;
                }
            }
        }
        __syncthreads();

        #pragma unroll
        for (int t = 0; t < 8; t++) {
            uint32_t ah[4], al[4];
            ldsm4(ah, aH + t * 32);
            ldsm4(al, aL + t * 32);
            const uint32_t bt = (uint32_t)t * (16 * S3_NP * 2);
            #pragma unroll
            for (int q = 0; q < 12; q++) {
                uint32_t bh[4], bl[4];
                ldsm4t(bh, bHb + bt + q * 32);
                ldsm4t(bl, bLb + bt + q * 32);
                mma16816(d[2 * q],     ah, bh);
                mma16816(d[2 * q],     al, bh);
                mma16816(d[2 * q],     ah, bl);
                mma16816(d[2 * q + 1], ah, bh + 2);
                mma16816(d[2 * q + 1], al, bh + 2);
                mma16816(d[2 * q + 1], ah, bl + 2);
            }
        }
    }

    __syncthreads();
    float* Dsm = reinterpret_cast<float*>(smc);
    {
        const int r0 = wid * 16 + (lane >> 2);
        const int cb = (lane & 3) * 2;
        #pragma unroll
        for (int nt = 0; nt < 24; nt++) {
            int n = nt * 8 + cb;
            Dsm[r0 * 200 + n]           = d[nt][0];
            Dsm[r0 * 200 + n + 1]       = d[nt][1];
            Dsm[(r0 + 8) * 200 + n]     = d[nt][2];
            Dsm[(r0 + 8) * 200 + n + 1] = d[nt][3];
        }
    }
    __syncthreads();
    for (int i = tid; i < 6400; i += 256) {
        int o = i >> 6, r = i & 63, s = r >> 5, t = r & 31;
        int n = s * 96 + t * 3;
        float v = fmaxf(Dsm[o * 200 + n], fmaxf(Dsm[o * 200 + n + 1], Dsm[o * 200 + n + 2]))
                  + __ldg(&b3[o]);
        g_y3p[(s0 + s) * 3200 + o * 32 + t] = pack_bf16_split(elu1(v));
    }
}

// ---------------- stage 4 (TENSOR): y3p -> feat ----------------
#define S4_KP 136
#define S4_NP 56
#define S4_AH 0
#define S4_AL 69632
#define S4_BH 139264
#define S4_BL 153600
#define S4_SMEM 167936

__global__ __launch_bounds__(256, 1) void stage4_k(const float* __restrict__ b4)
{
    extern __shared__ char smc[];
    const uint32_t sb = smem_u32(smc);
    const int tid = threadIdx.x, wid = tid >> 5, lane = tid & 31;
    const int s0 = blockIdx.x * 2;

    float d[12][4];   // [m-tile 0/1][6 n8-tiles]
    #pragma unroll
    for (int i = 0; i < 12; i++)
        #pragma unroll
        for (int j = 0; j < 4; j++) d[i][j] = 0.f;

    const uint32_t aOff0 = ((wid * 32 + ((lane >> 3) & 1) * 8 + (lane & 7)) * S4_KP + (lane >> 4) * 8) * 2;
    const uint32_t aOff1 = aOff0 + 16 * S4_KP * 2;
    const uint32_t bOff = ((((lane >> 3) & 1) * 8 + (lane & 7)) * S4_NP + (lane >> 4) * 8) * 2;
    const uint32_t aH0 = sb + S4_AH + aOff0, aL0 = sb + S4_AL + aOff0;
    const uint32_t aH1 = sb + S4_AH + aOff1, aL1 = sb + S4_AL + aOff1;
    const uint32_t bHb = sb + S4_BH + bOff, bLb = sb + S4_BL + bOff;

    const int kloc = tid >> 1, seg = tid & 1;
    uint16_t* bhRow = reinterpret_cast<uint16_t*>(smc + S4_BH) + kloc * S4_NP + seg * 24;
    uint16_t* blRow = reinterpret_cast<uint16_t*>(smc + S4_BL) + kloc * S4_NP + seg * 24;

    for (int ch = 0; ch < 8; ch++) {
        __syncthreads();
        {
            const float4* srcH = reinterpret_cast<const float4*>(g_w4h + ch * 34816);
            const float4* srcL = reinterpret_cast<const float4*>(g_w4l + ch * 34816);
            float4* dstH = reinterpret_cast<float4*>(smc + S4_AH);
            float4* dstL = reinterpret_cast<float4*>(smc + S4_AL);
            #pragma unroll 1
            for (int i = tid; i < 4352; i += 256) { dstH[i] = srcH[i]; dstL[i] = srcL[i]; }
        }
        {
            const int gk = ch * 128 + kloc;
            if (gk < 1000) {
                const int c = gk / 10, kk = gk - c * 10;
                const uint32_t* src = g_y3p + (s0 + seg) * 3200 + c * 32 + kk;
                #pragma unroll
                for (int j = 0; j < 24; j += 2) {
                    uint32_t q0 = (j < 21)     ? __ldg(&src[j])     : 0u;
                    uint32_t q1 = (j + 1 < 21) ? __ldg(&src[j + 1]) : 0u;
                    *reinterpret_cast<uint32_t*>(bhRow + j) = __byte_perm(q0, q1, 0x5410);
                    *reinterpret_cast<uint32_t*>(blRow + j) = __byte_perm(q0, q1, 0x7632);
                }
            } else {
                #pragma unroll
                for (int j = 0; j < 24; j += 2) {
                    *reinterpret_cast<uint32_t*>(bhRow + j) = 0u;
                    *reinterpret_cast<uint32_t*>(blRow + j) = 0u;
                }
            }
        }
        __syncthreads();

        #pragma unroll
        for (int t = 0; t < 8; t++) {
            uint32_t ah0[4], al0[4], ah1[4], al1[4];
            ldsm4(ah0, aH0 + t * 32);
            ldsm4(al0, aL0 + t * 32);
            ldsm4(ah1, aH1 + t * 32);
            ldsm4(al1, aL1 + t * 32);
            const uint32_t bt = (uint32_t)t * (16 * S4_NP * 2);
            #pragma unroll
            for (int q = 0; q < 3; q++) {
                uint32_t bh[4], bl[4];
                ldsm4t(bh, bHb + bt + q * 32);
                ldsm4t(bl, bLb + bt + q * 32);
                mma16816(d[2 * q],     ah0, bh);
                mma16816(d[2 * q],     al0, bh);
                mma16816(d[2 * q],     ah0, bl);
                mma16816(d[2 * q + 1], ah0, bh + 2);
                mma16816(d[2 * q + 1], al0, bh + 2);
                mma16816(d[2 * q + 1], ah0, bl + 2);
                mma16816(d[6 + 2 * q],     ah1, bh);
                mma16816(d[6 + 2 * q],     al1, bh);
                mma16816(d[6 + 2 * q],     ah1, bl);
                mma16816(d[6 + 2 * q + 1], ah1, bh + 2);
                mma16816(d[6 + 2 * q + 1], al1, bh + 2);
                mma16816(d[6 + 2 * q + 1], ah1, bl + 2);
            }
        }
    }

    __syncthreads();
    float* Dsm = reinterpret_cast<float*>(smc);
    {
        const int r0 = wid * 32 + (lane >> 2);
        const int cb = (lane & 3) * 2;
        #pragma unroll
        for (int m = 0; m < 2; m++) {
            #pragma unroll
            for (int q = 0; q < 6; q++) {
                int row = r0 + m * 16;
                int n = q * 8 + cb;
                Dsm[row * 56 + n]           = d[m * 6 + q][0];
                Dsm[row * 56 + n + 1]       = d[m * 6 + q][1];
                Dsm[(row + 8) * 56 + n]     = d[m * 6 + q][2];
                Dsm[(row + 8) * 56 + n + 1] = d[m * 6 + q][3];
            }
        }
    }
    __syncthreads();
    for (int i = tid; i < 2800; i += 256) {
        int o = i / 14, r = i - o * 14, s = r / 7, t = r - s * 7;
        int n = s * 24 + t * 3;
        float v = fmaxf(Dsm[o * 56 + n], fmaxf(Dsm[o * 56 + n + 1], Dsm[o * 56 + n + 2]))
                  + __ldg(&b4[o]);
        g_feat[(s0 + s) * 1400 + o * 7 + t] = elu1(v);
    }
}

// ---------------- head ----------------
__global__ void head_k(const int* __restrict__ sid, const float* __restrict__ hW,
                       const float* __restrict__ hB, float* __restrict__ out)
{
    const int b = blockIdx.x;
    const int s = sid[b];
    const float* f = g_feat + b * 1400;
    const float* W = hW + s * (4 * 1400);
    float acc[4] = {0.f, 0.f, 0.f, 0.f};
    for (int i = threadIdx.x; i < 1400; i += blockDim.x) {
        float fv = f[i];
        #pragma unroll
        for (int o = 0; o < 4; o++) acc[o] = fmaf(fv, __ldg(&W[o * 1400 + i]), acc[o]);
    }
    #pragma unroll
    for (int off = 16; off > 0; off >>= 1) {
        #pragma unroll
        for (int o = 0; o < 4; o++) acc[o] += __shfl_down_sync(0xFFFFFFFFu, acc[o], off);
    }
    __shared__ float red[4][4];
    const int w = threadIdx.x >> 5, l = threadIdx.x & 31;
    if (l == 0) {
        #pragma unroll
        for (int o = 0; o < 4; o++) red[o][w] = acc[o];
    }
    __syncthreads();
    if (threadIdx.x < 4) {
        int o = threadIdx.x;
        out[b * 4 + o] = red[o][0] + red[o][1] + red[o][2] + red[o][3] + __ldg(&hB[s * 4 + o]);
    }
}

// ---------------- launch ----------------
extern "C" void kernel_launch(void* const* d_in, const int* in_sizes, int n_in,
                              void* d_out, int out_size)
{
    const float* x      = (const float*)d_in[0];
    const int*   sid    = (const int*)  d_in[1];
    const float* w_time = (const float*)d_in[2];
    const float* b_time = (const float*)d_in[3];
    const float* w_spat = (const float*)d_in[4];
    const float* b_spat = (const float*)d_in[5];
    const float* w2     = (const float*)d_in[6];
    const float* b2     = (const float*)d_in[7];
    const float* w3     = (const float*)d_in[8];
    const float* b3     = (const float*)d_in[9];
    const float* w4     = (const float*)d_in[10];
    const float* b4     = (const float*)d_in[11];
    const float* hW     = (const float*)d_in[12];
    const float* hB     = (const float*)d_in[13];
    float* out = (float*)d_out;

    const int smem1 = (22 * 504 + 25 * 264) * 4;     // 70,752
    cudaFuncSetAttribute(stage1_k, cudaFuncAttributeMaxDynamicSharedMemorySize, smem1);
    cudaFuncSetAttribute(stage2_k, cudaFuncAttributeMaxDynamicSharedMemorySize, S2_SMEM);
    cudaFuncSetAttribute(stage3_k, cudaFuncAttributeMaxDynamicSharedMemorySize, S3_SMEM);
    cudaFuncSetAttribute(stage4_k, cudaFuncAttributeMaxDynamicSharedMemorySize, S4_SMEM);

    precompute_k<<<1, 256>>>(w_time, b_time, w_spat, b_spat);
    precompute_w_k<<<(365568 + 255) / 256, 256>>>(w2, w3, w4);
    stage1_k<<<dim3(B_, 2), 352, smem1>>>(x);
    stage2_k<<<dim3(B_, 3), 256, S2_SMEM>>>(b2);
    stage3_k<<<128, 256, S3_SMEM>>>(b3);
    stage4_k<<<128, 256, S4_SMEM>>>(b4);
    head_k<<<B_, 128>>>(sid, hW, hB, out);
}

// round 11
// speedup vs baseline: 1.7587x; 1.1954x over previous
#include <cuda_runtime.h>
#include <cuda_bf16.h>
#include <math.h>
#include <stdint.h>

#define B_ 256

// ---------------- device scratch ----------------
__device__ float g_Weff[25 * 220];
__device__ float g_beff[25];
__device__ uint32_t g_y1p[B_ * 25 * 330];            // packed bf16 h | l<<16
__device__ uint32_t g_y2p[B_ * 50 * 107];
__device__ uint32_t g_y3p[B_ * 100 * 32];
__device__ float g_feat[B_ * 1400];
// chunk-image weights (bf16 split)
__device__ __align__(16) uint16_t g_w1h[10 * 32 * 40];   // [tap][c row][o col], stride 40
__device__ __align__(16) uint16_t g_w1l[10 * 32 * 40];
__device__ __align__(16) uint16_t g_w2h[2 * 64 * 136];
__device__ __align__(16) uint16_t g_w2l[2 * 64 * 136];
__device__ __align__(16) uint16_t g_w3h[4 * 128 * 136];
__device__ __align__(16) uint16_t g_w3l[4 * 128 * 136];
__device__ __align__(16) uint16_t g_w4h[8 * 256 * 136];
__device__ __align__(16) uint16_t g_w4l[8 * 256 * 136];

__device__ __forceinline__ float elu1(float x) { return x > 0.f ? x : expm1f(x); }

__device__ __forceinline__ uint32_t smem_u32(const void* p) {
    uint32_t a;
    asm("{ .reg .u64 t; cvta.to.shared.u64 t, %1; cvt.u32.u64 %0, t; }" : "=r"(a) : "l"(p));
    return a;
}
__device__ __forceinline__ void ldsm4(uint32_t* r, uint32_t addr) {
    asm volatile("ldmatrix.sync.aligned.m8n8.x4.shared.b16 {%0,%1,%2,%3}, [%4];"
                 : "=r"(r[0]), "=r"(r[1]), "=r"(r[2]), "=r"(r[3]) : "r"(addr));
}
__device__ __forceinline__ void ldsm4t(uint32_t* r, uint32_t addr) {
    asm volatile("ldmatrix.sync.aligned.m8n8.x4.trans.shared.b16 {%0,%1,%2,%3}, [%4];"
                 : "=r"(r[0]), "=r"(r[1]), "=r"(r[2]), "=r"(r[3]) : "r"(addr));
}
__device__ __forceinline__ void mma16816(float* d, const uint32_t* a, const uint32_t* b) {
    asm volatile("mma.sync.aligned.m16n8k16.row.col.f32.bf16.bf16.f32 "
                 "{%0,%1,%2,%3}, {%4,%5,%6,%7}, {%8,%9}, {%0,%1,%2,%3};"
                 : "+f"(d[0]), "+f"(d[1]), "+f"(d[2]), "+f"(d[3])
                 : "r"(a[0]), "r"(a[1]), "r"(a[2]), "r"(a[3]), "r"(b[0]), "r"(b[1]));
}
__device__ __forceinline__ uint32_t pack_bf16_split(float v) {
    __nv_bfloat16 h = __float2bfloat16(v);
    float hf = __bfloat162float(h);
    __nv_bfloat16 l = __float2bfloat16(v - hf);
    uint16_t hb = reinterpret_cast<uint16_t&>(h);
    uint16_t lb = reinterpret_cast<uint16_t&>(l);
    return (uint32_t)hb | ((uint32_t)lb << 16);
}

// ---------------- kernel 0: fold conv_time into conv_spat ----------------
__global__ void precompute_k(const float* __restrict__ w_time, const float* __restrict__ b_time,
                             const float* __restrict__ w_spat, const float* __restrict__ b_spat)
{
    for (int idx = threadIdx.x; idx < 25 * 220; idx += blockDim.x) {
        int p = idx / 220, rem = idx % 220, c = rem / 10, k = rem % 10;
        float s = 0.f;
        #pragma unroll
        for (int o = 0; o < 25; o++)
            s = fmaf(w_spat[p * 550 + o * 22 + c], w_time[o * 10 + k], s);
        g_Weff[idx] = s;
    }
    if (threadIdx.x < 25) {
        int p = threadIdx.x;
        float s = b_spat[p];
        for (int o = 0; o < 25; o++) {
            float w = 0.f;
            for (int c = 0; c < 22; c++) w += w_spat[p * 550 + o * 22 + c];
            s = fmaf(b_time[o], w, s);
        }
        g_beff[p] = s;
    }
}

// ---------------- kernel 0b: ALL weight images in one launch ----------------
__global__ void precompute_w_k(const float* __restrict__ w2, const float* __restrict__ w3,
                               const float* __restrict__ w4)
{
    int idx = blockIdx.x * 256 + threadIdx.x;
    if (idx < 17408) {
        int ch = idx / 8704, r = idx % 8704, row = r / 136, kloc = r % 136;
        int gk = ch * 128 + kloc;
        float v = (kloc < 128 && row < 50 && gk < 250) ? w2[row * 250 + gk] : 0.f;
        uint32_t p = pack_bf16_split(v);
        g_w2h[idx] = (uint16_t)(p & 0xffff);
        g_w2l[idx] = (uint16_t)(p >> 16);
    } else if (idx < 87040) {
        int i3 = idx - 17408;
        int ch = i3 / 17408, r = i3 % 17408, row = r / 136, kloc = r % 136;
        int gk = ch * 128 + kloc;
        float v = (kloc < 128 && row < 100 && gk < 500) ? w3[row * 500 + gk] : 0.f;
        uint32_t p = pack_bf16_split(v);
        g_w3h[i3] = (uint16_t)(p & 0xffff);
        g_w3l[i3] = (uint16_t)(p >> 16);
    } else if (idx < 365568) {
        int i4 = idx - 87040;
        int ch = i4 / 34816, r = i4 % 34816, row = r / 136, kloc = r % 136;
        int gk = ch * 128 + kloc;
        float v = (kloc < 128 && row < 200 && gk < 1000) ? w4[row * 1000 + gk] : 0.f;
        uint32_t p = pack_bf16_split(v);
        g_w4h[i4] = (uint16_t)(p & 0xffff);
        g_w4l[i4] = (uint16_t)(p >> 16);
    } else if (idx < 365568 + 12800) {
        // w1 image: [tap kk][c row (32)][o col (40)] = Weff[o][c*10+kk]
        int i1 = idx - 365568;
        int kk = i1 / 1280, r = i1 % 1280, c = r / 40, o = r % 40;
        float v = (c < 22 && o < 25) ? g_Weff[o * 220 + c * 10 + kk] : 0.f;
        uint32_t p = pack_bf16_split(v);
        g_w1h[i1] = (uint16_t)(p & 0xffff);
        g_w1l[i1] = (uint16_t)(p >> 16);
    }
}

// ---------------- stage 1 (TENSOR, tap-decomposed): x -> y1p ----------------
// per CTA (sample b, tile of 192 positions): D[192 m][32 n=ch] = Σ_kk xT[m+kk][c] W_kk[c][o]
// A = xT [208 rows][40 k-pad], row stride 80 B (conflict-free); taps = row offsets.
// W resident: [10][32][40] per split. Single fill, no chunking.
#define S1_AH 0
#define S1_AL 16640
#define S1_WH 33280
#define S1_WL 58880
#define S1_SMEM 84480

__global__ __launch_bounds__(384, 2) void stage1_k(const float* __restrict__ x)
{
    extern __shared__ char smc[];
    const uint32_t sb = smem_u32(smc);
    const int tid = threadIdx.x, wid = tid >> 5, lane = tid & 31;
    const int b = blockIdx.x, tile = blockIdx.y;
    const int m0 = tile * 192;
    __shared__ float bs[25];
    if (tid < 25) bs[tid] = g_beff[tid];

    // W fill: 1600 float4 per split
    {
        const float4* srcH = reinterpret_cast<const float4*>(g_w1h);
        const float4* srcL = reinterpret_cast<const float4*>(g_w1l);
        float4* dstH = reinterpret_cast<float4*>(smc + S1_WH);
        float4* dstL = reinterpret_cast<float4*>(smc + S1_WL);
        #pragma unroll 1
        for (int i = tid; i < 1600; i += 384) { dstH[i] = srcH[i]; dstL[i] = srcL[i]; }
    }
    // A fill: 208 rows x 20 u32-cols (40 u16); col pair cp covers channels 2cp,2cp+1
    {
        const float* xb = x + b * 22000;
        #pragma unroll 1
        for (int i = tid; i < 4160; i += 384) {
            int cp = i / 208, r = i - cp * 208;
            int t = m0 + r;
            uint32_t h2 = 0u, l2 = 0u;
            if (cp < 11 && t < 1000) {
                uint32_t p0 = pack_bf16_split(__ldg(&xb[(2 * cp) * 1000 + t]));
                uint32_t p1 = pack_bf16_split(__ldg(&xb[(2 * cp + 1) * 1000 + t]));
                h2 = __byte_perm(p0, p1, 0x5410);
                l2 = __byte_perm(p0, p1, 0x7632);
            }
            reinterpret_cast<uint32_t*>(smc + S1_AH)[r * 20 + cp] = h2;
            reinterpret_cast<uint32_t*>(smc + S1_AL)[r * 20 + cp] = l2;
        }
    }
    __syncthreads();

    float d[4][4];
    #pragma unroll
    for (int i = 0; i < 4; i++)
        #pragma unroll
        for (int j = 0; j < 4; j++) d[i][j] = 0.f;

    // A lane base: row = wid*16 + ldsm row, col-group (lane>>4)*8
    const uint32_t aOff = ((wid * 16 + ((lane >> 3) & 1) * 8 + (lane & 7)) * 40 + (lane >> 4) * 8) * 2;
    const uint32_t aHb = sb + S1_AH + aOff, aLb = sb + S1_AL + aOff;
    const uint32_t bOff = ((((lane >> 3) & 1) * 8 + (lane & 7)) * 40 + (lane >> 4) * 8) * 2;
    const uint32_t bHb = sb + S1_WH + bOff, bLb = sb + S1_WL + bOff;

    #pragma unroll 1
    for (int kk = 0; kk < 10; kk++) {
        #pragma unroll
        for (int s = 0; s < 2; s++) {
            uint32_t ah[4], al[4];
            ldsm4(ah, aHb + kk * 80 + s * 32);
            ldsm4(al, aLb + kk * 80 + s * 32);
            const uint32_t wb = (uint32_t)kk * 2560 + (uint32_t)s * 1280;
            #pragma unroll
            for (int q = 0; q < 2; q++) {
                uint32_t bh[4], bl[4];
                ldsm4t(bh, bHb + wb + q * 32);
                ldsm4t(bl, bLb + wb + q * 32);
                mma16816(d[2 * q],     ah, bh);
                mma16816(d[2 * q],     al, bh);
                mma16816(d[2 * q],     ah, bl);
                mma16816(d[2 * q + 1], ah, bh + 2);
                mma16816(d[2 * q + 1], al, bh + 2);
                mma16816(d[2 * q + 1], ah, bl + 2);
            }
        }
    }

    // epilogue: Dsm [32 ch][200 m] f32 (25.6 KB, reuses A region)
    __syncthreads();
    float* Dsm = reinterpret_cast<float*>(smc);
    {
        const int mloc = wid * 16 + (lane >> 2);
        const int cb = (lane & 3) * 2;
        #pragma unroll
        for (int q = 0; q < 4; q++) {
            int n = q * 8 + cb;
            Dsm[n * 200 + mloc]           = d[q][0];
            Dsm[(n + 1) * 200 + mloc]     = d[q][1];
            Dsm[n * 200 + mloc + 8]       = d[q][2];
            Dsm[(n + 1) * 200 + mloc + 8] = d[q][3];
        }
    }
    __syncthreads();
    #pragma unroll 1
    for (int i = tid; i < 1600; i += 384) {
        int o = i >> 6, j = i & 63;
        int tp = tile * 64 + j;
        if (o < 25 && tp < 330) {
            const float* row = Dsm + o * 200 + 3 * j;
            float v = fmaxf(row[0], fmaxf(row[1], row[2])) + bs[o];
            g_y1p[b * 8250 + o * 330 + tp] = pack_bf16_split(elu1(v));
        }
    }
}

// ---------------- stage 2 (TENSOR, 3 n-tiles, 2 CTA/SM): y1p -> y2p ----------------
#define S2_KP 136
#define S2_NP 120
#define S2_AH 0
#define S2_AL 17408
#define S2_BH 34816
#define S2_BL 65536
#define S2_SMEM 96256

__global__ __launch_bounds__(256, 2) void stage2_k(const float* __restrict__ b2)
{
    extern __shared__ char smc[];
    const uint32_t sb = smem_u32(smc);
    const int tid = threadIdx.x, wid = tid >> 5, lane = tid & 31;
    const int b = blockIdx.x, nt = blockIdx.y;
    const int p0 = nt * 36;
    const int np = (nt == 2) ? 35 : 36;
    const int n0 = 3 * p0;

    float d[7][4];
    #pragma unroll
    for (int i = 0; i < 7; i++)
        #pragma unroll
        for (int j = 0; j < 4; j++) d[i][j] = 0.f;

    const int mw = wid & 3, nw = wid >> 2;
    const uint32_t aOff = ((mw * 16 + ((lane >> 3) & 1) * 8 + (lane & 7)) * S2_KP + (lane >> 4) * 8) * 2;
    const uint32_t bOff = ((((lane >> 3) & 1) * 8 + (lane & 7)) * S2_NP + (lane >> 4) * 8 + nw * 56) * 2;
    const uint32_t aH = sb + S2_AH + aOff, aL = sb + S2_AL + aOff;
    const uint32_t bHb = sb + S2_BH + bOff, bLb = sb + S2_BL + bOff;

    const int kloc = tid >> 1, seg = tid & 1;
    uint16_t* bhRow = reinterpret_cast<uint16_t*>(smc + S2_BH) + kloc * S2_NP + seg * 56;
    uint16_t* blRow = reinterpret_cast<uint16_t*>(smc + S2_BL) + kloc * S2_NP + seg * 56;

    for (int ch = 0; ch < 2; ch++) {
        __syncthreads();
        {
            const float4* srcH = reinterpret_cast<const float4*>(g_w2h + ch * 8704);
            const float4* srcL = reinterpret_cast<const float4*>(g_w2l + ch * 8704);
            float4* dstH = reinterpret_cast<float4*>(smc + S2_AH);
            float4* dstL = reinterpret_cast<float4*>(smc + S2_AL);
            #pragma unroll 1
            for (int i = tid; i < 1088; i += 256) { dstH[i] = srcH[i]; dstL[i] = srcL[i]; }
        }
        {
            const int gk = ch * 128 + kloc;
            if (gk < 250) {
                const int c = gk / 10, kk = gk - c * 10;
                const uint32_t* src = g_y1p + b * 8250 + c * 330 + n0 + kk;
                const int jmax = 330 - n0 - kk;
                #pragma unroll 7
                for (int j = 0; j < 56; j += 2) {
                    int cc = seg * 56 + j;
                    uint32_t q0 = (cc < jmax)     ? __ldg(&src[cc])     : 0u;
                    uint32_t q1 = (cc + 1 < jmax) ? __ldg(&src[cc + 1]) : 0u;
                    *reinterpret_cast<uint32_t*>(bhRow + j) = __byte_perm(q0, q1, 0x5410);
                    *reinterpret_cast<uint32_t*>(blRow + j) = __byte_perm(q0, q1, 0x7632);
                }
            } else {
                #pragma unroll 7
                for (int j = 0; j < 56; j += 2) {
                    *reinterpret_cast<uint32_t*>(bhRow + j) = 0u;
                    *reinterpret_cast<uint32_t*>(blRow + j) = 0u;
                }
            }
        }
        __syncthreads();

        #pragma unroll
        for (int t = 0; t < 8; t++) {
            uint32_t ah[4], al[4];
            ldsm4(ah, aH + t * 32);
            ldsm4(al, aL + t * 32);
            const uint32_t bt = (uint32_t)t * (16 * S2_NP * 2);
            #pragma unroll
            for (int q = 0; q < 3; q++) {
                uint32_t bh[4], bl[4];
                ldsm4t(bh, bHb + bt + q * 32);
                ldsm4t(bl, bLb + bt + q * 32);
                mma16816(d[2 * q],     ah, bh);
                mma16816(d[2 * q],     al, bh);
                mma16816(d[2 * q],     ah, bl);
                mma16816(d[2 * q + 1], ah, bh + 2);
                mma16816(d[2 * q + 1], al, bh + 2);
                mma16816(d[2 * q + 1], ah, bl + 2);
            }
            {
                uint32_t bh[4], bl[4];
                ldsm4t(bh, bHb + bt + 3 * 32);
                ldsm4t(bl, bLb + bt + 3 * 32);
                mma16816(d[6], ah, bh);
                mma16816(d[6], al, bh);
                mma16816(d[6], ah, bl);
            }
        }
    }

    __syncthreads();
    float* Dsm = reinterpret_cast<float*>(smc);
    {
        const int r0 = mw * 16 + (lane >> 2);
        const int cb = (lane & 3) * 2;
        #pragma unroll
        for (int q = 0; q < 7; q++) {
            int n = nw * 56 + q * 8 + cb;
            Dsm[r0 * 120 + n]           = d[q][0];
            Dsm[r0 * 120 + n + 1]       = d[q][1];
            Dsm[(r0 + 8) * 120 + n]     = d[q][2];
            Dsm[(r0 + 8) * 120 + n + 1] = d[q][3];
        }
    }
    __syncthreads();
    const int cnt = 50 * np;
    for (int i = tid; i < cnt; i += 256) {
        int o = i / np, j = i - o * np;
        int nl = 3 * j;
        float v = fmaxf(Dsm[o * 120 + nl], fmaxf(Dsm[o * 120 + nl + 1], Dsm[o * 120 + nl + 2]))
                  + __ldg(&b2[o]);
        g_y2p[b * 5350 + o * 107 + p0 + j] = pack_bf16_split(elu1(v));
    }
}

// ---------------- stage 3 (TENSOR): y2p -> y3p ----------------
#define S3_KP 136
#define S3_NP 200
#define S3_AH 0
#define S3_AL 34816
#define S3_BH 69632
#define S3_BL 120832
#define S3_SMEM 172032

__global__ __launch_bounds__(256, 1) void stage3_k(const float* __restrict__ b3)
{
    extern __shared__ char smc[];
    const uint32_t sb = smem_u32(smc);
    const int tid = threadIdx.x, wid = tid >> 5, lane = tid & 31;
    const int s0 = blockIdx.x * 2;

    float d[24][4];
    #pragma unroll
    for (int i = 0; i < 24; i++)
        #pragma unroll
        for (int j = 0; j < 4; j++) d[i][j] = 0.f;

    const uint32_t aOff = ((wid * 16 + ((lane >> 3) & 1) * 8 + (lane & 7)) * S3_KP + (lane >> 4) * 8) * 2;
    const uint32_t bOff = ((((lane >> 3) & 1) * 8 + (lane & 7)) * S3_NP + (lane >> 4) * 8) * 2;
    const uint32_t aH = sb + S3_AH + aOff, aL = sb + S3_AL + aOff;
    const uint32_t bHb = sb + S3_BH + bOff, bLb = sb + S3_BL + bOff;

    const int kloc = tid >> 1, seg = tid & 1;
    uint16_t* bhRow = reinterpret_cast<uint16_t*>(smc + S3_BH) + kloc * S3_NP + seg * 96;
    uint16_t* blRow = reinterpret_cast<uint16_t*>(smc + S3_BL) + kloc * S3_NP + seg * 96;

    for (int ch = 0; ch < 4; ch++) {
        __syncthreads();
        {
            const float4* srcH = reinterpret_cast<const float4*>(g_w3h + ch * 17408);
            const float4* srcL = reinterpret_cast<const float4*>(g_w3l + ch * 17408);
            float4* dstH = reinterpret_cast<float4*>(smc + S3_AH);
            float4* dstL = reinterpret_cast<float4*>(smc + S3_AL);
            #pragma unroll 1
            for (int i = tid; i < 2176; i += 256) { dstH[i] = srcH[i]; dstL[i] = srcL[i]; }
        }
        {
            const int gk = ch * 128 + kloc;
            if (gk < 500) {
                const int c = gk / 10, kk = gk - c * 10;
                const uint32_t* src = g_y2p + (s0 + seg) * 5350 + c * 107 + kk;
                #pragma unroll 8
                for (int j = 0; j < 96; j += 2) {
                    uint32_t q0 = __ldg(&src[j]);
                    uint32_t q1 = __ldg(&src[j + 1]);
                    *reinterpret_cast<uint32_t*>(bhRow + j) = __byte_perm(q0, q1, 0x5410);
                    *reinterpret_cast<uint32_t*>(blRow + j) = __byte_perm(q0, q1, 0x7632);
                }
            } else {
                #pragma unroll 8
                for (int j = 0; j < 96; j += 2) {
                    *reinterpret_cast<uint32_t*>(bhRow + j) = 0u;
                    *reinterpret_cast<uint32_t*>(blRow + j) = 0u;
                }
            }
        }
        __syncthreads();

        #pragma unroll
        for (int t = 0; t < 8; t++) {
            uint32_t ah[4], al[4];
            ldsm4(ah, aH + t * 32);
            ldsm4(al, aL + t * 32);
            const uint32_t bt = (uint32_t)t * (16 * S3_NP * 2);
            #pragma unroll
            for (int q = 0; q < 12; q++) {
                uint32_t bh[4], bl[4];
                ldsm4t(bh, bHb + bt + q * 32);
                ldsm4t(bl, bLb + bt + q * 32);
                mma16816(d[2 * q],     ah, bh);
                mma16816(d[2 * q],     al, bh);
                mma16816(d[2 * q],     ah, bl);
                mma16816(d[2 * q + 1], ah, bh + 2);
                mma16816(d[2 * q + 1], al, bh + 2);
                mma16816(d[2 * q + 1], ah, bl + 2);
            }
        }
    }

    __syncthreads();
    float* Dsm = reinterpret_cast<float*>(smc);
    {
        const int r0 = wid * 16 + (lane >> 2);
        const int cb = (lane & 3) * 2;
        #pragma unroll
        for (int nt = 0; nt < 24; nt++) {
            int n = nt * 8 + cb;
            Dsm[r0 * 200 + n]           = d[nt][0];
            Dsm[r0 * 200 + n + 1]       = d[nt][1];
            Dsm[(r0 + 8) * 200 + n]     = d[nt][2];
            Dsm[(r0 + 8) * 200 + n + 1] = d[nt][3];
        }
    }
    __syncthreads();
    for (int i = tid; i < 6400; i += 256) {
        int o = i >> 6, r = i & 63, s = r >> 5, t = r & 31;
        int n = s * 96 + t * 3;
        float v = fmaxf(Dsm[o * 200 + n], fmaxf(Dsm[o * 200 + n + 1], Dsm[o * 200 + n + 2]))
                  + __ldg(&b3[o]);
        g_y3p[(s0 + s) * 3200 + o * 32 + t] = pack_bf16_split(elu1(v));
    }
}

// ---------------- stage 4 (TENSOR): y3p -> feat ----------------
#define S4_KP 136
#define S4_NP 56
#define S4_AH 0
#define S4_AL 69632
#define S4_BH 139264
#define S4_BL 153600
#define S4_SMEM 167936

__global__ __launch_bounds__(256, 1) void stage4_k(const float* __restrict__ b4)
{
    extern __shared__ char smc[];
    const uint32_t sb = smem_u32(smc);
    const int tid = threadIdx.x, wid = tid >> 5, lane = tid & 31;
    const int s0 = blockIdx.x * 2;

    float d[12][4];
    #pragma unroll
    for (int i = 0; i < 12; i++)
        #pragma unroll
        for (int j = 0; j < 4; j++) d[i][j] = 0.f;

    const uint32_t aOff0 = ((wid * 32 + ((lane >> 3) & 1) * 8 + (lane & 7)) * S4_KP + (lane >> 4) * 8) * 2;
    const uint32_t aOff1 = aOff0 + 16 * S4_KP * 2;
    const uint32_t bOff = ((((lane >> 3) & 1) * 8 + (lane & 7)) * S4_NP + (lane >> 4) * 8) * 2;
    const uint32_t aH0 = sb + S4_AH + aOff0, aL0 = sb + S4_AL + aOff0;
    const uint32_t aH1 = sb + S4_AH + aOff1, aL1 = sb + S4_AL + aOff1;
    const uint32_t bHb = sb + S4_BH + bOff, bLb = sb + S4_BL + bOff;

    const int kloc = tid >> 1, seg = tid & 1;
    uint16_t* bhRow = reinterpret_cast<uint16_t*>(smc + S4_BH) + kloc * S4_NP + seg * 24;
    uint16_t* blRow = reinterpret_cast<uint16_t*>(smc + S4_BL) + kloc * S4_NP + seg * 24;

    for (int ch = 0; ch < 8; ch++) {
        __syncthreads();
        {
            const float4* srcH = reinterpret_cast<const float4*>(g_w4h + ch * 34816);
            const float4* srcL = reinterpret_cast<const float4*>(g_w4l + ch * 34816);
            float4* dstH = reinterpret_cast<float4*>(smc + S4_AH);
            float4* dstL = reinterpret_cast<float4*>(smc + S4_AL);
            #pragma unroll 1
            for (int i = tid; i < 4352; i += 256) { dstH[i] = srcH[i]; dstL[i] = srcL[i]; }
        }
        {
            const int gk = ch * 128 + kloc;
            if (gk < 1000) {
                const int c = gk / 10, kk = gk - c * 10;
                const uint32_t* src = g_y3p + (s0 + seg) * 3200 + c * 32 + kk;
                #pragma unroll
                for (int j = 0; j < 24; j += 2) {
                    uint32_t q0 = (j < 21)     ? __ldg(&src[j])     : 0u;
                    uint32_t q1 = (j + 1 < 21) ? __ldg(&src[j + 1]) : 0u;
                    *reinterpret_cast<uint32_t*>(bhRow + j) = __byte_perm(q0, q1, 0x5410);
                    *reinterpret_cast<uint32_t*>(blRow + j) = __byte_perm(q0, q1, 0x7632);
                }
            } else {
                #pragma unroll
                for (int j = 0; j < 24; j += 2) {
                    *reinterpret_cast<uint32_t*>(bhRow + j) = 0u;
                    *reinterpret_cast<uint32_t*>(blRow + j) = 0u;
                }
            }
        }
        __syncthreads();

        #pragma unroll
        for (int t = 0; t < 8; t++) {
            uint32_t ah0[4], al0[4], ah1[4], al1[4];
            ldsm4(ah0, aH0 + t * 32);
            ldsm4(al0, aL0 + t * 32);
            ldsm4(ah1, aH1 + t * 32);
            ldsm4(al1, aL1 + t * 32);
            const uint32_t bt = (uint32_t)t * (16 * S4_NP * 2);
            #pragma unroll
            for (int q = 0; q < 3; q++) {
                uint32_t bh[4], bl[4];
                ldsm4t(bh, bHb + bt + q * 32);
                ldsm4t(bl, bLb + bt + q * 32);
                mma16816(d[2 * q],     ah0, bh);
                mma16816(d[2 * q],     al0, bh);
                mma16816(d[2 * q],     ah0, bl);
                mma16816(d[2 * q + 1], ah0, bh + 2);
                mma16816(d[2 * q + 1], al0, bh + 2);
                mma16816(d[2 * q + 1], ah0, bl + 2);
                mma16816(d[6 + 2 * q],     ah1, bh);
                mma16816(d[6 + 2 * q],     al1, bh);
                mma16816(d[6 + 2 * q],     ah1, bl);
                mma16816(d[6 + 2 * q + 1], ah1, bh + 2);
                mma16816(d[6 + 2 * q + 1], al1, bh + 2);
                mma16816(d[6 + 2 * q + 1], ah1, bl + 2);
            }
        }
    }

    __syncthreads();
    float* Dsm = reinterpret_cast<float*>(smc);
    {
        const int r0 = wid * 32 + (lane >> 2);
        const int cb = (lane & 3) * 2;
        #pragma unroll
        for (int m = 0; m < 2; m++) {
            #pragma unroll
            for (int q = 0; q < 6; q++) {
                int row = r0 + m * 16;
                int n = q * 8 + cb;
                Dsm[row * 56 + n]           = d[m * 6 + q][0];
                Dsm[row * 56 + n + 1]       = d[m * 6 + q][1];
                Dsm[(row + 8) * 56 + n]     = d[m * 6 + q][2];
                Dsm[(row + 8) * 56 + n + 1] = d[m * 6 + q][3];
            }
        }
    }
    __syncthreads();
    for (int i = tid; i < 2800; i += 256) {
        int o = i / 14, r = i - o * 14, s = r / 7, t = r - s * 7;
        int n = s * 24 + t * 3;
        float v = fmaxf(Dsm[o * 56 + n], fmaxf(Dsm[o * 56 + n + 1], Dsm[o * 56 + n + 2]))
                  + __ldg(&b4[o]);
        g_feat[(s0 + s) * 1400 + o * 7 + t] = elu1(v);
    }
}

// ---------------- head ----------------
__global__ void head_k(const int* __restrict__ sid, const float* __restrict__ hW,
                       const float* __restrict__ hB, float* __restrict__ out)
{
    const int b = blockIdx.x;
    const int s = sid[b];
    const float* f = g_feat + b * 1400;
    const float* W = hW + s * (4 * 1400);
    float acc[4] = {0.f, 0.f, 0.f, 0.f};
    for (int i = threadIdx.x; i < 1400; i += blockDim.x) {
        float fv = f[i];
        #pragma unroll
        for (int o = 0; o < 4; o++) acc[o] = fmaf(fv, __ldg(&W[o * 1400 + i]), acc[o]);
    }
    #pragma unroll
    for (int off = 16; off > 0; off >>= 1) {
        #pragma unroll
        for (int o = 0; o < 4; o++) acc[o] += __shfl_down_sync(0xFFFFFFFFu, acc[o], off);
    }
    __shared__ float red[4][4];
    const int w = threadIdx.x >> 5, l = threadIdx.x & 31;
    if (l == 0) {
        #pragma unroll
        for (int o = 0; o < 4; o++) red[o][w] = acc[o];
    }
    __syncthreads();
    if (threadIdx.x < 4) {
        int o = threadIdx.x;
        out[b * 4 + o] = red[o][0] + red[o][1] + red[o][2] + red[o][3] + __ldg(&hB[s * 4 + o]);
    }
}

// ---------------- launch ----------------
extern "C" void kernel_launch(void* const* d_in, const int* in_sizes, int n_in,
                              void* d_out, int out_size)
{
    const float* x      = (const float*)d_in[0];
    const int*   sid    = (const int*)  d_in[1];
    const float* w_time = (const float*)d_in[2];
    const float* b_time = (const float*)d_in[3];
    const float* w_spat = (const float*)d_in[4];
    const float* b_spat = (const float*)d_in[5];
    const float* w2     = (const float*)d_in[6];
    const float* b2     = (const float*)d_in[7];
    const float* w3     = (const float*)d_in[8];
    const float* b3     = (const float*)d_in[9];
    const float* w4     = (const float*)d_in[10];
    const float* b4     = (const float*)d_in[11];
    const float* hW     = (const float*)d_in[12];
    const float* hB     = (const float*)d_in[13];
    float* out = (float*)d_out;

    cudaFuncSetAttribute(stage1_k, cudaFuncAttributeMaxDynamicSharedMemorySize, S1_SMEM);
    cudaFuncSetAttribute(stage2_k, cudaFuncAttributeMaxDynamicSharedMemorySize, S2_SMEM);
    cudaFuncSetAttribute(stage3_k, cudaFuncAttributeMaxDynamicSharedMemorySize, S3_SMEM);
    cudaFuncSetAttribute(stage4_k, cudaFuncAttributeMaxDynamicSharedMemorySize, S4_SMEM);

    precompute_k<<<1, 256>>>(w_time, b_time, w_spat, b_spat);
    precompute_w_k<<<(378368 + 255) / 256, 256>>>(w2, w3, w4);
    stage1_k<<<dim3(B_, 6), 384, S1_SMEM>>>(x);
    stage2_k<<<dim3(B_, 3), 256, S2_SMEM>>>(b2);
    stage3_k<<<128, 256, S3_SMEM>>>(b3);
    stage4_k<<<128, 256, S4_SMEM>>>(b4);
    head_k<<<B_, 128>>>(sid, hW, hB, out);
}

// round 12
// speedup vs baseline: 1.7591x; 1.0003x over previous
#include <cuda_runtime.h>
#include <cuda_bf16.h>
#include <math.h>
#include <stdint.h>

#define B_ 256

// ---------------- device scratch ----------------
__device__ float g_Weff[25 * 220];
__device__ float g_beff[25];
__device__ uint32_t g_y1p[B_ * 330 * 26];            // TRANSPOSED: [b][pos][ch(25)+pad], packed bf16 h|l<<16
__device__ uint32_t g_y2p[B_ * 50 * 107];
__device__ uint32_t g_y3p[B_ * 100 * 32];
__device__ float g_feat[B_ * 1400];
// weight images (bf16 split)
__device__ __align__(16) uint16_t g_w1h[10 * 32 * 40];   // stage1 tap images
__device__ __align__(16) uint16_t g_w1l[10 * 32 * 40];
__device__ __align__(16) uint16_t g_w2th[10 * 32 * 56];  // stage2 tap images [kk][c][o]
__device__ __align__(16) uint16_t g_w2tl[10 * 32 * 56];
__device__ __align__(16) uint16_t g_w3h[4 * 128 * 136];
__device__ __align__(16) uint16_t g_w3l[4 * 128 * 136];
__device__ __align__(16) uint16_t g_w4h[8 * 256 * 136];
__device__ __align__(16) uint16_t g_w4l[8 * 256 * 136];

__device__ __forceinline__ float elu1(float x) { return x > 0.f ? x : expm1f(x); }

__device__ __forceinline__ uint32_t smem_u32(const void* p) {
    uint32_t a;
    asm("{ .reg .u64 t; cvta.to.shared.u64 t, %1; cvt.u32.u64 %0, t; }" : "=r"(a) : "l"(p));
    return a;
}
__device__ __forceinline__ void ldsm4(uint32_t* r, uint32_t addr) {
    asm volatile("ldmatrix.sync.aligned.m8n8.x4.shared.b16 {%0,%1,%2,%3}, [%4];"
                 : "=r"(r[0]), "=r"(r[1]), "=r"(r[2]), "=r"(r[3]) : "r"(addr));
}
__device__ __forceinline__ void ldsm4t(uint32_t* r, uint32_t addr) {
    asm volatile("ldmatrix.sync.aligned.m8n8.x4.trans.shared.b16 {%0,%1,%2,%3}, [%4];"
                 : "=r"(r[0]), "=r"(r[1]), "=r"(r[2]), "=r"(r[3]) : "r"(addr));
}
__device__ __forceinline__ void mma16816(float* d, const uint32_t* a, const uint32_t* b) {
    asm volatile("mma.sync.aligned.m16n8k16.row.col.f32.bf16.bf16.f32 "
                 "{%0,%1,%2,%3}, {%4,%5,%6,%7}, {%8,%9}, {%0,%1,%2,%3};"
                 : "+f"(d[0]), "+f"(d[1]), "+f"(d[2]), "+f"(d[3])
                 : "r"(a[0]), "r"(a[1]), "r"(a[2]), "r"(a[3]), "r"(b[0]), "r"(b[1]));
}
__device__ __forceinline__ uint32_t pack_bf16_split(float v) {
    __nv_bfloat16 h = __float2bfloat16(v);
    float hf = __bfloat162float(h);
    __nv_bfloat16 l = __float2bfloat16(v - hf);
    uint16_t hb = reinterpret_cast<uint16_t&>(h);
    uint16_t lb = reinterpret_cast<uint16_t&>(l);
    return (uint32_t)hb | ((uint32_t)lb << 16);
}

// ---------------- kernel 0: fold conv_time into conv_spat ----------------
__global__ void precompute_k(const float* __restrict__ w_time, const float* __restrict__ b_time,
                             const float* __restrict__ w_spat, const float* __restrict__ b_spat)
{
    for (int idx = threadIdx.x; idx < 25 * 220; idx += blockDim.x) {
        int p = idx / 220, rem = idx % 220, c = rem / 10, k = rem % 10;
        float s = 0.f;
        #pragma unroll
        for (int o = 0; o < 25; o++)
            s = fmaf(w_spat[p * 550 + o * 22 + c], w_time[o * 10 + k], s);
        g_Weff[idx] = s;
    }
    if (threadIdx.x < 25) {
        int p = threadIdx.x;
        float s = b_spat[p];
        for (int o = 0; o < 25; o++) {
            float w = 0.f;
            for (int c = 0; c < 22; c++) w += w_spat[p * 550 + o * 22 + c];
            s = fmaf(b_time[o], w, s);
        }
        g_beff[p] = s;
    }
}

// ---------------- kernel 0b: ALL weight images in one launch ----------------
__global__ void precompute_w_k(const float* __restrict__ w2, const float* __restrict__ w3,
                               const float* __restrict__ w4)
{
    int idx = blockIdx.x * 256 + threadIdx.x;
    if (idx < 69632) {
        int ch = idx / 17408, r = idx % 17408, row = r / 136, kloc = r % 136;
        int gk = ch * 128 + kloc;
        float v = (kloc < 128 && row < 100 && gk < 500) ? w3[row * 500 + gk] : 0.f;
        uint32_t p = pack_bf16_split(v);
        g_w3h[idx] = (uint16_t)(p & 0xffff);
        g_w3l[idx] = (uint16_t)(p >> 16);
    } else if (idx < 348160) {
        int i4 = idx - 69632;
        int ch = i4 / 34816, r = i4 % 34816, row = r / 136, kloc = r % 136;
        int gk = ch * 128 + kloc;
        float v = (kloc < 128 && row < 200 && gk < 1000) ? w4[row * 1000 + gk] : 0.f;
        uint32_t p = pack_bf16_split(v);
        g_w4h[i4] = (uint16_t)(p & 0xffff);
        g_w4l[i4] = (uint16_t)(p >> 16);
    } else if (idx < 360960) {
        // w1 tap image: [kk][c(32)][o(40)] = Weff[o][c*10+kk]
        int i1 = idx - 348160;
        int kk = i1 / 1280, r = i1 % 1280, c = r / 40, o = r % 40;
        float v = (c < 22 && o < 25) ? g_Weff[o * 220 + c * 10 + kk] : 0.f;
        uint32_t p = pack_bf16_split(v);
        g_w1h[i1] = (uint16_t)(p & 0xffff);
        g_w1l[i1] = (uint16_t)(p >> 16);
    } else if (idx < 378880) {
        // w2 tap image: [kk][c(32)][o(56)] = w2[o][c*10+kk]
        int i2 = idx - 360960;
        int kk = i2 / 1792, r = i2 % 1792, c = r / 56, o = r % 56;
        float v = (c < 25 && o < 50) ? w2[o * 250 + c * 10 + kk] : 0.f;
        uint32_t p = pack_bf16_split(v);
        g_w2th[i2] = (uint16_t)(p & 0xffff);
        g_w2tl[i2] = (uint16_t)(p >> 16);
    }
}

// ---------------- stage 1 (TENSOR, tap-decomposed): x -> y1pT ----------------
#define S1_AH 0
#define S1_AL 16640
#define S1_WH 33280
#define S1_WL 58880
#define S1_SMEM 84480

__global__ __launch_bounds__(384, 2) void stage1_k(const float* __restrict__ x)
{
    extern __shared__ char smc[];
    const uint32_t sb = smem_u32(smc);
    const int tid = threadIdx.x, wid = tid >> 5, lane = tid & 31;
    const int b = blockIdx.x, tile = blockIdx.y;
    const int m0 = tile * 192;
    __shared__ float bs[25];
    if (tid < 25) bs[tid] = g_beff[tid];

    {
        const float4* srcH = reinterpret_cast<const float4*>(g_w1h);
        const float4* srcL = reinterpret_cast<const float4*>(g_w1l);
        float4* dstH = reinterpret_cast<float4*>(smc + S1_WH);
        float4* dstL = reinterpret_cast<float4*>(smc + S1_WL);
        #pragma unroll 1
        for (int i = tid; i < 1600; i += 384) { dstH[i] = srcH[i]; dstL[i] = srcL[i]; }
    }
    {
        const float* xb = x + b * 22000;
        #pragma unroll 1
        for (int i = tid; i < 4160; i += 384) {
            int cp = i / 208, r = i - cp * 208;
            int t = m0 + r;
            uint32_t h2 = 0u, l2 = 0u;
            if (cp < 11 && t < 1000) {
                uint32_t p0 = pack_bf16_split(__ldg(&xb[(2 * cp) * 1000 + t]));
                uint32_t p1 = pack_bf16_split(__ldg(&xb[(2 * cp + 1) * 1000 + t]));
                h2 = __byte_perm(p0, p1, 0x5410);
                l2 = __byte_perm(p0, p1, 0x7632);
            }
            reinterpret_cast<uint32_t*>(smc + S1_AH)[r * 20 + cp] = h2;
            reinterpret_cast<uint32_t*>(smc + S1_AL)[r * 20 + cp] = l2;
        }
    }
    __syncthreads();

    float d[4][4];
    #pragma unroll
    for (int i = 0; i < 4; i++)
        #pragma unroll
        for (int j = 0; j < 4; j++) d[i][j] = 0.f;

    const uint32_t aOff = ((wid * 16 + ((lane >> 3) & 1) * 8 + (lane & 7)) * 40 + (lane >> 4) * 8) * 2;
    const uint32_t aHb = sb + S1_AH + aOff, aLb = sb + S1_AL + aOff;
    const uint32_t bOff = ((((lane >> 3) & 1) * 8 + (lane & 7)) * 40 + (lane >> 4) * 8) * 2;
    const uint32_t bHb = sb + S1_WH + bOff, bLb = sb + S1_WL + bOff;

    #pragma unroll 1
    for (int kk = 0; kk < 10; kk++) {
        #pragma unroll
        for (int s = 0; s < 2; s++) {
            uint32_t ah[4], al[4];
            ldsm4(ah, aHb + kk * 80 + s * 32);
            ldsm4(al, aLb + kk * 80 + s * 32);
            const uint32_t wb = (uint32_t)kk * 2560 + (uint32_t)s * 1280;
            #pragma unroll
            for (int q = 0; q < 2; q++) {
                uint32_t bh[4], bl[4];
                ldsm4t(bh, bHb + wb + q * 32);
                ldsm4t(bl, bLb + wb + q * 32);
                mma16816(d[2 * q],     ah, bh);
                mma16816(d[2 * q],     al, bh);
                mma16816(d[2 * q],     ah, bl);
                mma16816(d[2 * q + 1], ah, bh + 2);
                mma16816(d[2 * q + 1], al, bh + 2);
                mma16816(d[2 * q + 1], ah, bl + 2);
            }
        }
    }

    __syncthreads();
    float* Dsm = reinterpret_cast<float*>(smc);
    {
        const int mloc = wid * 16 + (lane >> 2);
        const int cb = (lane & 3) * 2;
        #pragma unroll
        for (int q = 0; q < 4; q++) {
            int n = q * 8 + cb;
            Dsm[n * 200 + mloc]           = d[q][0];
            Dsm[(n + 1) * 200 + mloc]     = d[q][1];
            Dsm[n * 200 + mloc + 8]       = d[q][2];
            Dsm[(n + 1) * 200 + mloc + 8] = d[q][3];
        }
    }
    __syncthreads();
    // transposed output: y1pT[b][tp][o], o=25 zero pad
    #pragma unroll 1
    for (int i = tid; i < 1664; i += 384) {
        int j = i / 26, o = i - j * 26;
        int tp = tile * 64 + j;
        if (tp < 330) {
            uint32_t pv = 0u;
            if (o < 25) {
                const float* row = Dsm + o * 200 + 3 * j;
                float v = fmaxf(row[0], fmaxf(row[1], row[2])) + bs[o];
                pv = pack_bf16_split(elu1(v));
            }
            g_y1p[b * 8580 + tp * 26 + o] = pv;
        }
    }
}

// ---------------- stage 2 (TENSOR, tap-decomposed): y1pT -> y2p ----------------
// per CTA (sample b): D[336 m][56 n] = Σ_kk y1T[m+kk][32 c-pad] x W2_kk[32][56]
// A: [384 rows][40 u16] stride 80 B; W resident [10][32][56] stride 112 B.
#define S2_AH 0
#define S2_AL 30720
#define S2_WH 61440
#define S2_WL 97280
#define S2_SMEM 133376

__global__ __launch_bounds__(256, 1) void stage2_k(const float* __restrict__ b2)
{
    extern __shared__ char smc[];
    const uint32_t sb = smem_u32(smc);
    const int tid = threadIdx.x, wid = tid >> 5, lane = tid & 31;
    const int b = blockIdx.x;
    __shared__ float bs[50];
    if (tid < 50) bs[tid] = __ldg(&b2[tid]);

    // W fill: 2240 float4 per split
    {
        const float4* srcH = reinterpret_cast<const float4*>(g_w2th);
        const float4* srcL = reinterpret_cast<const float4*>(g_w2tl);
        float4* dstH = reinterpret_cast<float4*>(smc + S2_WH);
        float4* dstL = reinterpret_cast<float4*>(smc + S2_WL);
        #pragma unroll 1
        for (int i = tid; i < 2240; i += 256) { dstH[i] = srcH[i]; dstL[i] = srcL[i]; }
    }
    // A fill: 384 rows x 16 channel-pairs
    {
        const uint32_t* yb = g_y1p + b * 8580;
        #pragma unroll 1
        for (int i = tid; i < 6144; i += 256) {
            int r = i >> 4, cp = i & 15;
            uint32_t h2 = 0u, l2 = 0u;
            if (r < 330 && cp < 13) {
                uint32_t p0 = __ldg(&yb[r * 26 + 2 * cp]);
                uint32_t p1 = __ldg(&yb[r * 26 + 2 * cp + 1]);
                h2 = __byte_perm(p0, p1, 0x5410);
                l2 = __byte_perm(p0, p1, 0x7632);
            }
            *reinterpret_cast<uint32_t*>(smc + S2_AH + r * 80 + cp * 4) = h2;
            *reinterpret_cast<uint32_t*>(smc + S2_AL + r * 80 + cp * 4) = l2;
        }
    }
    __syncthreads();

    float d[3][7][4];
    #pragma unroll
    for (int m = 0; m < 3; m++)
        #pragma unroll
        for (int q = 0; q < 7; q++)
            #pragma unroll
            for (int j = 0; j < 4; j++) d[m][q][j] = 0.f;

    const uint32_t aLane = ((((lane >> 3) & 1) * 8 + (lane & 7)) * 40 + (lane >> 4) * 8) * 2;
    const uint32_t bLane = ((((lane >> 3) & 1) * 8 + (lane & 7)) * 56 + (lane >> 4) * 8) * 2;

    #pragma unroll 1
    for (int kk = 0; kk < 10; kk++) {
        #pragma unroll
        for (int g = 0; g < 2; g++) {
            uint32_t bh[4][4], bl[4][4];
            const uint32_t wb = sb + (uint32_t)kk * 3584 + (uint32_t)g * (16 * 112) + bLane;
            #pragma unroll
            for (int q = 0; q < 4; q++) {
                ldsm4t(bh[q], S2_WH + wb + q * 32);
                ldsm4t(bl[q], S2_WL + wb + q * 32);
            }
            #pragma unroll
            for (int mt = 0; mt < 3; mt++) {
                const int tile = wid + mt * 8;
                if (tile > 20) break;
                const uint32_t arow = (uint32_t)(tile * 16 + kk) * 80 + (uint32_t)g * 32;
                uint32_t ah[4], al[4];
                ldsm4(ah, sb + S2_AH + arow + aLane);
                ldsm4(al, sb + S2_AL + arow + aLane);
                #pragma unroll
                for (int q = 0; q < 3; q++) {
                    mma16816(d[mt][2 * q],     ah, bh[q]);
                    mma16816(d[mt][2 * q],     al, bh[q]);
                    mma16816(d[mt][2 * q],     ah, bl[q]);
                    mma16816(d[mt][2 * q + 1], ah, bh[q] + 2);
                    mma16816(d[mt][2 * q + 1], al, bh[q] + 2);
                    mma16816(d[mt][2 * q + 1], ah, bl[q] + 2);
                }
                mma16816(d[mt][6], ah, bh[3]);
                mma16816(d[mt][6], al, bh[3]);
                mma16816(d[mt][6], ah, bl[3]);
            }
        }
    }

    // epilogue: Dsm [336 m][56 o] f32 (75,264 B, reuses A/W space)
    __syncthreads();
    float* Dsm = reinterpret_cast<float*>(smc);
    {
        const int r0 = (lane >> 2);
        const int cb = (lane & 3) * 2;
        #pragma unroll
        for (int mt = 0; mt < 3; mt++) {
            const int tile = wid + mt * 8;
            if (tile > 20) break;
            const int rr = tile * 16 + r0;
            #pragma unroll
            for (int q = 0; q < 7; q++) {
                int n = q * 8 + cb;
                Dsm[rr * 56 + n]           = d[mt][q][0];
                Dsm[rr * 56 + n + 1]       = d[mt][q][1];
                Dsm[(rr + 8) * 56 + n]     = d[mt][q][2];
                Dsm[(rr + 8) * 56 + n + 1] = d[mt][q][3];
            }
        }
    }
    __syncthreads();
    #pragma unroll 1
    for (int i = tid; i < 5350; i += 256) {
        int o = i / 107, p = i - o * 107;
        const float* c0 = Dsm + (3 * p) * 56 + o;
        float v = fmaxf(c0[0], fmaxf(c0[56], c0[112])) + bs[o];
        g_y2p[b * 5350 + o * 107 + p] = pack_bf16_split(elu1(v));
    }
}

// ---------------- stage 3 (TENSOR): y2p -> y3p ----------------
#define S3_KP 136
#define S3_NP 200
#define S3_AH 0
#define S3_AL 34816
#define S3_BH 69632
#define S3_BL 120832
#define S3_SMEM 172032

__global__ __launch_bounds__(256, 1) void stage3_k(const float* __restrict__ b3)
{
    extern __shared__ char smc[];
    const uint32_t sb = smem_u32(smc);
    const int tid = threadIdx.x, wid = tid >> 5, lane = tid & 31;
    const int s0 = blockIdx.x * 2;

    float d[24][4];
    #pragma unroll
    for (int i = 0; i < 24; i++)
        #pragma unroll
        for (int j = 0; j < 4; j++) d[i][j] = 0.f;

    const uint32_t aOff = ((wid * 16 + ((lane >> 3) & 1) * 8 + (lane & 7)) * S3_KP + (lane >> 4) * 8) * 2;
    const uint32_t bOff = ((((lane >> 3) & 1) * 8 + (lane & 7)) * S3_NP + (lane >> 4) * 8) * 2;
    const uint32_t aH = sb + S3_AH + aOff, aL = sb + S3_AL + aOff;
    const uint32_t bHb = sb + S3_BH + bOff, bLb = sb + S3_BL + bOff;

    const int kloc = tid >> 1, seg = tid & 1;
    uint16_t* bhRow = reinterpret_cast<uint16_t*>(smc + S3_BH) + kloc * S3_NP + seg * 96;
    uint16_t* blRow = reinterpret_cast<uint16_t*>(smc + S3_BL) + kloc * S3_NP + seg * 96;

    for (int ch = 0; ch < 4; ch++) {
        __syncthreads();
        {
            const float4* srcH = reinterpret_cast<const float4*>(g_w3h + ch * 17408);
            const float4* srcL = reinterpret_cast<const float4*>(g_w3l + ch * 17408);
            float4* dstH = reinterpret_cast<float4*>(smc + S3_AH);
            float4* dstL = reinterpret_cast<float4*>(smc + S3_AL);
            #pragma unroll 1
            for (int i = tid; i < 2176; i += 256) { dstH[i] = srcH[i]; dstL[i] = srcL[i]; }
        }
        {
            const int gk = ch * 128 + kloc;
            if (gk < 500) {
                const int c = gk / 10, kk = gk - c * 10;
                const uint32_t* src = g_y2p + (s0 + seg) * 5350 + c * 107 + kk;
                #pragma unroll 8
                for (int j = 0; j < 96; j += 2) {
                    uint32_t q0 = __ldg(&src[j]);
                    uint32_t q1 = __ldg(&src[j + 1]);
                    *reinterpret_cast<uint32_t*>(bhRow + j) = __byte_perm(q0, q1, 0x5410);
                    *reinterpret_cast<uint32_t*>(blRow + j) = __byte_perm(q0, q1, 0x7632);
                }
            } else {
                #pragma unroll 8
                for (int j = 0; j < 96; j += 2) {
                    *reinterpret_cast<uint32_t*>(bhRow + j) = 0u;
                    *reinterpret_cast<uint32_t*>(blRow + j) = 0u;
                }
            }
        }
        __syncthreads();

        #pragma unroll
        for (int t = 0; t < 8; t++) {
            uint32_t ah[4], al[4];
            ldsm4(ah, aH + t * 32);
            ldsm4(al, aL + t * 32);
            const uint32_t bt = (uint32_t)t * (16 * S3_NP * 2);
            #pragma unroll
            for (int q = 0; q < 12; q++) {
                uint32_t bh[4], bl[4];
                ldsm4t(bh, bHb + bt + q * 32);
                ldsm4t(bl, bLb + bt + q * 32);
                mma16816(d[2 * q],     ah, bh);
                mma16816(d[2 * q],     al, bh);
                mma16816(d[2 * q],     ah, bl);
                mma16816(d[2 * q + 1], ah, bh + 2);
                mma16816(d[2 * q + 1], al, bh + 2);
                mma16816(d[2 * q + 1], ah, bl + 2);
            }
        }
    }

    __syncthreads();
    float* Dsm = reinterpret_cast<float*>(smc);
    {
        const int r0 = wid * 16 + (lane >> 2);
        const int cb = (lane & 3) * 2;
        #pragma unroll
        for (int nt = 0; nt < 24; nt++) {
            int n = nt * 8 + cb;
            Dsm[r0 * 200 + n]           = d[nt][0];
            Dsm[r0 * 200 + n + 1]       = d[nt][1];
            Dsm[(r0 + 8) * 200 + n]     = d[nt][2];
            Dsm[(r0 + 8) * 200 + n + 1] = d[nt][3];
        }
    }
    __syncthreads();
    for (int i = tid; i < 6400; i += 256) {
        int o = i >> 6, r = i & 63, s = r >> 5, t = r & 31;
        int n = s * 96 + t * 3;
        float v = fmaxf(Dsm[o * 200 + n], fmaxf(Dsm[o * 200 + n + 1], Dsm[o * 200 + n + 2]))
                  + __ldg(&b3[o]);
        g_y3p[(s0 + s) * 3200 + o * 32 + t] = pack_bf16_split(elu1(v));
    }
}

// ---------------- stage 4 (TENSOR): y3p -> feat ----------------
#define S4_KP 136
#define S4_NP 56
#define S4_AH 0
#define S4_AL 69632
#define S4_BH 139264
#define S4_BL 153600
#define S4_SMEM 167936

__global__ __launch_bounds__(256, 1) void stage4_k(const float* __restrict__ b4)
{
    extern __shared__ char smc[];
    const uint32_t sb = smem_u32(smc);
    const int tid = threadIdx.x, wid = tid >> 5, lane = tid & 31;
    const int s0 = blockIdx.x * 2;

    float d[12][4];
    #pragma unroll
    for (int i = 0; i < 12; i++)
        #pragma unroll
        for (int j = 0; j < 4; j++) d[i][j] = 0.f;

    const uint32_t aOff0 = ((wid * 32 + ((lane >> 3) & 1) * 8 + (lane & 7)) * S4_KP + (lane >> 4) * 8) * 2;
    const uint32_t aOff1 = aOff0 + 16 * S4_KP * 2;
    const uint32_t bOff = ((((lane >> 3) & 1) * 8 + (lane & 7)) * S4_NP + (lane >> 4) * 8) * 2;
    const uint32_t aH0 = sb + S4_AH + aOff0, aL0 = sb + S4_AL + aOff0;
    const uint32_t aH1 = sb + S4_AH + aOff1, aL1 = sb + S4_AL + aOff1;
    const uint32_t bHb = sb + S4_BH + bOff, bLb = sb + S4_BL + bOff;

    const int kloc = tid >> 1, seg = tid & 1;
    uint16_t* bhRow = reinterpret_cast<uint16_t*>(smc + S4_BH) + kloc * S4_NP + seg * 24;
    uint16_t* blRow = reinterpret_cast<uint16_t*>(smc + S4_BL) + kloc * S4_NP + seg * 24;

    for (int ch = 0; ch < 8; ch++) {
        __syncthreads();
        {
            const float4* srcH = reinterpret_cast<const float4*>(g_w4h + ch * 34816);
            const float4* srcL = reinterpret_cast<const float4*>(g_w4l + ch * 34816);
            float4* dstH = reinterpret_cast<float4*>(smc + S4_AH);
            float4* dstL = reinterpret_cast<float4*>(smc + S4_AL);
            #pragma unroll 1
            for (int i = tid; i < 4352; i += 256) { dstH[i] = srcH[i]; dstL[i] = srcL[i]; }
        }
        {
            const int gk = ch * 128 + kloc;
            if (gk < 1000) {
                const int c = gk / 10, kk = gk - c * 10;
                const uint32_t* src = g_y3p + (s0 + seg) * 3200 + c * 32 + kk;
                #pragma unroll
                for (int j = 0; j < 24; j += 2) {
                    uint32_t q0 = (j < 21)     ? __ldg(&src[j])     : 0u;
                    uint32_t q1 = (j + 1 < 21) ? __ldg(&src[j + 1]) : 0u;
                    *reinterpret_cast<uint32_t*>(bhRow + j) = __byte_perm(q0, q1, 0x5410);
                    *reinterpret_cast<uint32_t*>(blRow + j) = __byte_perm(q0, q1, 0x7632);
                }
            } else {
                #pragma unroll
                for (int j = 0; j < 24; j += 2) {
                    *reinterpret_cast<uint32_t*>(bhRow + j) = 0u;
                    *reinterpret_cast<uint32_t*>(blRow + j) = 0u;
                }
            }
        }
        __syncthreads();

        #pragma unroll
        for (int t = 0; t < 8; t++) {
            uint32_t ah0[4], al0[4], ah1[4], al1[4];
            ldsm4(ah0, aH0 + t * 32);
            ldsm4(al0, aL0 + t * 32);
            ldsm4(ah1, aH1 + t * 32);
            ldsm4(al1, aL1 + t * 32);
            const uint32_t bt = (uint32_t)t * (16 * S4_NP * 2);
            #pragma unroll
            for (int q = 0; q < 3; q++) {
                uint32_t bh[4], bl[4];
                ldsm4t(bh, bHb + bt + q * 32);
                ldsm4t(bl, bLb + bt + q * 32);
                mma16816(d[2 * q],     ah0, bh);
                mma16816(d[2 * q],     al0, bh);
                mma16816(d[2 * q],     ah0, bl);
                mma16816(d[2 * q + 1], ah0, bh + 2);
                mma16816(d[2 * q + 1], al0, bh + 2);
                mma16816(d[2 * q + 1], ah0, bl + 2);
                mma16816(d[6 + 2 * q],     ah1, bh);
                mma16816(d[6 + 2 * q],     al1, bh);
                mma16816(d[6 + 2 * q],     ah1, bl);
                mma16816(d[6 + 2 * q + 1], ah1, bh + 2);
                mma16816(d[6 + 2 * q + 1], al1, bh + 2);
                mma16816(d[6 + 2 * q + 1], ah1, bl + 2);
            }
        }
    }

    __syncthreads();
    float* Dsm = reinterpret_cast<float*>(smc);
    {
        const int r0 = wid * 32 + (lane >> 2);
        const int cb = (lane & 3) * 2;
        #pragma unroll
        for (int m = 0; m < 2; m++) {
            #pragma unroll
            for (int q = 0; q < 6; q++) {
                int row = r0 + m * 16;
                int n = q * 8 + cb;
                Dsm[row * 56 + n]           = d[m * 6 + q][0];
                Dsm[row * 56 + n + 1]       = d[m * 6 + q][1];
                Dsm[(row + 8) * 56 + n]     = d[m * 6 + q][2];
                Dsm[(row + 8) * 56 + n + 1] = d[m * 6 + q][3];
            }
        }
    }
    __syncthreads();
    for (int i = tid; i < 2800; i += 256) {
        int o = i / 14, r = i - o * 14, s = r / 7, t = r - s * 7;
        int n = s * 24 + t * 3;
        float v = fmaxf(Dsm[o * 56 + n], fmaxf(Dsm[o * 56 + n + 1], Dsm[o * 56 + n + 2]))
                  + __ldg(&b4[o]);
        g_feat[(s0 + s) * 1400 + o * 7 + t] = elu1(v);
    }
}

// ---------------- head ----------------
__global__ void head_k(const int* __restrict__ sid, const float* __restrict__ hW,
                       const float* __restrict__ hB, float* __restrict__ out)
{
    const int b = blockIdx.x;
    const int s = sid[b];
    const float* f = g_feat + b * 1400;
    const float* W = hW + s * (4 * 1400);
    float acc[4] = {0.f, 0.f, 0.f, 0.f};
    for (int i = threadIdx.x; i < 1400; i += blockDim.x) {
        float fv = f[i];
        #pragma unroll
        for (int o = 0; o < 4; o++) acc[o] = fmaf(fv, __ldg(&W[o * 1400 + i]), acc[o]);
    }
    #pragma unroll
    for (int off = 16; off > 0; off >>= 1) {
        #pragma unroll
        for (int o = 0; o < 4; o++) acc[o] += __shfl_down_sync(0xFFFFFFFFu, acc[o], off);
    }
    __shared__ float red[4][4];
    const int w = threadIdx.x >> 5, l = threadIdx.x & 31;
    if (l == 0) {
        #pragma unroll
        for (int o = 0; o < 4; o++) red[o][w] = acc[o];
    }
    __syncthreads();
    if (threadIdx.x < 4) {
        int o = threadIdx.x;
        out[b * 4 + o] = red[o][0] + red[o][1] + red[o][2] + red[o][3] + __ldg(&hB[s * 4 + o]);
    }
}

// ---------------- launch ----------------
extern "C" void kernel_launch(void* const* d_in, const int* in_sizes, int n_in,
                              void* d_out, int out_size)
{
    const float* x      = (const float*)d_in[0];
    const int*   sid    = (const int*)  d_in[1];
    const float* w_time = (const float*)d_in[2];
    const float* b_time = (const float*)d_in[3];
    const float* w_spat = (const float*)d_in[4];
    const float* b_spat = (const float*)d_in[5];
    const float* w2     = (const float*)d_in[6];
    const float* b2     = (const float*)d_in[7];
    const float* w3     = (const float*)d_in[8];
    const float* b3     = (const float*)d_in[9];
    const float* w4     = (const float*)d_in[10];
    const float* b4     = (const float*)d_in[11];
    const float* hW     = (const float*)d_in[12];
    const float* hB     = (const float*)d_in[13];
    float* out = (float*)d_out;

    cudaFuncSetAttribute(stage1_k, cudaFuncAttributeMaxDynamicSharedMemorySize, S1_SMEM);
    cudaFuncSetAttribute(stage2_k, cudaFuncAttributeMaxDynamicSharedMemorySize, S2_SMEM);
    cudaFuncSetAttribute(stage3_k, cudaFuncAttributeMaxDynamicSharedMemorySize, S3_SMEM);
    cudaFuncSetAttribute(stage4_k, cudaFuncAttributeMaxDynamicSharedMemorySize, S4_SMEM);

    precompute_k<<<1, 256>>>(w_time, b_time, w_spat, b_spat);
    precompute_w_k<<<(378880 + 255) / 256, 256>>>(w2, w3, w4);
    stage1_k<<<dim3(B_, 6), 384, S1_SMEM>>>(x);
    stage2_k<<<B_, 256, S2_SMEM>>>(b2);
    stage3_k<<<128, 256, S3_SMEM>>>(b3);
    stage4_k<<<128, 256, S4_SMEM>>>(b4);
    head_k<<<B_, 128>>>(sid, hW, hB, out);
}

// round 13
// speedup vs baseline: 1.8212x; 1.0353x over previous
#include <cuda_runtime.h>
#include <cuda_bf16.h>
#include <math.h>
#include <stdint.h>

#define B_ 256

// ---------------- device scratch ----------------
__device__ float g_Weff[25 * 220];
__device__ float g_beff[25];
__device__ uint32_t g_y1p[B_ * 330 * 26];            // TRANSPOSED: [b][pos][ch(25)+pad]
__device__ uint32_t g_y2p[B_ * 50 * 107];
__device__ uint32_t g_y3p[B_ * 100 * 32];
__device__ float g_feat[B_ * 1400];
// weight images (bf16 split)
__device__ __align__(16) uint16_t g_w1h[10 * 32 * 40];
__device__ __align__(16) uint16_t g_w1l[10 * 32 * 40];
__device__ __align__(16) uint16_t g_w2th[10 * 32 * 56];
__device__ __align__(16) uint16_t g_w2tl[10 * 32 * 56];
__device__ __align__(16) uint16_t g_w3h[4 * 128 * 136];
__device__ __align__(16) uint16_t g_w3l[4 * 128 * 136];
__device__ __align__(16) uint16_t g_w4h[8 * 256 * 136];
__device__ __align__(16) uint16_t g_w4l[8 * 256 * 136];

__device__ __forceinline__ float elu1(float x) { return x > 0.f ? x : expm1f(x); }

__device__ __forceinline__ uint32_t smem_u32(const void* p) {
    uint32_t a;
    asm("{ .reg .u64 t; cvta.to.shared.u64 t, %1; cvt.u32.u64 %0, t; }" : "=r"(a) : "l"(p));
    return a;
}
__device__ __forceinline__ void ldsm4(uint32_t* r, uint32_t addr) {
    asm volatile("ldmatrix.sync.aligned.m8n8.x4.shared.b16 {%0,%1,%2,%3}, [%4];"
                 : "=r"(r[0]), "=r"(r[1]), "=r"(r[2]), "=r"(r[3]) : "r"(addr));
}
__device__ __forceinline__ void ldsm4t(uint32_t* r, uint32_t addr) {
    asm volatile("ldmatrix.sync.aligned.m8n8.x4.trans.shared.b16 {%0,%1,%2,%3}, [%4];"
                 : "=r"(r[0]), "=r"(r[1]), "=r"(r[2]), "=r"(r[3]) : "r"(addr));
}
__device__ __forceinline__ void mma16816(float* d, const uint32_t* a, const uint32_t* b) {
    asm volatile("mma.sync.aligned.m16n8k16.row.col.f32.bf16.bf16.f32 "
                 "{%0,%1,%2,%3}, {%4,%5,%6,%7}, {%8,%9}, {%0,%1,%2,%3};"
                 : "+f"(d[0]), "+f"(d[1]), "+f"(d[2]), "+f"(d[3])
                 : "r"(a[0]), "r"(a[1]), "r"(a[2]), "r"(a[3]), "r"(b[0]), "r"(b[1]));
}
__device__ __forceinline__ uint32_t pack_bf16_split(float v) {
    __nv_bfloat16 h = __float2bfloat16(v);
    float hf = __bfloat162float(h);
    __nv_bfloat16 l = __float2bfloat16(v - hf);
    uint16_t hb = reinterpret_cast<uint16_t&>(h);
    uint16_t lb = reinterpret_cast<uint16_t&>(l);
    return (uint32_t)hb | ((uint32_t)lb << 16);
}

// ---------------- kernel 0: fold conv_time into conv_spat ----------------
__global__ void precompute_k(const float* __restrict__ w_time, const float* __restrict__ b_time,
                             const float* __restrict__ w_spat, const float* __restrict__ b_spat)
{
    for (int idx = threadIdx.x; idx < 25 * 220; idx += blockDim.x) {
        int p = idx / 220, rem = idx % 220, c = rem / 10, k = rem % 10;
        float s = 0.f;
        #pragma unroll
        for (int o = 0; o < 25; o++)
            s = fmaf(w_spat[p * 550 + o * 22 + c], w_time[o * 10 + k], s);
        g_Weff[idx] = s;
    }
    if (threadIdx.x < 25) {
        int p = threadIdx.x;
        float s = b_spat[p];
        for (int o = 0; o < 25; o++) {
            float w = 0.f;
            for (int c = 0; c < 22; c++) w += w_spat[p * 550 + o * 22 + c];
            s = fmaf(b_time[o], w, s);
        }
        g_beff[p] = s;
    }
}

// ---------------- kernel 0b: ALL weight images in one launch ----------------
__global__ void precompute_w_k(const float* __restrict__ w2, const float* __restrict__ w3,
                               const float* __restrict__ w4)
{
    int idx = blockIdx.x * 256 + threadIdx.x;
    if (idx < 69632) {
        int ch = idx / 17408, r = idx % 17408, row = r / 136, kloc = r % 136;
        int gk = ch * 128 + kloc;
        float v = (kloc < 128 && row < 100 && gk < 500) ? w3[row * 500 + gk] : 0.f;
        uint32_t p = pack_bf16_split(v);
        g_w3h[idx] = (uint16_t)(p & 0xffff);
        g_w3l[idx] = (uint16_t)(p >> 16);
    } else if (idx < 348160) {
        int i4 = idx - 69632;
        int ch = i4 / 34816, r = i4 % 34816, row = r / 136, kloc = r % 136;
        int gk = ch * 128 + kloc;
        float v = (kloc < 128 && row < 200 && gk < 1000) ? w4[row * 1000 + gk] : 0.f;
        uint32_t p = pack_bf16_split(v);
        g_w4h[i4] = (uint16_t)(p & 0xffff);
        g_w4l[i4] = (uint16_t)(p >> 16);
    } else if (idx < 360960) {
        int i1 = idx - 348160;
        int kk = i1 / 1280, r = i1 % 1280, c = r / 40, o = r % 40;
        float v = (c < 22 && o < 25) ? g_Weff[o * 220 + c * 10 + kk] : 0.f;
        uint32_t p = pack_bf16_split(v);
        g_w1h[i1] = (uint16_t)(p & 0xffff);
        g_w1l[i1] = (uint16_t)(p >> 16);
    } else if (idx < 378880) {
        int i2 = idx - 360960;
        int kk = i2 / 1792, r = i2 % 1792, c = r / 56, o = r % 56;
        float v = (c < 25 && o < 50) ? w2[o * 250 + c * 10 + kk] : 0.f;
        uint32_t p = pack_bf16_split(v);
        g_w2th[i2] = (uint16_t)(p & 0xffff);
        g_w2tl[i2] = (uint16_t)(p >> 16);
    }
}

// ---------------- stage 1 (TENSOR, tap-decomposed): x -> y1pT ----------------
#define S1_AH 0
#define S1_AL 16640
#define S1_WH 33280
#define S1_WL 58880
#define S1_SMEM 84480

__global__ __launch_bounds__(384, 2) void stage1_k(const float* __restrict__ x)
{
    extern __shared__ char smc[];
    const uint32_t sb = smem_u32(smc);
    const int tid = threadIdx.x, wid = tid >> 5, lane = tid & 31;
    const int b = blockIdx.x, tile = blockIdx.y;
    const int m0 = tile * 192;
    __shared__ float bs[25];
    if (tid < 25) bs[tid] = g_beff[tid];

    {
        const float4* srcH = reinterpret_cast<const float4*>(g_w1h);
        const float4* srcL = reinterpret_cast<const float4*>(g_w1l);
        float4* dstH = reinterpret_cast<float4*>(smc + S1_WH);
        float4* dstL = reinterpret_cast<float4*>(smc + S1_WL);
        #pragma unroll 1
        for (int i = tid; i < 1600; i += 384) { dstH[i] = srcH[i]; dstL[i] = srcL[i]; }
    }
    {
        const float* xb = x + b * 22000;
        #pragma unroll 1
        for (int i = tid; i < 4160; i += 384) {
            int cp = i / 208, r = i - cp * 208;
            int t = m0 + r;
            uint32_t h2 = 0u, l2 = 0u;
            if (cp < 11 && t < 1000) {
                uint32_t p0 = pack_bf16_split(__ldg(&xb[(2 * cp) * 1000 + t]));
                uint32_t p1 = pack_bf16_split(__ldg(&xb[(2 * cp + 1) * 1000 + t]));
                h2 = __byte_perm(p0, p1, 0x5410);
                l2 = __byte_perm(p0, p1, 0x7632);
            }
            reinterpret_cast<uint32_t*>(smc + S1_AH)[r * 20 + cp] = h2;
            reinterpret_cast<uint32_t*>(smc + S1_AL)[r * 20 + cp] = l2;
        }
    }
    __syncthreads();

    float d[4][4];
    #pragma unroll
    for (int i = 0; i < 4; i++)
        #pragma unroll
        for (int j = 0; j < 4; j++) d[i][j] = 0.f;

    const uint32_t aOff = ((wid * 16 + ((lane >> 3) & 1) * 8 + (lane & 7)) * 40 + (lane >> 4) * 8) * 2;
    const uint32_t aHb = sb + S1_AH + aOff, aLb = sb + S1_AL + aOff;
    const uint32_t bOff = ((((lane >> 3) & 1) * 8 + (lane & 7)) * 40 + (lane >> 4) * 8) * 2;
    const uint32_t bHb = sb + S1_WH + bOff, bLb = sb + S1_WL + bOff;

    #pragma unroll 1
    for (int kk = 0; kk < 10; kk++) {
        #pragma unroll
        for (int s = 0; s < 2; s++) {
            uint32_t ah[4], al[4];
            ldsm4(ah, aHb + kk * 80 + s * 32);
            ldsm4(al, aLb + kk * 80 + s * 32);
            const uint32_t wb = (uint32_t)kk * 2560 + (uint32_t)s * 1280;
            #pragma unroll
            for (int q = 0; q < 2; q++) {
                uint32_t bh[4], bl[4];
                ldsm4t(bh, bHb + wb + q * 32);
                ldsm4t(bl, bLb + wb + q * 32);
                mma16816(d[2 * q],     ah, bh);
                mma16816(d[2 * q],     al, bh);
                mma16816(d[2 * q],     ah, bl);
                mma16816(d[2 * q + 1], ah, bh + 2);
                mma16816(d[2 * q + 1], al, bh + 2);
                mma16816(d[2 * q + 1], ah, bl + 2);
            }
        }
    }

    __syncthreads();
    float* Dsm = reinterpret_cast<float*>(smc);
    {
        const int mloc = wid * 16 + (lane >> 2);
        const int cb = (lane & 3) * 2;
        #pragma unroll
        for (int q = 0; q < 4; q++) {
            int n = q * 8 + cb;
            Dsm[n * 200 + mloc]           = d[q][0];
            Dsm[(n + 1) * 200 + mloc]     = d[q][1];
            Dsm[n * 200 + mloc + 8]       = d[q][2];
            Dsm[(n + 1) * 200 + mloc + 8] = d[q][3];
        }
    }
    __syncthreads();
    #pragma unroll 1
    for (int i = tid; i < 1664; i += 384) {
        int j = i / 26, o = i - j * 26;
        int tp = tile * 64 + j;
        if (tp < 330) {
            uint32_t pv = 0u;
            if (o < 25) {
                const float* row = Dsm + o * 200 + 3 * j;
                float v = fmaxf(row[0], fmaxf(row[1], row[2])) + bs[o];
                pv = pack_bf16_split(elu1(v));
            }
            g_y1p[b * 8580 + tp * 26 + o] = pv;
        }
    }
}

// ---------------- stage 2 (TENSOR, tap-decomposed, m-split): y1pT -> y2p ----------------
// grid (256, 2 halves). Each half: 11 m-tiles (halves share tile 10), A 192 rows from h*160.
// D[176 m][56 n] = Σ_kk y1T[m+kk][32 c-pad] x W2_kk[32][56]; 2 CTAs/SM (102,400 B).
#define S2_AH 0
#define S2_AL 15360
#define S2_WH 30720
#define S2_WL 66560
#define S2_SMEM 102400

__global__ __launch_bounds__(256, 2) void stage2_k(const float* __restrict__ b2)
{
    extern __shared__ char smc[];
    const uint32_t sb = smem_u32(smc);
    const int tid = threadIdx.x, wid = tid >> 5, lane = tid & 31;
    const int b = blockIdx.x, h = blockIdx.y;
    const int base = h * 160;
    __shared__ float bs[50];
    if (tid < 50) bs[tid] = __ldg(&b2[tid]);

    // W fill: 2240 float4 per split
    {
        const float4* srcH = reinterpret_cast<const float4*>(g_w2th);
        const float4* srcL = reinterpret_cast<const float4*>(g_w2tl);
        float4* dstH = reinterpret_cast<float4*>(smc + S2_WH);
        float4* dstL = reinterpret_cast<float4*>(smc + S2_WL);
        #pragma unroll 1
        for (int i = tid; i < 2240; i += 256) { dstH[i] = srcH[i]; dstL[i] = srcL[i]; }
    }
    // A fill: 192 rows x 16 channel-pairs, global pos = base + r
    {
        const uint32_t* yb = g_y1p + b * 8580;
        #pragma unroll 1
        for (int i = tid; i < 3072; i += 256) {
            int r = i >> 4, cp = i & 15;
            int gp = base + r;
            uint32_t h2 = 0u, l2 = 0u;
            if (gp < 330 && cp < 13) {
                uint32_t p0 = __ldg(&yb[gp * 26 + 2 * cp]);
                uint32_t p1 = __ldg(&yb[gp * 26 + 2 * cp + 1]);
                h2 = __byte_perm(p0, p1, 0x5410);
                l2 = __byte_perm(p0, p1, 0x7632);
            }
            *reinterpret_cast<uint32_t*>(smc + S2_AH + r * 80 + cp * 4) = h2;
            *reinterpret_cast<uint32_t*>(smc + S2_AL + r * 80 + cp * 4) = l2;
        }
    }
    __syncthreads();

    float d[2][7][4];
    #pragma unroll
    for (int m = 0; m < 2; m++)
        #pragma unroll
        for (int q = 0; q < 7; q++)
            #pragma unroll
            for (int j = 0; j < 4; j++) d[m][q][j] = 0.f;

    const uint32_t aLane = ((((lane >> 3) & 1) * 8 + (lane & 7)) * 40 + (lane >> 4) * 8) * 2;
    const uint32_t bLane = ((((lane >> 3) & 1) * 8 + (lane & 7)) * 56 + (lane >> 4) * 8) * 2;
    const bool has2 = (wid < 3);   // 11 local tiles: warp w -> t=w, and t=w+8 if w<3

    #pragma unroll 1
    for (int kk = 0; kk < 10; kk++) {
        #pragma unroll
        for (int g = 0; g < 2; g++) {
            uint32_t bh[4][4], bl[4][4];
            const uint32_t wb = sb + (uint32_t)kk * 3584 + (uint32_t)g * (16 * 112) + bLane;
            #pragma unroll
            for (int q = 0; q < 4; q++) {
                ldsm4t(bh[q], S2_WH + wb + q * 32);
                ldsm4t(bl[q], S2_WL + wb + q * 32);
            }
            #pragma unroll
            for (int mt = 0; mt < 2; mt++) {
                if (mt == 1 && !has2) break;
                const int t = wid + mt * 8;
                const uint32_t arow = (uint32_t)(t * 16 + kk) * 80 + (uint32_t)g * 32;
                uint32_t ah[4], al[4];
                ldsm4(ah, sb + S2_AH + arow + aLane);
                ldsm4(al, sb + S2_AL + arow + aLane);
                #pragma unroll
                for (int q = 0; q < 3; q++) {
                    mma16816(d[mt][2 * q],     ah, bh[q]);
                    mma16816(d[mt][2 * q],     al, bh[q]);
                    mma16816(d[mt][2 * q],     ah, bl[q]);
                    mma16816(d[mt][2 * q + 1], ah, bh[q] + 2);
                    mma16816(d[mt][2 * q + 1], al, bh[q] + 2);
                    mma16816(d[mt][2 * q + 1], ah, bl[q] + 2);
                }
                mma16816(d[mt][6], ah, bh[3]);
                mma16816(d[mt][6], al, bh[3]);
                mma16816(d[mt][6], ah, bl[3]);
            }
        }
    }

    // epilogue: Dsm [176 local m][56 o] f32 (39,424 B, fits in A regions)
    __syncthreads();
    float* Dsm = reinterpret_cast<float*>(smc);
    {
        const int r0 = (lane >> 2);
        const int cb = (lane & 3) * 2;
        #pragma unroll
        for (int mt = 0; mt < 2; mt++) {
            if (mt == 1 && !has2) break;
            const int rr = (wid + mt * 8) * 16 + r0;
            #pragma unroll
            for (int q = 0; q < 7; q++) {
                int n = q * 8 + cb;
                Dsm[rr * 56 + n]           = d[mt][q][0];
                Dsm[rr * 56 + n + 1]       = d[mt][q][1];
                Dsm[(rr + 8) * 56 + n]     = d[mt][q][2];
                Dsm[(rr + 8) * 56 + n + 1] = d[mt][q][3];
            }
        }
    }
    __syncthreads();
    // half0: pooled p 0..57 (local m = 3p); half1: p 58..106 (local m = 3p-160)
    const int np = h ? 49 : 58;
    const int pb = h ? 58 : 0;
    const int cnt = 50 * np;
    #pragma unroll 1
    for (int i = tid; i < cnt; i += 256) {
        int o = i / np, j = i - o * np;
        int p = pb + j;
        int ml = 3 * p - base;
        const float* c0 = Dsm + ml * 56 + o;
        float v = fmaxf(c0[0], fmaxf(c0[56], c0[112])) + bs[o];
        g_y2p[b * 5350 + o * 107 + p] = pack_bf16_split(elu1(v));
    }
}

// ---------------- stage 3 (TENSOR): y2p -> y3p ----------------
#define S3_KP 136
#define S3_NP 200
#define S3_AH 0
#define S3_AL 34816
#define S3_BH 69632
#define S3_BL 120832
#define S3_SMEM 172032

__global__ __launch_bounds__(256, 1) void stage3_k(const float* __restrict__ b3)
{
    extern __shared__ char smc[];
    const uint32_t sb = smem_u32(smc);
    const int tid = threadIdx.x, wid = tid >> 5, lane = tid & 31;
    const int s0 = blockIdx.x * 2;

    float d[24][4];
    #pragma unroll
    for (int i = 0; i < 24; i++)
        #pragma unroll
        for (int j = 0; j < 4; j++) d[i][j] = 0.f;

    const uint32_t aOff = ((wid * 16 + ((lane >> 3) & 1) * 8 + (lane & 7)) * S3_KP + (lane >> 4) * 8) * 2;
    const uint32_t bOff = ((((lane >> 3) & 1) * 8 + (lane & 7)) * S3_NP + (lane >> 4) * 8) * 2;
    const uint32_t aH = sb + S3_AH + aOff, aL = sb + S3_AL + aOff;
    const uint32_t bHb = sb + S3_BH + bOff, bLb = sb + S3_BL + bOff;

    const int kloc = tid >> 1, seg = tid & 1;
    uint16_t* bhRow = reinterpret_cast<uint16_t*>(smc + S3_BH) + kloc * S3_NP + seg * 96;
    uint16_t* blRow = reinterpret_cast<uint16_t*>(smc + S3_BL) + kloc * S3_NP + seg * 96;

    for (int ch = 0; ch < 4; ch++) {
        __syncthreads();
        {
            const float4* srcH = reinterpret_cast<const float4*>(g_w3h + ch * 17408);
            const float4* srcL = reinterpret_cast<const float4*>(g_w3l + ch * 17408);
            float4* dstH = reinterpret_cast<float4*>(smc + S3_AH);
            float4* dstL = reinterpret_cast<float4*>(smc + S3_AL);
            #pragma unroll 1
            for (int i = tid; i < 2176; i += 256) { dstH[i] = srcH[i]; dstL[i] = srcL[i]; }
        }
        {
            const int gk = ch * 128 + kloc;
            if (gk < 500) {
                const int c = gk / 10, kk = gk - c * 10;
                const uint32_t* src = g_y2p + (s0 + seg) * 5350 + c * 107 + kk;
                #pragma unroll 8
                for (int j = 0; j < 96; j += 2) {
                    uint32_t q0 = __ldg(&src[j]);
                    uint32_t q1 = __ldg(&src[j + 1]);
                    *reinterpret_cast<uint32_t*>(bhRow + j) = __byte_perm(q0, q1, 0x5410);
                    *reinterpret_cast<uint32_t*>(blRow + j) = __byte_perm(q0, q1, 0x7632);
                }
            } else {
                #pragma unroll 8
                for (int j = 0; j < 96; j += 2) {
                    *reinterpret_cast<uint32_t*>(bhRow + j) = 0u;
                    *reinterpret_cast<uint32_t*>(blRow + j) = 0u;
                }
            }
        }
        __syncthreads();

        #pragma unroll
        for (int t = 0; t < 8; t++) {
            uint32_t ah[4], al[4];
            ldsm4(ah, aH + t * 32);
            ldsm4(al, aL + t * 32);
            const uint32_t bt = (uint32_t)t * (16 * S3_NP * 2);
            #pragma unroll
            for (int q = 0; q < 12; q++) {
                uint32_t bh[4], bl[4];
                ldsm4t(bh, bHb + bt + q * 32);
                ldsm4t(bl, bLb + bt + q * 32);
                mma16816(d[2 * q],     ah, bh);
                mma16816(d[2 * q],     al, bh);
                mma16816(d[2 * q],     ah, bl);
                mma16816(d[2 * q + 1], ah, bh + 2);
                mma16816(d[2 * q + 1], al, bh + 2);
                mma16816(d[2 * q + 1], ah, bl + 2);
            }
        }
    }

    __syncthreads();
    float* Dsm = reinterpret_cast<float*>(smc);
    {
        const int r0 = wid * 16 + (lane >> 2);
        const int cb = (lane & 3) * 2;
        #pragma unroll
        for (int nt = 0; nt < 24; nt++) {
            int n = nt * 8 + cb;
            Dsm[r0 * 200 + n]           = d[nt][0];
            Dsm[r0 * 200 + n + 1]       = d[nt][1];
            Dsm[(r0 + 8) * 200 + n]     = d[nt][2];
            Dsm[(r0 + 8) * 200 + n + 1] = d[nt][3];
        }
    }
    __syncthreads();
    for (int i = tid; i < 6400; i += 256) {
        int o = i >> 6, r = i & 63, s = r >> 5, t = r & 31;
        int n = s * 96 + t * 3;
        float v = fmaxf(Dsm[o * 200 + n], fmaxf(Dsm[o * 200 + n + 1], Dsm[o * 200 + n + 2]))
                  + __ldg(&b3[o]);
        g_y3p[(s0 + s) * 3200 + o * 32 + t] = pack_bf16_split(elu1(v));
    }
}

// ---------------- stage 4 (TENSOR): y3p -> feat ----------------
#define S4_KP 136
#define S4_NP 56
#define S4_AH 0
#define S4_AL 69632
#define S4_BH 139264
#define S4_BL 153600
#define S4_SMEM 167936

__global__ __launch_bounds__(256, 1) void stage4_k(const float* __restrict__ b4)
{
    extern __shared__ char smc[];
    const uint32_t sb = smem_u32(smc);
    const int tid = threadIdx.x, wid = tid >> 5, lane = tid & 31;
    const int s0 = blockIdx.x * 2;

    float d[12][4];
    #pragma unroll
    for (int i = 0; i < 12; i++)
        #pragma unroll
        for (int j = 0; j < 4; j++) d[i][j] = 0.f;

    const uint32_t aOff0 = ((wid * 32 + ((lane >> 3) & 1) * 8 + (lane & 7)) * S4_KP + (lane >> 4) * 8) * 2;
    const uint32_t aOff1 = aOff0 + 16 * S4_KP * 2;
    const uint32_t bOff = ((((lane >> 3) & 1) * 8 + (lane & 7)) * S4_NP + (lane >> 4) * 8) * 2;
    const uint32_t aH0 = sb + S4_AH + aOff0, aL0 = sb + S4_AL + aOff0;
    const uint32_t aH1 = sb + S4_AH + aOff1, aL1 = sb + S4_AL + aOff1;
    const uint32_t bHb = sb + S4_BH + bOff, bLb = sb + S4_BL + bOff;

    const int kloc = tid >> 1, seg = tid & 1;
    uint16_t* bhRow = reinterpret_cast<uint16_t*>(smc + S4_BH) + kloc * S4_NP + seg * 24;
    uint16_t* blRow = reinterpret_cast<uint16_t*>(smc + S4_BL) + kloc * S4_NP + seg * 24;

    for (int ch = 0; ch < 8; ch++) {
        __syncthreads();
        {
            const float4* srcH = reinterpret_cast<const float4*>(g_w4h + ch * 34816);
            const float4* srcL = reinterpret_cast<const float4*>(g_w4l + ch * 34816);
            float4* dstH = reinterpret_cast<float4*>(smc + S4_AH);
            float4* dstL = reinterpret_cast<float4*>(smc + S4_AL);
            #pragma unroll 1
            for (int i = tid; i < 4352; i += 256) { dstH[i] = srcH[i]; dstL[i] = srcL[i]; }
        }
        {
            const int gk = ch * 128 + kloc;
            if (gk < 1000) {
                const int c = gk / 10, kk = gk - c * 10;
                const uint32_t* src = g_y3p + (s0 + seg) * 3200 + c * 32 + kk;
                #pragma unroll
                for (int j = 0; j < 24; j += 2) {
                    uint32_t q0 = (j < 21)     ? __ldg(&src[j])     : 0u;
                    uint32_t q1 = (j + 1 < 21) ? __ldg(&src[j + 1]) : 0u;
                    *reinterpret_cast<uint32_t*>(bhRow + j) = __byte_perm(q0, q1, 0x5410);
                    *reinterpret_cast<uint32_t*>(blRow + j) = __byte_perm(q0, q1, 0x7632);
                }
            } else {
                #pragma unroll
                for (int j = 0; j < 24; j += 2) {
                    *reinterpret_cast<uint32_t*>(bhRow + j) = 0u;
                    *reinterpret_cast<uint32_t*>(blRow + j) = 0u;
                }
            }
        }
        __syncthreads();

        #pragma unroll
        for (int t = 0; t < 8; t++) {
            uint32_t ah0[4], al0[4], ah1[4], al1[4];
            ldsm4(ah0, aH0 + t * 32);
            ldsm4(al0, aL0 + t * 32);
            ldsm4(ah1, aH1 + t * 32);
            ldsm4(al1, aL1 + t * 32);
            const uint32_t bt = (uint32_t)t * (16 * S4_NP * 2);
            #pragma unroll
            for (int q = 0; q < 3; q++) {
                uint32_t bh[4], bl[4];
                ldsm4t(bh, bHb + bt + q * 32);
                ldsm4t(bl, bLb + bt + q * 32);
                mma16816(d[2 * q],     ah0, bh);
                mma16816(d[2 * q],     al0, bh);
                mma16816(d[2 * q],     ah0, bl);
                mma16816(d[2 * q + 1], ah0, bh + 2);
                mma16816(d[2 * q + 1], al0, bh + 2);
                mma16816(d[2 * q + 1], ah0, bl + 2);
                mma16816(d[6 + 2 * q],     ah1, bh);
                mma16816(d[6 + 2 * q],     al1, bh);
                mma16816(d[6 + 2 * q],     ah1, bl);
                mma16816(d[6 + 2 * q + 1], ah1, bh + 2);
                mma16816(d[6 + 2 * q + 1], al1, bh + 2);
                mma16816(d[6 + 2 * q + 1], ah1, bl + 2);
            }
        }
    }

    __syncthreads();
    float* Dsm = reinterpret_cast<float*>(smc);
    {
        const int r0 = wid * 32 + (lane >> 2);
        const int cb = (lane & 3) * 2;
        #pragma unroll
        for (int m = 0; m < 2; m++) {
            #pragma unroll
            for (int q = 0; q < 6; q++) {
                int row = r0 + m * 16;
                int n = q * 8 + cb;
                Dsm[row * 56 + n]           = d[m * 6 + q][0];
                Dsm[row * 56 + n + 1]       = d[m * 6 + q][1];
                Dsm[(row + 8) * 56 + n]     = d[m * 6 + q][2];
                Dsm[(row + 8) * 56 + n + 1] = d[m * 6 + q][3];
            }
        }
    }
    __syncthreads();
    for (int i = tid; i < 2800; i += 256) {
        int o = i / 14, r = i - o * 14, s = r / 7, t = r - s * 7;
        int n = s * 24 + t * 3;
        float v = fmaxf(Dsm[o * 56 + n], fmaxf(Dsm[o * 56 + n + 1], Dsm[o * 56 + n + 2]))
                  + __ldg(&b4[o]);
        g_feat[(s0 + s) * 1400 + o * 7 + t] = elu1(v);
    }
}

// ---------------- head ----------------
__global__ void head_k(const int* __restrict__ sid, const float* __restrict__ hW,
                       const float* __restrict__ hB, float* __restrict__ out)
{
    const int b = blockIdx.x;
    const int s = sid[b];
    const float* f = g_feat + b * 1400;
    const float* W = hW + s * (4 * 1400);
    float acc[4] = {0.f, 0.f, 0.f, 0.f};
    for (int i = threadIdx.x; i < 1400; i += blockDim.x) {
        float fv = f[i];
        #pragma unroll
        for (int o = 0; o < 4; o++) acc[o] = fmaf(fv, __ldg(&W[o * 1400 + i]), acc[o]);
    }
    #pragma unroll
    for (int off = 16; off > 0; off >>= 1) {
        #pragma unroll
        for (int o = 0; o < 4; o++) acc[o] += __shfl_down_sync(0xFFFFFFFFu, acc[o], off);
    }
    __shared__ float red[4][4];
    const int w = threadIdx.x >> 5, l = threadIdx.x & 31;
    if (l == 0) {
        #pragma unroll
        for (int o = 0; o < 4; o++) red[o][w] = acc[o];
    }
    __syncthreads();
    if (threadIdx.x < 4) {
        int o = threadIdx.x;
        out[b * 4 + o] = red[o][0] + red[o][1] + red[o][2] + red[o][3] + __ldg(&hB[s * 4 + o]);
    }
}

// ---------------- launch ----------------
extern "C" void kernel_launch(void* const* d_in, const int* in_sizes, int n_in,
                              void* d_out, int out_size)
{
    const float* x      = (const float*)d_in[0];
    const int*   sid    = (const int*)  d_in[1];
    const float* w_time = (const float*)d_in[2];
    const float* b_time = (const float*)d_in[3];
    const float* w_spat = (const float*)d_in[4];
    const float* b_spat = (const float*)d_in[5];
    const float* w2     = (const float*)d_in[6];
    const float* b2     = (const float*)d_in[7];
    const float* w3     = (const float*)d_in[8];
    const float* b3     = (const float*)d_in[9];
    const float* w4     = (const float*)d_in[10];
    const float* b4     = (const float*)d_in[11];
    const float* hW     = (const float*)d_in[12];
    const float* hB     = (const float*)d_in[13];
    float* out = (float*)d_out;

    cudaFuncSetAttribute(stage1_k, cudaFuncAttributeMaxDynamicSharedMemorySize, S1_SMEM);
    cudaFuncSetAttribute(stage2_k, cudaFuncAttributeMaxDynamicSharedMemorySize, S2_SMEM);
    cudaFuncSetAttribute(stage3_k, cudaFuncAttributeMaxDynamicSharedMemorySize, S3_SMEM);
    cudaFuncSetAttribute(stage4_k, cudaFuncAttributeMaxDynamicSharedMemorySize, S4_SMEM);

    precompute_k<<<1, 256>>>(w_time, b_time, w_spat, b_spat);
    precompute_w_k<<<(378880 + 255) / 256, 256>>>(w2, w3, w4);
    stage1_k<<<dim3(B_, 6), 384, S1_SMEM>>>(x);
    stage2_k<<<dim3(B_, 2), 256, S2_SMEM>>>(b2);
    stage3_k<<<128, 256, S3_SMEM>>>(b3);
    stage4_k<<<128, 256, S4_SMEM>>>(b4);
    head_k<<<B_, 128>>>(sid, hW, hB, out);
}

// round 14
// speedup vs baseline: 1.9770x; 1.0855x over previous
#include <cuda_runtime.h>
#include <cuda_bf16.h>
#include <math.h>
#include <stdint.h>

#define B_ 256

// ---------------- device scratch ----------------
__device__ float g_Weff[25 * 220];
__device__ float g_beff[25];
__device__ uint32_t g_y1p[B_ * 330 * 26];            // TRANSPOSED: [b][pos][ch(25)+pad]
__device__ uint32_t g_y2p[B_ * 50 * 107];
__device__ uint32_t g_y3p[B_ * 100 * 32];
__device__ float g_feat[B_ * 1400];
// weight images (bf16 split)
__device__ __align__(16) uint16_t g_w1h[10 * 32 * 40];
__device__ __align__(16) uint16_t g_w1l[10 * 32 * 40];
__device__ __align__(16) uint16_t g_w2th[10 * 32 * 56];
__device__ __align__(16) uint16_t g_w2tl[10 * 32 * 56];
__device__ __align__(16) uint16_t g_w3h[8 * 128 * 72];   // [8 k-chunks of 64][128 rows][72]
__device__ __align__(16) uint16_t g_w3l[8 * 128 * 72];
__device__ __align__(16) uint16_t g_w4h[16 * 256 * 72];  // [16 k-chunks of 64][256 rows][72]
__device__ __align__(16) uint16_t g_w4l[16 * 256 * 72];

__device__ __forceinline__ float elu1(float x) { return x > 0.f ? x : expm1f(x); }

__device__ __forceinline__ uint32_t smem_u32(const void* p) {
    uint32_t a;
    asm("{ .reg .u64 t; cvta.to.shared.u64 t, %1; cvt.u32.u64 %0, t; }" : "=r"(a) : "l"(p));
    return a;
}
__device__ __forceinline__ void ldsm4(uint32_t* r, uint32_t addr) {
    asm volatile("ldmatrix.sync.aligned.m8n8.x4.shared.b16 {%0,%1,%2,%3}, [%4];"
                 : "=r"(r[0]), "=r"(r[1]), "=r"(r[2]), "=r"(r[3]) : "r"(addr));
}
__device__ __forceinline__ void ldsm4t(uint32_t* r, uint32_t addr) {
    asm volatile("ldmatrix.sync.aligned.m8n8.x4.trans.shared.b16 {%0,%1,%2,%3}, [%4];"
                 : "=r"(r[0]), "=r"(r[1]), "=r"(r[2]), "=r"(r[3]) : "r"(addr));
}
__device__ __forceinline__ void mma16816(float* d, const uint32_t* a, const uint32_t* b) {
    asm volatile("mma.sync.aligned.m16n8k16.row.col.f32.bf16.bf16.f32 "
                 "{%0,%1,%2,%3}, {%4,%5,%6,%7}, {%8,%9}, {%0,%1,%2,%3};"
                 : "+f"(d[0]), "+f"(d[1]), "+f"(d[2]), "+f"(d[3])
                 : "r"(a[0]), "r"(a[1]), "r"(a[2]), "r"(a[3]), "r"(b[0]), "r"(b[1]));
}
__device__ __forceinline__ uint32_t pack_bf16_split(float v) {
    __nv_bfloat16 h = __float2bfloat16(v);
    float hf = __bfloat162float(h);
    __nv_bfloat16 l = __float2bfloat16(v - hf);
    uint16_t hb = reinterpret_cast<uint16_t&>(h);
    uint16_t lb = reinterpret_cast<uint16_t&>(l);
    return (uint32_t)hb | ((uint32_t)lb << 16);
}

// ---------------- kernel 0: fold conv_time into conv_spat ----------------
__global__ void precompute_k(const float* __restrict__ w_time, const float* __restrict__ b_time,
                             const float* __restrict__ w_spat, const float* __restrict__ b_spat)
{
    for (int idx = threadIdx.x; idx < 25 * 220; idx += blockDim.x) {
        int p = idx / 220, rem = idx % 220, c = rem / 10, k = rem % 10;
        float s = 0.f;
        #pragma unroll
        for (int o = 0; o < 25; o++)
            s = fmaf(w_spat[p * 550 + o * 22 + c], w_time[o * 10 + k], s);
        g_Weff[idx] = s;
    }
    if (threadIdx.x < 25) {
        int p = threadIdx.x;
        float s = b_spat[p];
        for (int o = 0; o < 25; o++) {
            float w = 0.f;
            for (int c = 0; c < 22; c++) w += w_spat[p * 550 + o * 22 + c];
            s = fmaf(b_time[o], w, s);
        }
        g_beff[p] = s;
    }
}

// ---------------- kernel 0b: ALL weight images in one launch ----------------
// w3: [8][128][72] (73728), w4: [16][256][72] (294912), w1 (12800), w2t (17920)
__global__ void precompute_w_k(const float* __restrict__ w2, const float* __restrict__ w3,
                               const float* __restrict__ w4)
{
    int idx = blockIdx.x * 256 + threadIdx.x;
    if (idx < 73728) {
        int ch = idx / 9216, r = idx % 9216, row = r / 72, kloc = r % 72;
        int gk = ch * 64 + kloc;
        float v = (kloc < 64 && row < 100 && gk < 500) ? w3[row * 500 + gk] : 0.f;
        uint32_t p = pack_bf16_split(v);
        g_w3h[idx] = (uint16_t)(p & 0xffff);
        g_w3l[idx] = (uint16_t)(p >> 16);
    } else if (idx < 368640) {
        int i4 = idx - 73728;
        int ch = i4 / 18432, r = i4 % 18432, row = r / 72, kloc = r % 72;
        int gk = ch * 64 + kloc;
        float v = (kloc < 64 && row < 200 && gk < 1000) ? w4[row * 1000 + gk] : 0.f;
        uint32_t p = pack_bf16_split(v);
        g_w4h[i4] = (uint16_t)(p & 0xffff);
        g_w4l[i4] = (uint16_t)(p >> 16);
    } else if (idx < 381440) {
        int i1 = idx - 368640;
        int kk = i1 / 1280, r = i1 % 1280, c = r / 40, o = r % 40;
        float v = (c < 22 && o < 25) ? g_Weff[o * 220 + c * 10 + kk] : 0.f;
        uint32_t p = pack_bf16_split(v);
        g_w1h[i1] = (uint16_t)(p & 0xffff);
        g_w1l[i1] = (uint16_t)(p >> 16);
    } else if (idx < 399360) {
        int i2 = idx - 381440;
        int kk = i2 / 1792, r = i2 % 1792, c = r / 56, o = r % 56;
        float v = (c < 25 && o < 50) ? w2[o * 250 + c * 10 + kk] : 0.f;
        uint32_t p = pack_bf16_split(v);
        g_w2th[i2] = (uint16_t)(p & 0xffff);
        g_w2tl[i2] = (uint16_t)(p >> 16);
    }
}

// ---------------- stage 1 (TENSOR, tap-decomposed): x -> y1pT ----------------
#define S1_AH 0
#define S1_AL 16640
#define S1_WH 33280
#define S1_WL 58880
#define S1_SMEM 84480

__global__ __launch_bounds__(384, 2) void stage1_k(const float* __restrict__ x)
{
    extern __shared__ char smc[];
    const uint32_t sb = smem_u32(smc);
    const int tid = threadIdx.x, wid = tid >> 5, lane = tid & 31;
    const int b = blockIdx.x, tile = blockIdx.y;
    const int m0 = tile * 192;
    __shared__ float bs[25];
    if (tid < 25) bs[tid] = g_beff[tid];

    {
        const float4* srcH = reinterpret_cast<const float4*>(g_w1h);
        const float4* srcL = reinterpret_cast<const float4*>(g_w1l);
        float4* dstH = reinterpret_cast<float4*>(smc + S1_WH);
        float4* dstL = reinterpret_cast<float4*>(smc + S1_WL);
        #pragma unroll 1
        for (int i = tid; i < 1600; i += 384) { dstH[i] = srcH[i]; dstL[i] = srcL[i]; }
    }
    {
        const float* xb = x + b * 22000;
        #pragma unroll 1
        for (int i = tid; i < 4160; i += 384) {
            int cp = i / 208, r = i - cp * 208;
            int t = m0 + r;
            uint32_t h2 = 0u, l2 = 0u;
            if (cp < 11 && t < 1000) {
                uint32_t p0 = pack_bf16_split(__ldg(&xb[(2 * cp) * 1000 + t]));
                uint32_t p1 = pack_bf16_split(__ldg(&xb[(2 * cp + 1) * 1000 + t]));
                h2 = __byte_perm(p0, p1, 0x5410);
                l2 = __byte_perm(p0, p1, 0x7632);
            }
            reinterpret_cast<uint32_t*>(smc + S1_AH)[r * 20 + cp] = h2;
            reinterpret_cast<uint32_t*>(smc + S1_AL)[r * 20 + cp] = l2;
        }
    }
    __syncthreads();

    float d[4][4];
    #pragma unroll
    for (int i = 0; i < 4; i++)
        #pragma unroll
        for (int j = 0; j < 4; j++) d[i][j] = 0.f;

    const uint32_t aOff = ((wid * 16 + ((lane >> 3) & 1) * 8 + (lane & 7)) * 40 + (lane >> 4) * 8) * 2;
    const uint32_t aHb = sb + S1_AH + aOff, aLb = sb + S1_AL + aOff;
    const uint32_t bOff = ((((lane >> 3) & 1) * 8 + (lane & 7)) * 40 + (lane >> 4) * 8) * 2;
    const uint32_t bHb = sb + S1_WH + bOff, bLb = sb + S1_WL + bOff;

    #pragma unroll 1
    for (int kk = 0; kk < 10; kk++) {
        #pragma unroll
        for (int s = 0; s < 2; s++) {
            uint32_t ah[4], al[4];
            ldsm4(ah, aHb + kk * 80 + s * 32);
            ldsm4(al, aLb + kk * 80 + s * 32);
            const uint32_t wb = (uint32_t)kk * 2560 + (uint32_t)s * 1280;
            #pragma unroll
            for (int q = 0; q < 2; q++) {
                uint32_t bh[4], bl[4];
                ldsm4t(bh, bHb + wb + q * 32);
                ldsm4t(bl, bLb + wb + q * 32);
                mma16816(d[2 * q],     ah, bh);
                mma16816(d[2 * q],     al, bh);
                mma16816(d[2 * q],     ah, bl);
                mma16816(d[2 * q + 1], ah, bh + 2);
                mma16816(d[2 * q + 1], al, bh + 2);
                mma16816(d[2 * q + 1], ah, bl + 2);
            }
        }
    }

    __syncthreads();
    float* Dsm = reinterpret_cast<float*>(smc);
    {
        const int mloc = wid * 16 + (lane >> 2);
        const int cb = (lane & 3) * 2;
        #pragma unroll
        for (int q = 0; q < 4; q++) {
            int n = q * 8 + cb;
            Dsm[n * 200 + mloc]           = d[q][0];
            Dsm[(n + 1) * 200 + mloc]     = d[q][1];
            Dsm[n * 200 + mloc + 8]       = d[q][2];
            Dsm[(n + 1) * 200 + mloc + 8] = d[q][3];
        }
    }
    __syncthreads();
    #pragma unroll 1
    for (int i = tid; i < 1664; i += 384) {
        int j = i / 26, o = i - j * 26;
        int tp = tile * 64 + j;
        if (tp < 330) {
            uint32_t pv = 0u;
            if (o < 25) {
                const float* row = Dsm + o * 200 + 3 * j;
                float v = fmaxf(row[0], fmaxf(row[1], row[2])) + bs[o];
                pv = pack_bf16_split(elu1(v));
            }
            g_y1p[b * 8580 + tp * 26 + o] = pv;
        }
    }
}

// ---------------- stage 2 (TENSOR, tap-decomposed, m-split): y1pT -> y2p ----------------
#define S2_AH 0
#define S2_AL 15360
#define S2_WH 30720
#define S2_WL 66560
#define S2_SMEM 102400

__global__ __launch_bounds__(256, 2) void stage2_k(const float* __restrict__ b2)
{
    extern __shared__ char smc[];
    const uint32_t sb = smem_u32(smc);
    const int tid = threadIdx.x, wid = tid >> 5, lane = tid & 31;
    const int b = blockIdx.x, h = blockIdx.y;
    const int base = h * 160;
    __shared__ float bs[50];
    if (tid < 50) bs[tid] = __ldg(&b2[tid]);

    {
        const float4* srcH = reinterpret_cast<const float4*>(g_w2th);
        const float4* srcL = reinterpret_cast<const float4*>(g_w2tl);
        float4* dstH = reinterpret_cast<float4*>(smc + S2_WH);
        float4* dstL = reinterpret_cast<float4*>(smc + S2_WL);
        #pragma unroll 1
        for (int i = tid; i < 2240; i += 256) { dstH[i] = srcH[i]; dstL[i] = srcL[i]; }
    }
    {
        const uint32_t* yb = g_y1p + b * 8580;
        #pragma unroll 1
        for (int i = tid; i < 3072; i += 256) {
            int r = i >> 4, cp = i & 15;
            int gp = base + r;
            uint32_t h2 = 0u, l2 = 0u;
            if (gp < 330 && cp < 13) {
                uint32_t p0 = __ldg(&yb[gp * 26 + 2 * cp]);
                uint32_t p1 = __ldg(&yb[gp * 26 + 2 * cp + 1]);
                h2 = __byte_perm(p0, p1, 0x5410);
                l2 = __byte_perm(p0, p1, 0x7632);
            }
            *reinterpret_cast<uint32_t*>(smc + S2_AH + r * 80 + cp * 4) = h2;
            *reinterpret_cast<uint32_t*>(smc + S2_AL + r * 80 + cp * 4) = l2;
        }
    }
    __syncthreads();

    float d[2][7][4];
    #pragma unroll
    for (int m = 0; m < 2; m++)
        #pragma unroll
        for (int q = 0; q < 7; q++)
            #pragma unroll
            for (int j = 0; j < 4; j++) d[m][q][j] = 0.f;

    const uint32_t aLane = ((((lane >> 3) & 1) * 8 + (lane & 7)) * 40 + (lane >> 4) * 8) * 2;
    const uint32_t bLane = ((((lane >> 3) & 1) * 8 + (lane & 7)) * 56 + (lane >> 4) * 8) * 2;
    const bool has2 = (wid < 3);

    #pragma unroll 1
    for (int kk = 0; kk < 10; kk++) {
        #pragma unroll
        for (int g = 0; g < 2; g++) {
            uint32_t bh[4][4], bl[4][4];
            const uint32_t wb = sb + (uint32_t)kk * 3584 + (uint32_t)g * (16 * 112) + bLane;
            #pragma unroll
            for (int q = 0; q < 4; q++) {
                ldsm4t(bh[q], S2_WH + wb + q * 32);
                ldsm4t(bl[q], S2_WL + wb + q * 32);
            }
            #pragma unroll
            for (int mt = 0; mt < 2; mt++) {
                if (mt == 1 && !has2) break;
                const int t = wid + mt * 8;
                const uint32_t arow = (uint32_t)(t * 16 + kk) * 80 + (uint32_t)g * 32;
                uint32_t ah[4], al[4];
                ldsm4(ah, sb + S2_AH + arow + aLane);
                ldsm4(al, sb + S2_AL + arow + aLane);
                #pragma unroll
                for (int q = 0; q < 3; q++) {
                    mma16816(d[mt][2 * q],     ah, bh[q]);
                    mma16816(d[mt][2 * q],     al, bh[q]);
                    mma16816(d[mt][2 * q],     ah, bl[q]);
                    mma16816(d[mt][2 * q + 1], ah, bh[q] + 2);
                    mma16816(d[mt][2 * q + 1], al, bh[q] + 2);
                    mma16816(d[mt][2 * q + 1], ah, bl[q] + 2);
                }
                mma16816(d[mt][6], ah, bh[3]);
                mma16816(d[mt][6], al, bh[3]);
                mma16816(d[mt][6], ah, bl[3]);
            }
        }
    }

    __syncthreads();
    float* Dsm = reinterpret_cast<float*>(smc);
    {
        const int r0 = (lane >> 2);
        const int cb = (lane & 3) * 2;
        #pragma unroll
        for (int mt = 0; mt < 2; mt++) {
            if (mt == 1 && !has2) break;
            const int rr = (wid + mt * 8) * 16 + r0;
            #pragma unroll
            for (int q = 0; q < 7; q++) {
                int n = q * 8 + cb;
                Dsm[rr * 56 + n]           = d[mt][q][0];
                Dsm[rr * 56 + n + 1]       = d[mt][q][1];
                Dsm[(rr + 8) * 56 + n]     = d[mt][q][2];
                Dsm[(rr + 8) * 56 + n + 1] = d[mt][q][3];
            }
        }
    }
    __syncthreads();
    const int np = h ? 49 : 58;
    const int pb = h ? 58 : 0;
    const int cnt = 50 * np;
    #pragma unroll 1
    for (int i = tid; i < cnt; i += 256) {
        int o = i / np, j = i - o * np;
        int p = pb + j;
        int ml = 3 * p - base;
        const float* c0 = Dsm + ml * 56 + o;
        float v = fmaxf(c0[0], fmaxf(c0[56], c0[112])) + bs[o];
        g_y2p[b * 5350 + o * 107 + p] = pack_bf16_split(elu1(v));
    }
}

// ---------------- stage 3 (TENSOR, 1 sample/CTA, 64-k chunks): y2p -> y3p ----------------
// D[128 m=w3 rows][96 n=positions] = A(w3)[128][512] x B(im2col)[96][512]^T
// A stride 72 u16 (144 B), B [64 k][104 u16 stride] (208 B); 2 CTAs/SM.
#define S3_AH 0
#define S3_AL 18432
#define S3_BH 36864
#define S3_BL 50176
#define S3_SMEM 63488

__global__ __launch_bounds__(256, 2) void stage3_k(const float* __restrict__ b3)
{
    extern __shared__ char smc[];
    const uint32_t sb = smem_u32(smc);
    const int tid = threadIdx.x, wid = tid >> 5, lane = tid & 31;
    const int b = blockIdx.x;
    __shared__ float bs[100];
    if (tid < 100) bs[tid] = __ldg(&b3[tid]);

    float d[12][4];
    #pragma unroll
    for (int i = 0; i < 12; i++)
        #pragma unroll
        for (int j = 0; j < 4; j++) d[i][j] = 0.f;

    const uint32_t aOff = ((wid * 16 + ((lane >> 3) & 1) * 8 + (lane & 7)) * 72 + (lane >> 4) * 8) * 2;
    const uint32_t bOff = ((((lane >> 3) & 1) * 8 + (lane & 7)) * 104 + (lane >> 4) * 8) * 2;
    const uint32_t aH = sb + S3_AH + aOff, aL = sb + S3_AL + aOff;
    const uint32_t bHb = sb + S3_BH + bOff, bLb = sb + S3_BL + bOff;

    const int kloc = tid >> 2, seg = tid & 3;   // k row 0..63, col-quarter (24 cols)
    uint16_t* bhRow = reinterpret_cast<uint16_t*>(smc + S3_BH) + kloc * 104 + seg * 24;
    uint16_t* blRow = reinterpret_cast<uint16_t*>(smc + S3_BL) + kloc * 104 + seg * 24;

    #pragma unroll 1
    for (int ch = 0; ch < 8; ch++) {
        __syncthreads();
        // A copy: 1152 float4 per split
        {
            const float4* srcH = reinterpret_cast<const float4*>(g_w3h + ch * 9216);
            const float4* srcL = reinterpret_cast<const float4*>(g_w3l + ch * 9216);
            float4* dstH = reinterpret_cast<float4*>(smc + S3_AH);
            float4* dstL = reinterpret_cast<float4*>(smc + S3_AL);
            #pragma unroll 1
            for (int i = tid; i < 1152; i += 256) { dstH[i] = srcH[i]; dstL[i] = srcL[i]; }
        }
        // B gather (no duplication beyond taps; 24 cols per thread)
        {
            const int gk = ch * 64 + kloc;
            if (gk < 500) {
                const int c = gk / 10, kk = gk - c * 10;
                const uint32_t* src = g_y2p + b * 5350 + c * 107 + kk + seg * 24;
                #pragma unroll
                for (int j = 0; j < 24; j += 2) {
                    uint32_t q0 = __ldg(&src[j]);
                    uint32_t q1 = __ldg(&src[j + 1]);
                    *reinterpret_cast<uint32_t*>(bhRow + j) = __byte_perm(q0, q1, 0x5410);
                    *reinterpret_cast<uint32_t*>(blRow + j) = __byte_perm(q0, q1, 0x7632);
                }
            } else {
                #pragma unroll
                for (int j = 0; j < 24; j += 2) {
                    *reinterpret_cast<uint32_t*>(bhRow + j) = 0u;
                    *reinterpret_cast<uint32_t*>(blRow + j) = 0u;
                }
            }
        }
        __syncthreads();

        #pragma unroll
        for (int t = 0; t < 4; t++) {
            uint32_t ah[4], al[4];
            ldsm4(ah, aH + t * 32);
            ldsm4(al, aL + t * 32);
            const uint32_t bt = (uint32_t)t * 3328;   // 16 rows * 208 B
            #pragma unroll
            for (int q = 0; q < 6; q++) {
                uint32_t bh[4], bl[4];
                ldsm4t(bh, bHb + bt + q * 32);
                ldsm4t(bl, bLb + bt + q * 32);
                mma16816(d[2 * q],     ah, bh);
                mma16816(d[2 * q],     al, bh);
                mma16816(d[2 * q],     ah, bl);
                mma16816(d[2 * q + 1], ah, bh + 2);
                mma16816(d[2 * q + 1], al, bh + 2);
                mma16816(d[2 * q + 1], ah, bl + 2);
            }
        }
    }

    // epilogue: Dsm [128 o][100 stride] f32 (51,200 B)
    __syncthreads();
    float* Dsm = reinterpret_cast<float*>(smc);
    {
        const int r0 = wid * 16 + (lane >> 2);
        const int cb = (lane & 3) * 2;
        #pragma unroll
        for (int q = 0; q < 12; q++) {
            int n = q * 8 + cb;
            Dsm[r0 * 100 + n]           = d[q][0];
            Dsm[r0 * 100 + n + 1]       = d[q][1];
            Dsm[(r0 + 8) * 100 + n]     = d[q][2];
            Dsm[(r0 + 8) * 100 + n + 1] = d[q][3];
        }
    }
    __syncthreads();
    #pragma unroll 1
    for (int i = tid; i < 3200; i += 256) {
        int o = i >> 5, t = i & 31;
        const float* c0 = Dsm + o * 100 + 3 * t;
        float v = fmaxf(c0[0], fmaxf(c0[1], c0[2])) + bs[o];
        g_y3p[b * 3200 + o * 32 + t] = pack_bf16_split(elu1(v));
    }
}

// ---------------- stage 4 (TENSOR, m-split, 64-k chunks): y3p -> feat ----------------
// grid (128 sample-pairs, 2 m-halves). D[128 rows][48 n (2 samples x 24)]
// A stride 72 u16, B [64 k][56 u16 stride]; 3 CTAs/SM.
#define S4_AH 0
#define S4_AL 18432
#define S4_BH 36864
#define S4_BL 44032
#define S4_SMEM 51200

__global__ __launch_bounds__(256, 3) void stage4_k(const float* __restrict__ b4)
{
    extern __shared__ char smc[];
    const uint32_t sb = smem_u32(smc);
    const int tid = threadIdx.x, wid = tid >> 5, lane = tid & 31;
    const int s0 = blockIdx.x * 2, h = blockIdx.y;
    const int nrow = h ? 72 : 128;
    __shared__ float bs[128];
    if (tid < 128) bs[tid] = (h * 128 + tid < 200) ? __ldg(&b4[h * 128 + tid]) : 0.f;

    // zero pad cols 48..55 once (never rewritten)
    {
        uint16_t* bhB = reinterpret_cast<uint16_t*>(smc + S4_BH);
        uint16_t* blB = reinterpret_cast<uint16_t*>(smc + S4_BL);
        for (int i = tid; i < 512; i += 256) {
            int r = i >> 3, c = 48 + (i & 7);
            bhB[r * 56 + c] = 0;
            blB[r * 56 + c] = 0;
        }
    }

    float d[6][4];
    #pragma unroll
    for (int i = 0; i < 6; i++)
        #pragma unroll
        for (int j = 0; j < 4; j++) d[i][j] = 0.f;

    const uint32_t aOff = ((wid * 16 + ((lane >> 3) & 1) * 8 + (lane & 7)) * 72 + (lane >> 4) * 8) * 2;
    const uint32_t bOff = ((((lane >> 3) & 1) * 8 + (lane & 7)) * 56 + (lane >> 4) * 8) * 2;
    const uint32_t aH = sb + S4_AH + aOff, aL = sb + S4_AL + aOff;
    const uint32_t bHb = sb + S4_BH + bOff, bLb = sb + S4_BL + bOff;

    const int kloc = tid >> 2, q4 = tid & 3;         // k row, quarter
    const int segq = q4 >> 1, jb = (q4 & 1) * 12;    // sample, col sub-block
    uint16_t* bhRow = reinterpret_cast<uint16_t*>(smc + S4_BH) + kloc * 56 + segq * 24 + jb;
    uint16_t* blRow = reinterpret_cast<uint16_t*>(smc + S4_BL) + kloc * 56 + segq * 24 + jb;

    #pragma unroll 1
    for (int ch = 0; ch < 16; ch++) {
        __syncthreads();
        // A copy: this half's 128 rows of the chunk (1152 float4 per split)
        {
            const float4* srcH = reinterpret_cast<const float4*>(g_w4h + ch * 18432 + h * 9216);
            const float4* srcL = reinterpret_cast<const float4*>(g_w4l + ch * 18432 + h * 9216);
            float4* dstH = reinterpret_cast<float4*>(smc + S4_AH);
            float4* dstL = reinterpret_cast<float4*>(smc + S4_AL);
            #pragma unroll 1
            for (int i = tid; i < 1152; i += 256) { dstH[i] = srcH[i]; dstL[i] = srcL[i]; }
        }
        // B gather: 12 cols per thread
        {
            const int gk = ch * 64 + kloc;
            if (gk < 1000) {
                const int c = gk / 10, kk = gk - c * 10;
                const uint32_t* src = g_y3p + (s0 + segq) * 3200 + c * 32 + kk + jb;
                #pragma unroll
                for (int j = 0; j < 12; j += 2) {
                    int gp = jb + j;                          // conv position
                    uint32_t q0 = (gp < 21)     ? __ldg(&src[j])     : 0u;
                    uint32_t q1 = (gp + 1 < 21) ? __ldg(&src[j + 1]) : 0u;
                    *reinterpret_cast<uint32_t*>(bhRow + j) = __byte_perm(q0, q1, 0x5410);
                    *reinterpret_cast<uint32_t*>(blRow + j) = __byte_perm(q0, q1, 0x7632);
                }
            } else {
                #pragma unroll
                for (int j = 0; j < 12; j += 2) {
                    *reinterpret_cast<uint32_t*>(bhRow + j) = 0u;
                    *reinterpret_cast<uint32_t*>(blRow + j) = 0u;
                }
            }
        }
        __syncthreads();

        #pragma unroll
        for (int t = 0; t < 4; t++) {
            uint32_t ah[4], al[4];
            ldsm4(ah, aH + t * 32);
            ldsm4(al, aL + t * 32);
            const uint32_t bt = (uint32_t)t * 1792;   // 16 rows * 112 B
            #pragma unroll
            for (int q = 0; q < 3; q++) {
                uint32_t bh[4], bl[4];
                ldsm4t(bh, bHb + bt + q * 32);
                ldsm4t(bl, bLb + bt + q * 32);
                mma16816(d[2 * q],     ah, bh);
                mma16816(d[2 * q],     al, bh);
                mma16816(d[2 * q],     ah, bl);
                mma16816(d[2 * q + 1], ah, bh + 2);
                mma16816(d[2 * q + 1], al, bh + 2);
                mma16816(d[2 * q + 1], ah, bl + 2);
            }
        }
    }

    // epilogue: Dsm [128 rows][56] f32 (28,672 B)
    __syncthreads();
    float* Dsm = reinterpret_cast<float*>(smc);
    {
        const int r0 = wid * 16 + (lane >> 2);
        const int cb = (lane & 3) * 2;
        #pragma unroll
        for (int q = 0; q < 6; q++) {
            int n = q * 8 + cb;
            Dsm[r0 * 56 + n]           = d[q][0];
            Dsm[r0 * 56 + n + 1]       = d[q][1];
            Dsm[(r0 + 8) * 56 + n]     = d[q][2];
            Dsm[(r0 + 8) * 56 + n + 1] = d[q][3];
        }
    }
    __syncthreads();
    const int cnt = nrow * 14;
    #pragma unroll 1
    for (int i = tid; i < cnt; i += 256) {
        int ol = i / 14, r = i - ol * 14, s = r / 7, t = r - s * 7;
        int n = s * 24 + 3 * t;
        float v = fmaxf(Dsm[ol * 56 + n], fmaxf(Dsm[ol * 56 + n + 1], Dsm[ol * 56 + n + 2]))
                  + bs[ol];
        g_feat[(s0 + s) * 1400 + (h * 128 + ol) * 7 + t] = elu1(v);
    }
}

// ---------------- head ----------------
__global__ void head_k(const int* __restrict__ sid, const float* __restrict__ hW,
                       const float* __restrict__ hB, float* __restrict__ out)
{
    const int b = blockIdx.x;
    const int s = sid[b];
    const float* f = g_feat + b * 1400;
    const float* W = hW + s * (4 * 1400);
    float acc[4] = {0.f, 0.f, 0.f, 0.f};
    for (int i = threadIdx.x; i < 1400; i += blockDim.x) {
        float fv = f[i];
        #pragma unroll
        for (int o = 0; o < 4; o++) acc[o] = fmaf(fv, __ldg(&W[o * 1400 + i]), acc[o]);
    }
    #pragma unroll
    for (int off = 16; off > 0; off >>= 1) {
        #pragma unroll
        for (int o = 0; o < 4; o++) acc[o] += __shfl_down_sync(0xFFFFFFFFu, acc[o], off);
    }
    __shared__ float red[4][4];
    const int w = threadIdx.x >> 5, l = threadIdx.x & 31;
    if (l == 0) {
        #pragma unroll
        for (int o = 0; o < 4; o++) red[o][w] = acc[o];
    }
    __syncthreads();
    if (threadIdx.x < 4) {
        int o = threadIdx.x;
        out[b * 4 + o] = red[o][0] + red[o][1] + red[o][2] + red[o][3] + __ldg(&hB[s * 4 + o]);
    }
}

// ---------------- launch ----------------
extern "C" void kernel_launch(void* const* d_in, const int* in_sizes, int n_in,
                              void* d_out, int out_size)
{
    const float* x      = (const float*)d_in[0];
    const int*   sid    = (const int*)  d_in[1];
    const float* w_time = (const float*)d_in[2];
    const float* b_time = (const float*)d_in[3];
    const float* w_spat = (const float*)d_in[4];
    const float* b_spat = (const float*)d_in[5];
    const float* w2     = (const float*)d_in[6];
    const float* b2     = (const float*)d_in[7];
    const float* w3     = (const float*)d_in[8];
    const float* b3     = (const float*)d_in[9];
    const float* w4     = (const float*)d_in[10];
    const float* b4     = (const float*)d_in[11];
    const float* hW     = (const float*)d_in[12];
    const float* hB     = (const float*)d_in[13];
    float* out = (float*)d_out;

    cudaFuncSetAttribute(stage1_k, cudaFuncAttributeMaxDynamicSharedMemorySize, S1_SMEM);
    cudaFuncSetAttribute(stage2_k, cudaFuncAttributeMaxDynamicSharedMemorySize, S2_SMEM);
    cudaFuncSetAttribute(stage3_k, cudaFuncAttributeMaxDynamicSharedMemorySize, S3_SMEM);
    cudaFuncSetAttribute(stage4_k, cudaFuncAttributeMaxDynamicSharedMemorySize, S4_SMEM);

    precompute_k<<<1, 256>>>(w_time, b_time, w_spat, b_spat);
    precompute_w_k<<<(399360 + 255) / 256, 256>>>(w2, w3, w4);
    stage1_k<<<dim3(B_, 6), 384, S1_SMEM>>>(x);
    stage2_k<<<dim3(B_, 2), 256, S2_SMEM>>>(b2);
    stage3_k<<<B_, 256, S3_SMEM>>>(b3);
    stage4_k<<<dim3(128, 2), 256, S4_SMEM>>>(b4);
    head_k<<<B_, 128>>>(sid, hW, hB, out);
}

// round 15
// speedup vs baseline: 1.9805x; 1.0018x over previous
#include <cuda_runtime.h>
#include <cuda_bf16.h>
#include <math.h>
#include <stdint.h>

#define B_ 256

// ---------------- device scratch ----------------
__device__ float g_Weff[25 * 220];
__device__ float g_beff[25];
__device__ uint32_t g_y1p[B_ * 330 * 26];            // TRANSPOSED: [b][pos][ch(25)+pad]
__device__ uint32_t g_y2p[B_ * 50 * 107];
__device__ uint32_t g_y3p[B_ * 100 * 32];
__device__ float g_feat[B_ * 1400];
// weight images (bf16 split)
__device__ __align__(16) uint16_t g_w1h[10 * 32 * 40];
__device__ __align__(16) uint16_t g_w1l[10 * 32 * 40];
__device__ __align__(16) uint16_t g_w2th[10 * 32 * 56];
__device__ __align__(16) uint16_t g_w2tl[10 * 32 * 56];
__device__ __align__(16) uint16_t g_w3h[8 * 128 * 72];
__device__ __align__(16) uint16_t g_w3l[8 * 128 * 72];
__device__ __align__(16) uint16_t g_w4h[16 * 256 * 72];
__device__ __align__(16) uint16_t g_w4l[16 * 256 * 72];

__device__ __forceinline__ float elu1(float x) { return x > 0.f ? x : expm1f(x); }

__device__ __forceinline__ uint32_t smem_u32(const void* p) {
    uint32_t a;
    asm("{ .reg .u64 t; cvta.to.shared.u64 t, %1; cvt.u32.u64 %0, t; }" : "=r"(a) : "l"(p));
    return a;
}
__device__ __forceinline__ void ldsm4(uint32_t* r, uint32_t addr) {
    asm volatile("ldmatrix.sync.aligned.m8n8.x4.shared.b16 {%0,%1,%2,%3}, [%4];"
                 : "=r"(r[0]), "=r"(r[1]), "=r"(r[2]), "=r"(r[3]) : "r"(addr));
}
__device__ __forceinline__ void ldsm4t(uint32_t* r, uint32_t addr) {
    asm volatile("ldmatrix.sync.aligned.m8n8.x4.trans.shared.b16 {%0,%1,%2,%3}, [%4];"
                 : "=r"(r[0]), "=r"(r[1]), "=r"(r[2]), "=r"(r[3]) : "r"(addr));
}
__device__ __forceinline__ void mma16816(float* d, const uint32_t* a, const uint32_t* b) {
    asm volatile("mma.sync.aligned.m16n8k16.row.col.f32.bf16.bf16.f32 "
                 "{%0,%1,%2,%3}, {%4,%5,%6,%7}, {%8,%9}, {%0,%1,%2,%3};"
                 : "+f"(d[0]), "+f"(d[1]), "+f"(d[2]), "+f"(d[3])
                 : "r"(a[0]), "r"(a[1]), "r"(a[2]), "r"(a[3]), "r"(b[0]), "r"(b[1]));
}
__device__ __forceinline__ uint32_t pack_bf16_split(float v) {
    __nv_bfloat16 h = __float2bfloat16(v);
    float hf = __bfloat162float(h);
    __nv_bfloat16 l = __float2bfloat16(v - hf);
    uint16_t hb = reinterpret_cast<uint16_t&>(h);
    uint16_t lb = reinterpret_cast<uint16_t&>(l);
    return (uint32_t)hb | ((uint32_t)lb << 16);
}

// ---------------- kernel 0: fold conv_time into conv_spat ----------------
__global__ void precompute_k(const float* __restrict__ w_time, const float* __restrict__ b_time,
                             const float* __restrict__ w_spat, const float* __restrict__ b_spat)
{
    for (int idx = threadIdx.x; idx < 25 * 220; idx += blockDim.x) {
        int p = idx / 220, rem = idx % 220, c = rem / 10, k = rem % 10;
        float s = 0.f;
        #pragma unroll
        for (int o = 0; o < 25; o++)
            s = fmaf(w_spat[p * 550 + o * 22 + c], w_time[o * 10 + k], s);
        g_Weff[idx] = s;
    }
    if (threadIdx.x < 25) {
        int p = threadIdx.x;
        float s = b_spat[p];
        for (int o = 0; o < 25; o++) {
            float w = 0.f;
            for (int c = 0; c < 22; c++) w += w_spat[p * 550 + o * 22 + c];
            s = fmaf(b_time[o], w, s);
        }
        g_beff[p] = s;
    }
}

// ---------------- kernel 0b: ALL weight images in one launch ----------------
__global__ void precompute_w_k(const float* __restrict__ w2, const float* __restrict__ w3,
                               const float* __restrict__ w4)
{
    int idx = blockIdx.x * 256 + threadIdx.x;
    if (idx < 73728) {
        int ch = idx / 9216, r = idx % 9216, row = r / 72, kloc = r % 72;
        int gk = ch * 64 + kloc;
        float v = (kloc < 64 && row < 100 && gk < 500) ? w3[row * 500 + gk] : 0.f;
        uint32_t p = pack_bf16_split(v);
        g_w3h[idx] = (uint16_t)(p & 0xffff);
        g_w3l[idx] = (uint16_t)(p >> 16);
    } else if (idx < 368640) {
        int i4 = idx - 73728;
        int ch = i4 / 18432, r = i4 % 18432, row = r / 72, kloc = r % 72;
        int gk = ch * 64 + kloc;
        float v = (kloc < 64 && row < 200 && gk < 1000) ? w4[row * 1000 + gk] : 0.f;
        uint32_t p = pack_bf16_split(v);
        g_w4h[i4] = (uint16_t)(p & 0xffff);
        g_w4l[i4] = (uint16_t)(p >> 16);
    } else if (idx < 381440) {
        int i1 = idx - 368640;
        int kk = i1 / 1280, r = i1 % 1280, c = r / 40, o = r % 40;
        float v = (c < 22 && o < 25) ? g_Weff[o * 220 + c * 10 + kk] : 0.f;
        uint32_t p = pack_bf16_split(v);
        g_w1h[i1] = (uint16_t)(p & 0xffff);
        g_w1l[i1] = (uint16_t)(p >> 16);
    } else if (idx < 399360) {
        int i2 = idx - 381440;
        int kk = i2 / 1792, r = i2 % 1792, c = r / 56, o = r % 56;
        float v = (c < 25 && o < 50) ? w2[o * 250 + c * 10 + kk] : 0.f;
        uint32_t p = pack_bf16_split(v);
        g_w2th[i2] = (uint16_t)(p & 0xffff);
        g_w2tl[i2] = (uint16_t)(p >> 16);
    }
}

// ---------------- stage 1 (TENSOR, tap-decomposed): x -> y1pT ----------------
#define S1_AH 0
#define S1_AL 16640
#define S1_WH 33280
#define S1_WL 58880
#define S1_SMEM 84480

__global__ __launch_bounds__(384, 2) void stage1_k(const float* __restrict__ x)
{
    extern __shared__ char smc[];
    const uint32_t sb = smem_u32(smc);
    const int tid = threadIdx.x, wid = tid >> 5, lane = tid & 31;
    const int b = blockIdx.x, tile = blockIdx.y;
    const int m0 = tile * 192;
    __shared__ float bs[25];
    if (tid < 25) bs[tid] = g_beff[tid];

    {
        const float4* srcH = reinterpret_cast<const float4*>(g_w1h);
        const float4* srcL = reinterpret_cast<const float4*>(g_w1l);
        float4* dstH = reinterpret_cast<float4*>(smc + S1_WH);
        float4* dstL = reinterpret_cast<float4*>(smc + S1_WL);
        #pragma unroll 1
        for (int i = tid; i < 1600; i += 384) { dstH[i] = srcH[i]; dstL[i] = srcL[i]; }
    }
    {
        const float* xb = x + b * 22000;
        #pragma unroll 1
        for (int i = tid; i < 4160; i += 384) {
            int cp = i / 208, r = i - cp * 208;
            int t = m0 + r;
            uint32_t h2 = 0u, l2 = 0u;
            if (cp < 11 && t < 1000) {
                uint32_t p0 = pack_bf16_split(__ldg(&xb[(2 * cp) * 1000 + t]));
                uint32_t p1 = pack_bf16_split(__ldg(&xb[(2 * cp + 1) * 1000 + t]));
                h2 = __byte_perm(p0, p1, 0x5410);
                l2 = __byte_perm(p0, p1, 0x7632);
            }
            reinterpret_cast<uint32_t*>(smc + S1_AH)[r * 20 + cp] = h2;
            reinterpret_cast<uint32_t*>(smc + S1_AL)[r * 20 + cp] = l2;
        }
    }
    __syncthreads();

    float d[4][4];
    #pragma unroll
    for (int i = 0; i < 4; i++)
        #pragma unroll
        for (int j = 0; j < 4; j++) d[i][j] = 0.f;

    const uint32_t aOff = ((wid * 16 + ((lane >> 3) & 1) * 8 + (lane & 7)) * 40 + (lane >> 4) * 8) * 2;
    const uint32_t aHb = sb + S1_AH + aOff, aLb = sb + S1_AL + aOff;
    const uint32_t bOff = ((((lane >> 3) & 1) * 8 + (lane & 7)) * 40 + (lane >> 4) * 8) * 2;
    const uint32_t bHb = sb + S1_WH + bOff, bLb = sb + S1_WL + bOff;

    #pragma unroll 1
    for (int kk = 0; kk < 10; kk++) {
        #pragma unroll
        for (int s = 0; s < 2; s++) {
            uint32_t ah[4], al[4];
            ldsm4(ah, aHb + kk * 80 + s * 32);
            ldsm4(al, aLb + kk * 80 + s * 32);
            const uint32_t wb = (uint32_t)kk * 2560 + (uint32_t)s * 1280;
            #pragma unroll
            for (int q = 0; q < 2; q++) {
                uint32_t bh[4], bl[4];
                ldsm4t(bh, bHb + wb + q * 32);
                ldsm4t(bl, bLb + wb + q * 32);
                mma16816(d[2 * q],     ah, bh);
                mma16816(d[2 * q],     al, bh);
                mma16816(d[2 * q],     ah, bl);
                mma16816(d[2 * q + 1], ah, bh + 2);
                mma16816(d[2 * q + 1], al, bh + 2);
                mma16816(d[2 * q + 1], ah, bl + 2);
            }
        }
    }

    __syncthreads();
    float* Dsm = reinterpret_cast<float*>(smc);
    {
        const int mloc = wid * 16 + (lane >> 2);
        const int cb = (lane & 3) * 2;
        #pragma unroll
        for (int q = 0; q < 4; q++) {
            int n = q * 8 + cb;
            Dsm[n * 200 + mloc]           = d[q][0];
            Dsm[(n + 1) * 200 + mloc]     = d[q][1];
            Dsm[n * 200 + mloc + 8]       = d[q][2];
            Dsm[(n + 1) * 200 + mloc + 8] = d[q][3];
        }
    }
    __syncthreads();
    #pragma unroll 1
    for (int i = tid; i < 1664; i += 384) {
        int j = i / 26, o = i - j * 26;
        int tp = tile * 64 + j;
        if (tp < 330) {
            uint32_t pv = 0u;
            if (o < 25) {
                const float* row = Dsm + o * 200 + 3 * j;
                float v = fmaxf(row[0], fmaxf(row[1], row[2])) + bs[o];
                pv = pack_bf16_split(elu1(v));
            }
            g_y1p[b * 8580 + tp * 26 + o] = pv;
        }
    }
}

// ---------------- stage 2 (TENSOR, tap-decomposed, balanced m-split): y1pT -> y2p ----------------
// grid (256, 2). h0: base 0, 11 tiles, p 0..57; h1: base 174, 10 tiles, p 58..106.
// A 192 rows x 40 u16; W resident [10][32][56]. 2 CTAs/SM.
#define S2_AH 0
#define S2_AL 15360
#define S2_WH 30720
#define S2_WL 66560
#define S2_SMEM 102400

__global__ __launch_bounds__(256, 2) void stage2_k(const float* __restrict__ b2)
{
    extern __shared__ char smc[];
    const uint32_t sb = smem_u32(smc);
    const int tid = threadIdx.x, wid = tid >> 5, lane = tid & 31;
    const int b = blockIdx.x, h = blockIdx.y;
    const int base = h ? 174 : 0;
    __shared__ float bs[50];
    if (tid < 50) bs[tid] = __ldg(&b2[tid]);

    {
        const float4* srcH = reinterpret_cast<const float4*>(g_w2th);
        const float4* srcL = reinterpret_cast<const float4*>(g_w2tl);
        float4* dstH = reinterpret_cast<float4*>(smc + S2_WH);
        float4* dstL = reinterpret_cast<float4*>(smc + S2_WL);
        #pragma unroll 1
        for (int i = tid; i < 2240; i += 256) { dstH[i] = srcH[i]; dstL[i] = srcL[i]; }
    }
    {
        const uint32_t* yb = g_y1p + b * 8580;
        #pragma unroll 1
        for (int i = tid; i < 3072; i += 256) {
            int r = i >> 4, cp = i & 15;
            int gp = base + r;
            uint32_t h2 = 0u, l2 = 0u;
            if (gp < 330 && cp < 13) {
                uint32_t p0 = __ldg(&yb[gp * 26 + 2 * cp]);
                uint32_t p1 = __ldg(&yb[gp * 26 + 2 * cp + 1]);
                h2 = __byte_perm(p0, p1, 0x5410);
                l2 = __byte_perm(p0, p1, 0x7632);
            }
            *reinterpret_cast<uint32_t*>(smc + S2_AH + r * 80 + cp * 4) = h2;
            *reinterpret_cast<uint32_t*>(smc + S2_AL + r * 80 + cp * 4) = l2;
        }
    }
    __syncthreads();

    float d[2][7][4];
    #pragma unroll
    for (int m = 0; m < 2; m++)
        #pragma unroll
        for (int q = 0; q < 7; q++)
            #pragma unroll
            for (int j = 0; j < 4; j++) d[m][q][j] = 0.f;

    const uint32_t aLane = ((((lane >> 3) & 1) * 8 + (lane & 7)) * 40 + (lane >> 4) * 8) * 2;
    const uint32_t bLane = ((((lane >> 3) & 1) * 8 + (lane & 7)) * 56 + (lane >> 4) * 8) * 2;
    const int ndouble = h ? 2 : 3;            // warps with a 2nd m-tile
    const bool has2 = (wid < ndouble);

    #pragma unroll 1
    for (int kk = 0; kk < 10; kk++) {
        #pragma unroll
        for (int g = 0; g < 2; g++) {
            // A fragments FIRST (both tiles) — their latency hides under B issue
            uint32_t ah0[4], al0[4], ah1[4], al1[4];
            {
                const uint32_t arow0 = (uint32_t)(wid * 16 + kk) * 80 + (uint32_t)g * 32;
                ldsm4(ah0, sb + S2_AH + arow0 + aLane);
                ldsm4(al0, sb + S2_AL + arow0 + aLane);
            }
            if (has2) {
                const uint32_t arow1 = (uint32_t)((wid + 8) * 16 + kk) * 80 + (uint32_t)g * 32;
                ldsm4(ah1, sb + S2_AH + arow1 + aLane);
                ldsm4(al1, sb + S2_AL + arow1 + aLane);
            }
            // B fragments
            uint32_t bh[4][4], bl[4][4];
            const uint32_t wb = sb + (uint32_t)kk * 3584 + (uint32_t)g * (16 * 112) + bLane;
            #pragma unroll
            for (int q = 0; q < 4; q++) {
                ldsm4t(bh[q], S2_WH + wb + q * 32);
                ldsm4t(bl[q], S2_WL + wb + q * 32);
            }
            // MMAs tile 0
            #pragma unroll
            for (int q = 0; q < 3; q++) {
                mma16816(d[0][2 * q],     ah0, bh[q]);
                mma16816(d[0][2 * q],     al0, bh[q]);
                mma16816(d[0][2 * q],     ah0, bl[q]);
                mma16816(d[0][2 * q + 1], ah0, bh[q] + 2);
                mma16816(d[0][2 * q + 1], al0, bh[q] + 2);
                mma16816(d[0][2 * q + 1], ah0, bl[q] + 2);
            }
            mma16816(d[0][6], ah0, bh[3]);
            mma16816(d[0][6], al0, bh[3]);
            mma16816(d[0][6], ah0, bl[3]);
            // MMAs tile 1
            if (has2) {
                #pragma unroll
                for (int q = 0; q < 3; q++) {
                    mma16816(d[1][2 * q],     ah1, bh[q]);
                    mma16816(d[1][2 * q],     al1, bh[q]);
                    mma16816(d[1][2 * q],     ah1, bl[q]);
                    mma16816(d[1][2 * q + 1], ah1, bh[q] + 2);
                    mma16816(d[1][2 * q + 1], al1, bh[q] + 2);
                    mma16816(d[1][2 * q + 1], ah1, bl[q] + 2);
                }
                mma16816(d[1][6], ah1, bh[3]);
                mma16816(d[1][6], al1, bh[3]);
                mma16816(d[1][6], ah1, bl[3]);
            }
        }
    }

    __syncthreads();
    float* Dsm = reinterpret_cast<float*>(smc);
    {
        const int r0 = (lane >> 2);
        const int cb = (lane & 3) * 2;
        #pragma unroll
        for (int mt = 0; mt < 2; mt++) {
            if (mt == 1 && !has2) break;
            const int rr = (wid + mt * 8) * 16 + r0;
            #pragma unroll
            for (int q = 0; q < 7; q++) {
                int n = q * 8 + cb;
                Dsm[rr * 56 + n]           = d[mt][q][0];
                Dsm[rr * 56 + n + 1]       = d[mt][q][1];
                Dsm[(rr + 8) * 56 + n]     = d[mt][q][2];
                Dsm[(rr + 8) * 56 + n + 1] = d[mt][q][3];
            }
        }
    }
    __syncthreads();
    const int np = h ? 49 : 58;
    const int pb = h ? 58 : 0;
    const int cnt = 50 * np;
    #pragma unroll 1
    for (int i = tid; i < cnt; i += 256) {
        int o = i / np, j = i - o * np;
        int p = pb + j;
        int ml = 3 * p - base;
        const float* c0 = Dsm + ml * 56 + o;
        float v = fmaxf(c0[0], fmaxf(c0[56], c0[112])) + bs[o];
        g_y2p[b * 5350 + o * 107 + p] = pack_bf16_split(elu1(v));
    }
}

// ---------------- stage 3 (TENSOR, 1 sample/CTA, 64-k chunks): y2p -> y3p ----------------
#define S3_AH 0
#define S3_AL 18432
#define S3_BH 36864
#define S3_BL 50176
#define S3_SMEM 63488

__global__ __launch_bounds__(256, 2) void stage3_k(const float* __restrict__ b3)
{
    extern __shared__ char smc[];
    const uint32_t sb = smem_u32(smc);
    const int tid = threadIdx.x, wid = tid >> 5, lane = tid & 31;
    const int b = blockIdx.x;
    __shared__ float bs[100];
    if (tid < 100) bs[tid] = __ldg(&b3[tid]);

    float d[12][4];
    #pragma unroll
    for (int i = 0; i < 12; i++)
        #pragma unroll
        for (int j = 0; j < 4; j++) d[i][j] = 0.f;

    const uint32_t aOff = ((wid * 16 + ((lane >> 3) & 1) * 8 + (lane & 7)) * 72 + (lane >> 4) * 8) * 2;
    const uint32_t bOff = ((((lane >> 3) & 1) * 8 + (lane & 7)) * 104 + (lane >> 4) * 8) * 2;
    const uint32_t aH = sb + S3_AH + aOff, aL = sb + S3_AL + aOff;
    const uint32_t bHb = sb + S3_BH + bOff, bLb = sb + S3_BL + bOff;

    const int kloc = tid >> 2, seg = tid & 3;
    uint16_t* bhRow = reinterpret_cast<uint16_t*>(smc + S3_BH) + kloc * 104 + seg * 24;
    uint16_t* blRow = reinterpret_cast<uint16_t*>(smc + S3_BL) + kloc * 104 + seg * 24;

    #pragma unroll 1
    for (int ch = 0; ch < 8; ch++) {
        __syncthreads();
        {
            const float4* srcH = reinterpret_cast<const float4*>(g_w3h + ch * 9216);
            const float4* srcL = reinterpret_cast<const float4*>(g_w3l + ch * 9216);
            float4* dstH = reinterpret_cast<float4*>(smc + S3_AH);
            float4* dstL = reinterpret_cast<float4*>(smc + S3_AL);
            #pragma unroll 1
            for (int i = tid; i < 1152; i += 256) { dstH[i] = srcH[i]; dstL[i] = srcL[i]; }
        }
        {
            const int gk = ch * 64 + kloc;
            if (gk < 500) {
                const int c = gk / 10, kk = gk - c * 10;
                const uint32_t* src = g_y2p + b * 5350 + c * 107 + kk + seg * 24;
                #pragma unroll
                for (int j = 0; j < 24; j += 2) {
                    uint32_t q0 = __ldg(&src[j]);
                    uint32_t q1 = __ldg(&src[j + 1]);
                    *reinterpret_cast<uint32_t*>(bhRow + j) = __byte_perm(q0, q1, 0x5410);
                    *reinterpret_cast<uint32_t*>(blRow + j) = __byte_perm(q0, q1, 0x7632);
                }
            } else {
                #pragma unroll
                for (int j = 0; j < 24; j += 2) {
                    *reinterpret_cast<uint32_t*>(bhRow + j) = 0u;
                    *reinterpret_cast<uint32_t*>(blRow + j) = 0u;
                }
            }
        }
        __syncthreads();

        #pragma unroll
        for (int t = 0; t < 4; t++) {
            uint32_t ah[4], al[4];
            ldsm4(ah, aH + t * 32);
            ldsm4(al, aL + t * 32);
            const uint32_t bt = (uint32_t)t * 3328;
            #pragma unroll
            for (int q = 0; q < 6; q++) {
                uint32_t bh[4], bl[4];
                ldsm4t(bh, bHb + bt + q * 32);
                ldsm4t(bl, bLb + bt + q * 32);
                mma16816(d[2 * q],     ah, bh);
                mma16816(d[2 * q],     al, bh);
                mma16816(d[2 * q],     ah, bl);
                mma16816(d[2 * q + 1], ah, bh + 2);
                mma16816(d[2 * q + 1], al, bh + 2);
                mma16816(d[2 * q + 1], ah, bl + 2);
            }
        }
    }

    __syncthreads();
    float* Dsm = reinterpret_cast<float*>(smc);
    {
        const int r0 = wid * 16 + (lane >> 2);
        const int cb = (lane & 3) * 2;
        #pragma unroll
        for (int q = 0; q < 12; q++) {
            int n = q * 8 + cb;
            Dsm[r0 * 100 + n]           = d[q][0];
            Dsm[r0 * 100 + n + 1]       = d[q][1];
            Dsm[(r0 + 8) * 100 + n]     = d[q][2];
            Dsm[(r0 + 8) * 100 + n + 1] = d[q][3];
        }
    }
    __syncthreads();
    #pragma unroll 1
    for (int i = tid; i < 3200; i += 256) {
        int o = i >> 5, t = i & 31;
        const float* c0 = Dsm + o * 100 + 3 * t;
        float v = fmaxf(c0[0], fmaxf(c0[1], c0[2])) + bs[o];
        g_y3p[b * 3200 + o * 32 + t] = pack_bf16_split(elu1(v));
    }
}

// ---------------- stage 4 (TENSOR, m-split, 64-k chunks): y3p -> feat ----------------
#define S4_AH 0
#define S4_AL 18432
#define S4_BH 36864
#define S4_BL 44032
#define S4_SMEM 51200

__global__ __launch_bounds__(256, 3) void stage4_k(const float* __restrict__ b4)
{
    extern __shared__ char smc[];
    const uint32_t sb = smem_u32(smc);
    const int tid = threadIdx.x, wid = tid >> 5, lane = tid & 31;
    const int s0 = blockIdx.x * 2, h = blockIdx.y;
    const int nrow = h ? 72 : 128;
    __shared__ float bs[128];
    if (tid < 128) bs[tid] = (h * 128 + tid < 200) ? __ldg(&b4[h * 128 + tid]) : 0.f;

    {
        uint16_t* bhB = reinterpret_cast<uint16_t*>(smc + S4_BH);
        uint16_t* blB = reinterpret_cast<uint16_t*>(smc + S4_BL);
        for (int i = tid; i < 512; i += 256) {
            int r = i >> 3, c = 48 + (i & 7);
            bhB[r * 56 + c] = 0;
            blB[r * 56 + c] = 0;
        }
    }

    float d[6][4];
    #pragma unroll
    for (int i = 0; i < 6; i++)
        #pragma unroll
        for (int j = 0; j < 4; j++) d[i][j] = 0.f;

    const uint32_t aOff = ((wid * 16 + ((lane >> 3) & 1) * 8 + (lane & 7)) * 72 + (lane >> 4) * 8) * 2;
    const uint32_t bOff = ((((lane >> 3) & 1) * 8 + (lane & 7)) * 56 + (lane >> 4) * 8) * 2;
    const uint32_t aH = sb + S4_AH + aOff, aL = sb + S4_AL + aOff;
    const uint32_t bHb = sb + S4_BH + bOff, bLb = sb + S4_BL + bOff;

    const int kloc = tid >> 2, q4 = tid & 3;
    const int segq = q4 >> 1, jb = (q4 & 1) * 12;
    uint16_t* bhRow = reinterpret_cast<uint16_t*>(smc + S4_BH) + kloc * 56 + segq * 24 + jb;
    uint16_t* blRow = reinterpret_cast<uint16_t*>(smc + S4_BL) + kloc * 56 + segq * 24 + jb;

    #pragma unroll 1
    for (int ch = 0; ch < 16; ch++) {
        __syncthreads();
        {
            const float4* srcH = reinterpret_cast<const float4*>(g_w4h + ch * 18432 + h * 9216);
            const float4* srcL = reinterpret_cast<const float4*>(g_w4l + ch * 18432 + h * 9216);
            float4* dstH = reinterpret_cast<float4*>(smc + S4_AH);
            float4* dstL = reinterpret_cast<float4*>(smc + S4_AL);
            #pragma unroll 1
            for (int i = tid; i < 1152; i += 256) { dstH[i] = srcH[i]; dstL[i] = srcL[i]; }
        }
        {
            const int gk = ch * 64 + kloc;
            if (gk < 1000) {
                const int c = gk / 10, kk = gk - c * 10;
                const uint32_t* src = g_y3p + (s0 + segq) * 3200 + c * 32 + kk + jb;
                #pragma unroll
                for (int j = 0; j < 12; j += 2) {
                    int gp = jb + j;
                    uint32_t q0 = (gp < 21)     ? __ldg(&src[j])     : 0u;
                    uint32_t q1 = (gp + 1 < 21) ? __ldg(&src[j + 1]) : 0u;
                    *reinterpret_cast<uint32_t*>(bhRow + j) = __byte_perm(q0, q1, 0x5410);
                    *reinterpret_cast<uint32_t*>(blRow + j) = __byte_perm(q0, q1, 0x7632);
                }
            } else {
                #pragma unroll
                for (int j = 0; j < 12; j += 2) {
                    *reinterpret_cast<uint32_t*>(bhRow + j) = 0u;
                    *reinterpret_cast<uint32_t*>(blRow + j) = 0u;
                }
            }
        }
        __syncthreads();

        #pragma unroll
        for (int t = 0; t < 4; t++) {
            uint32_t ah[4], al[4];
            ldsm4(ah, aH + t * 32);
            ldsm4(al, aL + t * 32);
            const uint32_t bt = (uint32_t)t * 1792;
            #pragma unroll
            for (int q = 0; q < 3; q++) {
                uint32_t bh[4], bl[4];
                ldsm4t(bh, bHb + bt + q * 32);
                ldsm4t(bl, bLb + bt + q * 32);
                mma16816(d[2 * q],     ah, bh);
                mma16816(d[2 * q],     al, bh);
                mma16816(d[2 * q],     ah, bl);
                mma16816(d[2 * q + 1], ah, bh + 2);
                mma16816(d[2 * q + 1], al, bh + 2);
                mma16816(d[2 * q + 1], ah, bl + 2);
            }
        }
    }

    __syncthreads();
    float* Dsm = reinterpret_cast<float*>(smc);
    {
        const int r0 = wid * 16 + (lane >> 2);
        const int cb = (lane & 3) * 2;
        #pragma unroll
        for (int q = 0; q < 6; q++) {
            int n = q * 8 + cb;
            Dsm[r0 * 56 + n]           = d[q][0];
            Dsm[r0 * 56 + n + 1]       = d[q][1];
            Dsm[(r0 + 8) * 56 + n]     = d[q][2];
            Dsm[(r0 + 8) * 56 + n + 1] = d[q][3];
        }
    }
    __syncthreads();
    const int cnt = nrow * 14;
    #pragma unroll 1
    for (int i = tid; i < cnt; i += 256) {
        int ol = i / 14, r = i - ol * 14, s = r / 7, t = r - s * 7;
        int n = s * 24 + 3 * t;
        float v = fmaxf(Dsm[ol * 56 + n], fmaxf(Dsm[ol * 56 + n + 1], Dsm[ol * 56 + n + 2]))
                  + bs[ol];
        g_feat[(s0 + s) * 1400 + (h * 128 + ol) * 7 + t] = elu1(v);
    }
}

// ---------------- head ----------------
__global__ void head_k(const int* __restrict__ sid, const float* __restrict__ hW,
                       const float* __restrict__ hB, float* __restrict__ out)
{
    const int b = blockIdx.x;
    const int s = sid[b];
    const float* f = g_feat + b * 1400;
    const float* W = hW + s * (4 * 1400);
    float acc[4] = {0.f, 0.f, 0.f, 0.f};
    for (int i = threadIdx.x; i < 1400; i += blockDim.x) {
        float fv = f[i];
        #pragma unroll
        for (int o = 0; o < 4; o++) acc[o] = fmaf(fv, __ldg(&W[o * 1400 + i]), acc[o]);
    }
    #pragma unroll
    for (int off = 16; off > 0; off >>= 1) {
        #pragma unroll
        for (int o = 0; o < 4; o++) acc[o] += __shfl_down_sync(0xFFFFFFFFu, acc[o], off);
    }
    __shared__ float red[4][4];
    const int w = threadIdx.x >> 5, l = threadIdx.x & 31;
    if (l == 0) {
        #pragma unroll
        for (int o = 0; o < 4; o++) red[o][w] = acc[o];
    }
    __syncthreads();
    if (threadIdx.x < 4) {
        int o = threadIdx.x;
        out[b * 4 + o] = red[o][0] + red[o][1] + red[o][2] + red[o][3] + __ldg(&hB[s * 4 + o]);
    }
}

// ---------------- launch ----------------
extern "C" void kernel_launch(void* const* d_in, const int* in_sizes, int n_in,
                              void* d_out, int out_size)
{
    const float* x      = (const float*)d_in[0];
    const int*   sid    = (const int*)  d_in[1];
    const float* w_time = (const float*)d_in[2];
    const float* b_time = (const float*)d_in[3];
    const float* w_spat = (const float*)d_in[4];
    const float* b_spat = (const float*)d_in[5];
    const float* w2     = (const float*)d_in[6];
    const float* b2     = (const float*)d_in[7];
    const float* w3     = (const float*)d_in[8];
    const float* b3     = (const float*)d_in[9];
    const float* w4     = (const float*)d_in[10];
    const float* b4     = (const float*)d_in[11];
    const float* hW     = (const float*)d_in[12];
    const float* hB     = (const float*)d_in[13];
    float* out = (float*)d_out;

    cudaFuncSetAttribute(stage1_k, cudaFuncAttributeMaxDynamicSharedMemorySize, S1_SMEM);
    cudaFuncSetAttribute(stage2_k, cudaFuncAttributeMaxDynamicSharedMemorySize, S2_SMEM);
    cudaFuncSetAttribute(stage3_k, cudaFuncAttributeMaxDynamicSharedMemorySize, S3_SMEM);
    cudaFuncSetAttribute(stage4_k, cudaFuncAttributeMaxDynamicSharedMemorySize, S4_SMEM);

    precompute_k<<<1, 256>>>(w_time, b_time, w_spat, b_spat);
    precompute_w_k<<<(399360 + 255) / 256, 256>>>(w2, w3, w4);
    stage1_k<<<dim3(B_, 6), 384, S1_SMEM>>>(x);
    stage2_k<<<dim3(B_, 2), 256, S2_SMEM>>>(b2);
    stage3_k<<<B_, 256, S3_SMEM>>>(b3);
    stage4_k<<<dim3(128, 2), 256, S4_SMEM>>>(b4);
    head_k<<<B_, 128>>>(sid, hW, hB, out);
}

// round 16
// speedup vs baseline: 2.1145x; 1.0677x over previous
#include <cuda_runtime.h>
#include <cuda_bf16.h>
#include <math.h>
#include <stdint.h>

#define B_ 256

// ---------------- device scratch ----------------
__device__ float g_beff[25];
__device__ uint32_t g_xp[B_ * 22000];                // packed x bf16 h|l<<16
__device__ uint32_t g_y1p[B_ * 330 * 26];            // TRANSPOSED: [b][pos][ch(25)+pad]
__device__ uint32_t g_y2p[B_ * 50 * 107];
__device__ uint32_t g_y3p[B_ * 100 * 32];
__device__ float g_feat[B_ * 1400];
__device__ __align__(16) uint16_t g_w1h[10 * 32 * 40];
__device__ __align__(16) uint16_t g_w1l[10 * 32 * 40];
__device__ __align__(16) uint16_t g_w2th[10 * 32 * 56];
__device__ __align__(16) uint16_t g_w2tl[10 * 32 * 56];
__device__ __align__(16) uint16_t g_w3h[8 * 128 * 72];
__device__ __align__(16) uint16_t g_w3l[8 * 128 * 72];
__device__ __align__(16) uint16_t g_w4h[16 * 256 * 72];
__device__ __align__(16) uint16_t g_w4l[16 * 256 * 72];

__device__ __forceinline__ float elu1(float x) { return x > 0.f ? x : expm1f(x); }

__device__ __forceinline__ uint32_t smem_u32(const void* p) {
    uint32_t a;
    asm("{ .reg .u64 t; cvta.to.shared.u64 t, %1; cvt.u32.u64 %0, t; }" : "=r"(a) : "l"(p));
    return a;
}
__device__ __forceinline__ void cpa16(uint32_t dst, const void* src) {
    asm volatile("cp.async.cg.shared.global [%0], [%1], 16;" :: "r"(dst), "l"(src));
}
#define CP_COMMIT() asm volatile("cp.async.commit_group;" ::: "memory")
#define CP_WAIT0()  asm volatile("cp.async.wait_group 0;" ::: "memory")
__device__ __forceinline__ void ldsm4(uint32_t* r, uint32_t addr) {
    asm volatile("ldmatrix.sync.aligned.m8n8.x4.shared.b16 {%0,%1,%2,%3}, [%4];"
                 : "=r"(r[0]), "=r"(r[1]), "=r"(r[2]), "=r"(r[3]) : "r"(addr));
}
__device__ __forceinline__ void ldsm4t(uint32_t* r, uint32_t addr) {
    asm volatile("ldmatrix.sync.aligned.m8n8.x4.trans.shared.b16 {%0,%1,%2,%3}, [%4];"
                 : "=r"(r[0]), "=r"(r[1]), "=r"(r[2]), "=r"(r[3]) : "r"(addr));
}
__device__ __forceinline__ void mma16816(float* d, const uint32_t* a, const uint32_t* b) {
    asm volatile("mma.sync.aligned.m16n8k16.row.col.f32.bf16.bf16.f32 "
                 "{%0,%1,%2,%3}, {%4,%5,%6,%7}, {%8,%9}, {%0,%1,%2,%3};"
                 : "+f"(d[0]), "+f"(d[1]), "+f"(d[2]), "+f"(d[3])
                 : "r"(a[0]), "r"(a[1]), "r"(a[2]), "r"(a[3]), "r"(b[0]), "r"(b[1]));
}
__device__ __forceinline__ uint32_t pack_bf16_split(float v) {
    __nv_bfloat16 h = __float2bfloat16(v);
    float hf = __bfloat162float(h);
    __nv_bfloat16 l = __float2bfloat16(v - hf);
    uint16_t hb = reinterpret_cast<uint16_t&>(h);
    uint16_t lb = reinterpret_cast<uint16_t&>(l);
    return (uint32_t)hb | ((uint32_t)lb << 16);
}

// ---------------- kernel 0 (merged): x-pack + ALL weight images + beff ----------------
#define PW_X   (B_ * 22000)           // 5,632,000
#define PW_W3  (PW_X + 73728)
#define PW_W4  (PW_W3 + 294912)
#define PW_W1  (PW_W4 + 12800)
#define PW_W2  (PW_W1 + 17920)
#define PW_BE  (PW_W2 + 25)
__global__ void precompute_all_k(const float* __restrict__ x,
                                 const float* __restrict__ w_time, const float* __restrict__ b_time,
                                 const float* __restrict__ w_spat, const float* __restrict__ b_spat,
                                 const float* __restrict__ w2, const float* __restrict__ w3,
                                 const float* __restrict__ w4)
{
    int idx = blockIdx.x * 256 + threadIdx.x;
    if (idx < PW_X) {
        g_xp[idx] = pack_bf16_split(__ldg(&x[idx]));
    } else if (idx < PW_W3) {
        int i3 = idx - PW_X;
        int ch = i3 / 9216, r = i3 % 9216, row = r / 72, kloc = r % 72;
        int gk = ch * 64 + kloc;
        float v = (kloc < 64 && row < 100 && gk < 500) ? w3[row * 500 + gk] : 0.f;
        uint32_t p = pack_bf16_split(v);
        g_w3h[i3] = (uint16_t)(p & 0xffff);
        g_w3l[i3] = (uint16_t)(p >> 16);
    } else if (idx < PW_W4) {
        int i4 = idx - PW_W3;
        int ch = i4 / 18432, r = i4 % 18432, row = r / 72, kloc = r % 72;
        int gk = ch * 64 + kloc;
        float v = (kloc < 64 && row < 200 && gk < 1000) ? w4[row * 1000 + gk] : 0.f;
        uint32_t p = pack_bf16_split(v);
        g_w4h[i4] = (uint16_t)(p & 0xffff);
        g_w4l[i4] = (uint16_t)(p >> 16);
    } else if (idx < PW_W1) {
        int i1 = idx - PW_W4;
        int kk = i1 / 1280, r = i1 % 1280, c = r / 40, o = r % 40;
        float v = 0.f;
        if (c < 22 && o < 25) {
            #pragma unroll
            for (int oo = 0; oo < 25; oo++)
                v = fmaf(w_spat[o * 550 + oo * 22 + c], w_time[oo * 10 + kk], v);
        }
        uint32_t p = pack_bf16_split(v);
        g_w1h[i1] = (uint16_t)(p & 0xffff);
        g_w1l[i1] = (uint16_t)(p >> 16);
    } else if (idx < PW_W2) {
        int i2 = idx - PW_W1;
        int kk = i2 / 1792, r = i2 % 1792, c = r / 56, o = r % 56;
        float v = (c < 25 && o < 50) ? w2[o * 250 + c * 10 + kk] : 0.f;
        uint32_t p = pack_bf16_split(v);
        g_w2th[i2] = (uint16_t)(p & 0xffff);
        g_w2tl[i2] = (uint16_t)(p >> 16);
    } else if (idx < PW_BE) {
        int p = idx - PW_W2;
        float s = b_spat[p];
        for (int oo = 0; oo < 25; oo++) {
            float w = 0.f;
            for (int c = 0; c < 22; c++) w += w_spat[p * 550 + oo * 22 + c];
            s = fmaf(b_time[oo], w, s);
        }
        g_beff[p] = s;
    }
}

// ---------------- stage 1 (TENSOR, tap-decomposed): g_xp -> y1pT ----------------
#define S1_AH 0
#define S1_AL 16640
#define S1_WH 33280
#define S1_WL 58880
#define S1_SMEM 84480

__global__ __launch_bounds__(384, 2) void stage1_k()
{
    extern __shared__ char smc[];
    const uint32_t sb = smem_u32(smc);
    const int tid = threadIdx.x, wid = tid >> 5, lane = tid & 31;
    const int b = blockIdx.x, tile = blockIdx.y;
    const int m0 = tile * 192;
    __shared__ float bs[25];
    if (tid < 25) bs[tid] = g_beff[tid];

    // W fill async
    {
        const float4* srcH = reinterpret_cast<const float4*>(g_w1h);
        const float4* srcL = reinterpret_cast<const float4*>(g_w1l);
        for (int i = tid; i < 1600; i += 384) {
            cpa16(sb + S1_WH + i * 16, srcH + i);
            cpa16(sb + S1_WL + i * 16, srcL + i);
        }
        CP_COMMIT();
    }
    // A fill from packed x
    {
        const uint32_t* xb = g_xp + b * 22000;
        #pragma unroll 2
        for (int i = tid; i < 4160; i += 384) {
            int cp = i / 208, r = i - cp * 208;
            int t = m0 + r;
            uint32_t h2 = 0u, l2 = 0u;
            if (cp < 11 && t < 1000) {
                uint32_t p0 = __ldg(&xb[(2 * cp) * 1000 + t]);
                uint32_t p1 = __ldg(&xb[(2 * cp + 1) * 1000 + t]);
                h2 = __byte_perm(p0, p1, 0x5410);
                l2 = __byte_perm(p0, p1, 0x7632);
            }
            reinterpret_cast<uint32_t*>(smc + S1_AH)[r * 20 + cp] = h2;
            reinterpret_cast<uint32_t*>(smc + S1_AL)[r * 20 + cp] = l2;
        }
    }
    CP_WAIT0();
    __syncthreads();

    float d[4][4];
    #pragma unroll
    for (int i = 0; i < 4; i++)
        #pragma unroll
        for (int j = 0; j < 4; j++) d[i][j] = 0.f;

    const uint32_t aOff = ((wid * 16 + ((lane >> 3) & 1) * 8 + (lane & 7)) * 40 + (lane >> 4) * 8) * 2;
    const uint32_t aHb = sb + S1_AH + aOff, aLb = sb + S1_AL + aOff;
    const uint32_t bOff = ((((lane >> 3) & 1) * 8 + (lane & 7)) * 40 + (lane >> 4) * 8) * 2;
    const uint32_t bHb = sb + S1_WH + bOff, bLb = sb + S1_WL + bOff;

    #pragma unroll 1
    for (int kk = 0; kk < 10; kk++) {
        #pragma unroll
        for (int s = 0; s < 2; s++) {
            uint32_t ah[4], al[4];
            ldsm4(ah, aHb + kk * 80 + s * 32);
            ldsm4(al, aLb + kk * 80 + s * 32);
            const uint32_t wb = (uint32_t)kk * 2560 + (uint32_t)s * 1280;
            #pragma unroll
            for (int q = 0; q < 2; q++) {
                uint32_t bh[4], bl[4];
                ldsm4t(bh, bHb + wb + q * 32);
                ldsm4t(bl, bLb + wb + q * 32);
                mma16816(d[2 * q],     ah, bh);
                mma16816(d[2 * q],     al, bh);
                mma16816(d[2 * q],     ah, bl);
                mma16816(d[2 * q + 1], ah, bh + 2);
                mma16816(d[2 * q + 1], al, bh + 2);
                mma16816(d[2 * q + 1], ah, bl + 2);
            }
        }
    }

    __syncthreads();
    float* Dsm = reinterpret_cast<float*>(smc);
    {
        const int mloc = wid * 16 + (lane >> 2);
        const int cb = (lane & 3) * 2;
        #pragma unroll
        for (int q = 0; q < 4; q++) {
            int n = q * 8 + cb;
            Dsm[n * 200 + mloc]           = d[q][0];
            Dsm[(n + 1) * 200 + mloc]     = d[q][1];
            Dsm[n * 200 + mloc + 8]       = d[q][2];
            Dsm[(n + 1) * 200 + mloc + 8] = d[q][3];
        }
    }
    __syncthreads();
    #pragma unroll 1
    for (int i = tid; i < 1664; i += 384) {
        int j = i / 26, o = i - j * 26;
        int tp = tile * 64 + j;
        if (tp < 330) {
            uint32_t pv = 0u;
            if (o < 25) {
                const float* row = Dsm + o * 200 + 3 * j;
                float v = fmaxf(row[0], fmaxf(row[1], row[2])) + bs[o];
                pv = pack_bf16_split(elu1(v));
            }
            g_y1p[b * 8580 + tp * 26 + o] = pv;
        }
    }
}

// ---------------- stage 2 (TENSOR, tap-decomposed, balanced m-split): y1pT -> y2p ----------------
#define S2_AH 0
#define S2_AL 15360
#define S2_WH 30720
#define S2_WL 66560
#define S2_SMEM 102400

__global__ __launch_bounds__(256, 2) void stage2_k(const float* __restrict__ b2)
{
    extern __shared__ char smc[];
    const uint32_t sb = smem_u32(smc);
    const int tid = threadIdx.x, wid = tid >> 5, lane = tid & 31;
    const int b = blockIdx.x, h = blockIdx.y;
    const int base = h ? 174 : 0;
    __shared__ float bs[50];
    if (tid < 50) bs[tid] = __ldg(&b2[tid]);

    // W fill async
    {
        const float4* srcH = reinterpret_cast<const float4*>(g_w2th);
        const float4* srcL = reinterpret_cast<const float4*>(g_w2tl);
        for (int i = tid; i < 2240; i += 256) {
            cpa16(sb + S2_WH + i * 16, srcH + i);
            cpa16(sb + S2_WL + i * 16, srcL + i);
        }
        CP_COMMIT();
    }
    // A fill (gather)
    {
        const uint32_t* yb = g_y1p + b * 8580;
        #pragma unroll 2
        for (int i = tid; i < 3072; i += 256) {
            int r = i >> 4, cp = i & 15;
            int gp = base + r;
            uint32_t h2 = 0u, l2 = 0u;
            if (gp < 330 && cp < 13) {
                uint32_t p0 = __ldg(&yb[gp * 26 + 2 * cp]);
                uint32_t p1 = __ldg(&yb[gp * 26 + 2 * cp + 1]);
                h2 = __byte_perm(p0, p1, 0x5410);
                l2 = __byte_perm(p0, p1, 0x7632);
            }
            *reinterpret_cast<uint32_t*>(smc + S2_AH + r * 80 + cp * 4) = h2;
            *reinterpret_cast<uint32_t*>(smc + S2_AL + r * 80 + cp * 4) = l2;
        }
    }
    CP_WAIT0();
    __syncthreads();

    float d[2][7][4];
    #pragma unroll
    for (int m = 0; m < 2; m++)
        #pragma unroll
        for (int q = 0; q < 7; q++)
            #pragma unroll
            for (int j = 0; j < 4; j++) d[m][q][j] = 0.f;

    const uint32_t aLane = ((((lane >> 3) & 1) * 8 + (lane & 7)) * 40 + (lane >> 4) * 8) * 2;
    const uint32_t bLane = ((((lane >> 3) & 1) * 8 + (lane & 7)) * 56 + (lane >> 4) * 8) * 2;
    const int ndouble = h ? 2 : 3;
    const bool has2 = (wid < ndouble);

    #pragma unroll 1
    for (int kk = 0; kk < 10; kk++) {
        #pragma unroll
        for (int g = 0; g < 2; g++) {
            uint32_t ah0[4], al0[4], ah1[4], al1[4];
            {
                const uint32_t arow0 = (uint32_t)(wid * 16 + kk) * 80 + (uint32_t)g * 32;
                ldsm4(ah0, sb + S2_AH + arow0 + aLane);
                ldsm4(al0, sb + S2_AL + arow0 + aLane);
            }
            if (has2) {
                const uint32_t arow1 = (uint32_t)((wid + 8) * 16 + kk) * 80 + (uint32_t)g * 32;
                ldsm4(ah1, sb + S2_AH + arow1 + aLane);
                ldsm4(al1, sb + S2_AL + arow1 + aLane);
            }
            uint32_t bh[4][4], bl[4][4];
            const uint32_t wb = sb + (uint32_t)kk * 3584 + (uint32_t)g * (16 * 112) + bLane;
            #pragma unroll
            for (int q = 0; q < 4; q++) {
                ldsm4t(bh[q], S2_WH + wb + q * 32);
                ldsm4t(bl[q], S2_WL + wb + q * 32);
            }
            #pragma unroll
            for (int q = 0; q < 3; q++) {
                mma16816(d[0][2 * q],     ah0, bh[q]);
                mma16816(d[0][2 * q],     al0, bh[q]);
                mma16816(d[0][2 * q],     ah0, bl[q]);
                mma16816(d[0][2 * q + 1], ah0, bh[q] + 2);
                mma16816(d[0][2 * q + 1], al0, bh[q] + 2);
                mma16816(d[0][2 * q + 1], ah0, bl[q] + 2);
            }
            mma16816(d[0][6], ah0, bh[3]);
            mma16816(d[0][6], al0, bh[3]);
            mma16816(d[0][6], ah0, bl[3]);
            if (has2) {
                #pragma unroll
                for (int q = 0; q < 3; q++) {
                    mma16816(d[1][2 * q],     ah1, bh[q]);
                    mma16816(d[1][2 * q],     al1, bh[q]);
                    mma16816(d[1][2 * q],     ah1, bl[q]);
                    mma16816(d[1][2 * q + 1], ah1, bh[q] + 2);
                    mma16816(d[1][2 * q + 1], al1, bh[q] + 2);
                    mma16816(d[1][2 * q + 1], ah1, bl[q] + 2);
                }
                mma16816(d[1][6], ah1, bh[3]);
                mma16816(d[1][6], al1, bh[3]);
                mma16816(d[1][6], ah1, bl[3]);
            }
        }
    }

    __syncthreads();
    float* Dsm = reinterpret_cast<float*>(smc);
    {
        const int r0 = (lane >> 2);
        const int cb = (lane & 3) * 2;
        #pragma unroll
        for (int mt = 0; mt < 2; mt++) {
            if (mt == 1 && !has2) break;
            const int rr = (wid + mt * 8) * 16 + r0;
            #pragma unroll
            for (int q = 0; q < 7; q++) {
                int n = q * 8 + cb;
                Dsm[rr * 56 + n]           = d[mt][q][0];
                Dsm[rr * 56 + n + 1]       = d[mt][q][1];
                Dsm[(rr + 8) * 56 + n]     = d[mt][q][2];
                Dsm[(rr + 8) * 56 + n + 1] = d[mt][q][3];
            }
        }
    }
    __syncthreads();
    const int np = h ? 49 : 58;
    const int pb = h ? 58 : 0;
    const int cnt = 50 * np;
    #pragma unroll 1
    for (int i = tid; i < cnt; i += 256) {
        int o = i / np, j = i - o * np;
        int p = pb + j;
        int ml = 3 * p - base;
        const float* c0 = Dsm + ml * 56 + o;
        float v = fmaxf(c0[0], fmaxf(c0[56], c0[112])) + bs[o];
        g_y2p[b * 5350 + o * 107 + p] = pack_bf16_split(elu1(v));
    }
}

// ---------------- stage 3 (TENSOR, 1 sample/CTA, 64-k chunks): y2p -> y3p ----------------
#define S3_AH 0
#define S3_AL 18432
#define S3_BH 36864
#define S3_BL 50176
#define S3_SMEM 63488

__global__ __launch_bounds__(256, 2) void stage3_k(const float* __restrict__ b3)
{
    extern __shared__ char smc[];
    const uint32_t sb = smem_u32(smc);
    const int tid = threadIdx.x, wid = tid >> 5, lane = tid & 31;
    const int b = blockIdx.x;
    __shared__ float bs[100];
    if (tid < 100) bs[tid] = __ldg(&b3[tid]);

    float d[12][4];
    #pragma unroll
    for (int i = 0; i < 12; i++)
        #pragma unroll
        for (int j = 0; j < 4; j++) d[i][j] = 0.f;

    const uint32_t aOff = ((wid * 16 + ((lane >> 3) & 1) * 8 + (lane & 7)) * 72 + (lane >> 4) * 8) * 2;
    const uint32_t bOff = ((((lane >> 3) & 1) * 8 + (lane & 7)) * 104 + (lane >> 4) * 8) * 2;
    const uint32_t aH = sb + S3_AH + aOff, aL = sb + S3_AL + aOff;
    const uint32_t bHb = sb + S3_BH + bOff, bLb = sb + S3_BL + bOff;

    const int kloc = tid >> 2, seg = tid & 3;
    uint16_t* bhRow = reinterpret_cast<uint16_t*>(smc + S3_BH) + kloc * 104 + seg * 24;
    uint16_t* blRow = reinterpret_cast<uint16_t*>(smc + S3_BL) + kloc * 104 + seg * 24;

    #pragma unroll 1
    for (int ch = 0; ch < 8; ch++) {
        __syncthreads();
        // A copy async
        {
            const float4* srcH = reinterpret_cast<const float4*>(g_w3h + ch * 9216);
            const float4* srcL = reinterpret_cast<const float4*>(g_w3l + ch * 9216);
            for (int i = tid; i < 1152; i += 256) {
                cpa16(sb + S3_AH + i * 16, srcH + i);
                cpa16(sb + S3_AL + i * 16, srcL + i);
            }
            CP_COMMIT();
        }
        // B gather
        {
            const int gk = ch * 64 + kloc;
            if (gk < 500) {
                const int c = gk / 10, kk = gk - c * 10;
                const uint32_t* src = g_y2p + b * 5350 + c * 107 + kk + seg * 24;
                #pragma unroll
                for (int j = 0; j < 24; j += 2) {
                    uint32_t q0 = __ldg(&src[j]);
                    uint32_t q1 = __ldg(&src[j + 1]);
                    *reinterpret_cast<uint32_t*>(bhRow + j) = __byte_perm(q0, q1, 0x5410);
                    *reinterpret_cast<uint32_t*>(blRow + j) = __byte_perm(q0, q1, 0x7632);
                }
            } else {
                #pragma unroll
                for (int j = 0; j < 24; j += 2) {
                    *reinterpret_cast<uint32_t*>(bhRow + j) = 0u;
                    *reinterpret_cast<uint32_t*>(blRow + j) = 0u;
                }
            }
        }
        CP_WAIT0();
        __syncthreads();

        #pragma unroll
        for (int t = 0; t < 4; t++) {
            uint32_t ah[4], al[4];
            ldsm4(ah, aH + t * 32);
            ldsm4(al, aL + t * 32);
            const uint32_t bt = (uint32_t)t * 3328;
            #pragma unroll
            for (int q = 0; q < 6; q++) {
                uint32_t bh[4], bl[4];
                ldsm4t(bh, bHb + bt + q * 32);
                ldsm4t(bl, bLb + bt + q * 32);
                mma16816(d[2 * q],     ah, bh);
                mma16816(d[2 * q],     al, bh);
                mma16816(d[2 * q],     ah, bl);
                mma16816(d[2 * q + 1], ah, bh + 2);
                mma16816(d[2 * q + 1], al, bh + 2);
                mma16816(d[2 * q + 1], ah, bl + 2);
            }
        }
    }

    __syncthreads();
    float* Dsm = reinterpret_cast<float*>(smc);
    {
        const int r0 = wid * 16 + (lane >> 2);
        const int cb = (lane & 3) * 2;
        #pragma unroll
        for (int q = 0; q < 12; q++) {
            int n = q * 8 + cb;
            Dsm[r0 * 100 + n]           = d[q][0];
            Dsm[r0 * 100 + n + 1]       = d[q][1];
            Dsm[(r0 + 8) * 100 + n]     = d[q][2];
            Dsm[(r0 + 8) * 100 + n + 1] = d[q][3];
        }
    }
    __syncthreads();
    #pragma unroll 1
    for (int i = tid; i < 3200; i += 256) {
        int o = i >> 5, t = i & 31;
        const float* c0 = Dsm + o * 100 + 3 * t;
        float v = fmaxf(c0[0], fmaxf(c0[1], c0[2])) + bs[o];
        g_y3p[b * 3200 + o * 32 + t] = pack_bf16_split(elu1(v));
    }
}

// ---------------- stage 4 (TENSOR, m-split, 64-k chunks): y3p -> feat ----------------
#define S4_AH 0
#define S4_AL 18432
#define S4_BH 36864
#define S4_BL 44032
#define S4_SMEM 51200

__global__ __launch_bounds__(256, 3) void stage4_k(const float* __restrict__ b4)
{
    extern __shared__ char smc[];
    const uint32_t sb = smem_u32(smc);
    const int tid = threadIdx.x, wid = tid >> 5, lane = tid & 31;
    const int s0 = blockIdx.x * 2, h = blockIdx.y;
    const int nrow = h ? 72 : 128;
    __shared__ float bs[128];
    if (tid < 128) bs[tid] = (h * 128 + tid < 200) ? __ldg(&b4[h * 128 + tid]) : 0.f;

    {
        uint16_t* bhB = reinterpret_cast<uint16_t*>(smc + S4_BH);
        uint16_t* blB = reinterpret_cast<uint16_t*>(smc + S4_BL);
        for (int i = tid; i < 512; i += 256) {
            int r = i >> 3, c = 48 + (i & 7);
            bhB[r * 56 + c] = 0;
            blB[r * 56 + c] = 0;
        }
    }

    float d[6][4];
    #pragma unroll
    for (int i = 0; i < 6; i++)
        #pragma unroll
        for (int j = 0; j < 4; j++) d[i][j] = 0.f;

    const uint32_t aOff = ((wid * 16 + ((lane >> 3) & 1) * 8 + (lane & 7)) * 72 + (lane >> 4) * 8) * 2;
    const uint32_t bOff = ((((lane >> 3) & 1) * 8 + (lane & 7)) * 56 + (lane >> 4) * 8) * 2;
    const uint32_t aH = sb + S4_AH + aOff, aL = sb + S4_AL + aOff;
    const uint32_t bHb = sb + S4_BH + bOff, bLb = sb + S4_BL + bOff;

    const int kloc = tid >> 2, q4 = tid & 3;
    const int segq = q4 >> 1, jb = (q4 & 1) * 12;
    uint16_t* bhRow = reinterpret_cast<uint16_t*>(smc + S4_BH) + kloc * 56 + segq * 24 + jb;
    uint16_t* blRow = reinterpret_cast<uint16_t*>(smc + S4_BL) + kloc * 56 + segq * 24 + jb;

    #pragma unroll 1
    for (int ch = 0; ch < 16; ch++) {
        __syncthreads();
        {
            const float4* srcH = reinterpret_cast<const float4*>(g_w4h + ch * 18432 + h * 9216);
            const float4* srcL = reinterpret_cast<const float4*>(g_w4l + ch * 18432 + h * 9216);
            for (int i = tid; i < 1152; i += 256) {
                cpa16(sb + S4_AH + i * 16, srcH + i);
                cpa16(sb + S4_AL + i * 16, srcL + i);
            }
            CP_COMMIT();
        }
        {
            const int gk = ch * 64 + kloc;
            if (gk < 1000) {
                const int c = gk / 10, kk = gk - c * 10;
                const uint32_t* src = g_y3p + (s0 + segq) * 3200 + c * 32 + kk + jb;
                #pragma unroll
                for (int j = 0; j < 12; j += 2) {
                    int gp = jb + j;
                    uint32_t q0 = (gp < 21)     ? __ldg(&src[j])     : 0u;
                    uint32_t q1 = (gp + 1 < 21) ? __ldg(&src[j + 1]) : 0u;
                    *reinterpret_cast<uint32_t*>(bhRow + j) = __byte_perm(q0, q1, 0x5410);
                    *reinterpret_cast<uint32_t*>(blRow + j) = __byte_perm(q0, q1, 0x7632);
                }
            } else {
                #pragma unroll
                for (int j = 0; j < 12; j += 2) {
                    *reinterpret_cast<uint32_t*>(bhRow + j) = 0u;
                    *reinterpret_cast<uint32_t*>(blRow + j) = 0u;
                }
            }
        }
        CP_WAIT0();
        __syncthreads();

        #pragma unroll
        for (int t = 0; t < 4; t++) {
            uint32_t ah[4], al[4];
            ldsm4(ah, aH + t * 32);
            ldsm4(al, aL + t * 32);
            const uint32_t bt = (uint32_t)t * 1792;
            #pragma unroll
            for (int q = 0; q < 3; q++) {
                uint32_t bh[4], bl[4];
                ldsm4t(bh, bHb + bt + q * 32);
                ldsm4t(bl, bLb + bt + q * 32);
                mma16816(d[2 * q],     ah, bh);
                mma16816(d[2 * q],     al, bh);
                mma16816(d[2 * q],     ah, bl);
                mma16816(d[2 * q + 1], ah, bh + 2);
                mma16816(d[2 * q + 1], al, bh + 2);
                mma16816(d[2 * q + 1], ah, bl + 2);
            }
        }
    }

    __syncthreads();
    float* Dsm = reinterpret_cast<float*>(smc);
    {
        const int r0 = wid * 16 + (lane >> 2);
        const int cb = (lane & 3) * 2;
        #pragma unroll
        for (int q = 0; q < 6; q++) {
            int n = q * 8 + cb;
            Dsm[r0 * 56 + n]           = d[q][0];
            Dsm[r0 * 56 + n + 1]       = d[q][1];
            Dsm[(r0 + 8) * 56 + n]     = d[q][2];
            Dsm[(r0 + 8) * 56 + n + 1] = d[q][3];
        }
    }
    __syncthreads();
    const int cnt = nrow * 14;
    #pragma unroll 1
    for (int i = tid; i < cnt; i += 256) {
        int ol = i / 14, r = i - ol * 14, s = r / 7, t = r - s * 7;
        int n = s * 24 + 3 * t;
        float v = fmaxf(Dsm[ol * 56 + n], fmaxf(Dsm[ol * 56 + n + 1], Dsm[ol * 56 + n + 2]))
                  + bs[ol];
        g_feat[(s0 + s) * 1400 + (h * 128 + ol) * 7 + t] = elu1(v);
    }
}

// ---------------- head (float4) ----------------
__global__ void head_k(const int* __restrict__ sid, const float* __restrict__ hW,
                       const float* __restrict__ hB, float* __restrict__ out)
{
    const int b = blockIdx.x;
    const int s = sid[b];
    const float4* f = reinterpret_cast<const float4*>(g_feat + b * 1400);
    const float4* W = reinterpret_cast<const float4*>(hW + s * 5600);
    float acc[4] = {0.f, 0.f, 0.f, 0.f};
    for (int i = threadIdx.x; i < 350; i += blockDim.x) {
        float4 fv = f[i];
        #pragma unroll
        for (int o = 0; o < 4; o++) {
            float4 wv = __ldg(&W[o * 350 + i]);
            acc[o] = fmaf(fv.x, wv.x, fmaf(fv.y, wv.y, fmaf(fv.z, wv.z, fmaf(fv.w, wv.w, acc[o]))));
        }
    }
    #pragma unroll
    for (int off = 16; off > 0; off >>= 1) {
        #pragma unroll
        for (int o = 0; o < 4; o++) acc[o] += __shfl_down_sync(0xFFFFFFFFu, acc[o], off);
    }
    __shared__ float red[4][4];
    const int w = threadIdx.x >> 5, l = threadIdx.x & 31;
    if (l == 0) {
        #pragma unroll
        for (int o = 0; o < 4; o++) red[o][w] = acc[o];
    }
    __syncthreads();
    if (threadIdx.x < 4) {
        int o = threadIdx.x;
        out[b * 4 + o] = red[o][0] + red[o][1] + red[o][2] + red[o][3] + __ldg(&hB[s * 4 + o]);
    }
}

// ---------------- launch ----------------
extern "C" void kernel_launch(void* const* d_in, const int* in_sizes, int n_in,
                              void* d_out, int out_size)
{
    const float* x      = (const float*)d_in[0];
    const int*   sid    = (const int*)  d_in[1];
    const float* w_time = (const float*)d_in[2];
    const float* b_time = (const float*)d_in[3];
    const float* w_spat = (const float*)d_in[4];
    const float* b_spat = (const float*)d_in[5];
    const float* w2     = (const float*)d_in[6];
    const float* b2     = (const float*)d_in[7];
    const float* w3     = (const float*)d_in[8];
    const float* b3     = (const float*)d_in[9];
    const float* w4     = (const float*)d_in[10];
    const float* b4     = (const float*)d_in[11];
    const float* hW     = (const float*)d_in[12];
    const float* hB     = (const float*)d_in[13];
    float* out = (float*)d_out;

    cudaFuncSetAttribute(stage1_k, cudaFuncAttributeMaxDynamicSharedMemorySize, S1_SMEM);
    cudaFuncSetAttribute(stage2_k, cudaFuncAttributeMaxDynamicSharedMemorySize, S2_SMEM);
    cudaFuncSetAttribute(stage3_k, cudaFuncAttributeMaxDynamicSharedMemorySize, S3_SMEM);
    cudaFuncSetAttribute(stage4_k, cudaFuncAttributeMaxDynamicSharedMemorySize, S4_SMEM);

    precompute_all_k<<<(PW_BE + 255) / 256, 256>>>(x, w_time, b_time, w_spat, b_spat, w2, w3, w4);
    stage1_k<<<dim3(B_, 6), 384, S1_SMEM>>>();
    stage2_k<<<dim3(B_, 2), 256, S2_SMEM>>>(b2);
    stage3_k<<<B_, 256, S3_SMEM>>>(b3);
    stage4_k<<<dim3(128, 2), 256, S4_SMEM>>>(b4);
    head_k<<<B_, 128>>>(sid, hW, hB, out);
}